// round 6
// baseline (speedup 1.0000x reference)
#include <cuda_runtime.h>
#include <math.h>

#define NN 20000
#define TT 10
#define HH 64
#define EE 200000
#define NT (NN*TT)          // 200000 rows
#define ROWF 640            // T*H floats per node
#define BN_SCALE_C 0.99999500003749971893f

// ---------------- scratch (static device globals: allocation-free) ----------
__device__ __align__(256) float g_h[NT*HH];       // projected features
__device__ __align__(256) float g_s[NT];          // attention logits (pre-lrelu)
__device__ __align__(256) float g_M[NT*HH];       // message accumulator
__device__ __align__(256) float g_X[NT*HH];       // node state between layers
__device__ __align__(256) int   g_deg[2][NN];
__device__ __align__(256) int   g_rowptr[2][NN+1];
__device__ __align__(256) int   g_eord[2][EE];

// ---------------- CSR build ----------------
__global__ void k_zero_deg() {
    int i = blockIdx.x*blockDim.x + threadIdx.x;
    if (i < 2*NN) ((int*)g_deg)[i] = 0;
}

__global__ void k_count(const int* __restrict__ ei) {
    int idx = blockIdx.x*blockDim.x + threadIdx.x;
    if (idx >= 2*EE) return;
    int ty = idx / EE, e = idx % EE;
    int dst = ei[ty*2*EE + EE + e];
    atomicAdd(&g_deg[ty][dst], 1);
}

__global__ void k_scan() {   // one block per edge type, exclusive scan
    int ty = blockIdx.x;
    __shared__ int sh[1024];
    __shared__ int carry;
    if (threadIdx.x == 0) carry = 0;
    __syncthreads();
    for (int base = 0; base < NN; base += 1024) {
        int i = base + threadIdx.x;
        int v = (i < NN) ? g_deg[ty][i] : 0;
        sh[threadIdx.x] = v;
        __syncthreads();
        for (int off = 1; off < 1024; off <<= 1) {
            int t = (threadIdx.x >= off) ? sh[threadIdx.x - off] : 0;
            __syncthreads();
            sh[threadIdx.x] += t;
            __syncthreads();
        }
        if (i < NN) g_rowptr[ty][i] = carry + sh[threadIdx.x] - v;
        __syncthreads();
        if (threadIdx.x == 0) carry += sh[1023];
        __syncthreads();
    }
    if (threadIdx.x == 0) g_rowptr[ty][NN] = carry;
}

__global__ void k_scatter(const int* __restrict__ ei) {
    int idx = blockIdx.x*blockDim.x + threadIdx.x;
    if (idx >= 2*EE) return;
    int ty = idx / EE, e = idx % EE;
    int dst = ei[ty*2*EE + EE + e];
    int pos = g_rowptr[ty][dst] + atomicAdd(&g_deg[ty][dst], 1);
    g_eord[ty][pos] = e;
}

// ---------------- GEMM: h = X @ W + b, s = h . a  (fused epilogue) ---------
// Block tile 64x64, K=64 resident, 128 threads, thread tile 8x4. 32KB smem.
__global__ void __launch_bounds__(128) k_gemm(
    const float* __restrict__ Xin, int useX,
    const float* __restrict__ W, const float* __restrict__ b,
    const float* __restrict__ a)
{
    __shared__ float Xs[64*64];
    __shared__ float Ws[64*64];
    const float* X = useX ? Xin : (const float*)g_X;

    int tid = threadIdx.x;
    int tx = tid & 15, ty = tid >> 4;     // ty in [0,8)
    int base = blockIdx.x * 64;

    const float4* Xg = (const float4*)(X + (size_t)base*64);
    float4* Xs4 = (float4*)Xs;
    const float4* Wg = (const float4*)W;
    float4* Ws4 = (float4*)Ws;
    #pragma unroll
    for (int v = 0; v < 8; v++) {
        int idx = tid + v*128;            // float4 idx; row = idx/16
        int row = idx >> 4;
        float4 val = make_float4(0.f,0.f,0.f,0.f);
        if (base + row < NT) val = Xg[idx];
        Xs4[idx] = val;
        Ws4[idx] = Wg[idx];
    }
    __syncthreads();

    float acc[8][4];
    #pragma unroll
    for (int r = 0; r < 8; r++)
        #pragma unroll
        for (int c = 0; c < 4; c++) acc[r][c] = 0.f;

    #pragma unroll 4
    for (int k = 0; k < 64; k++) {
        float4 bv = ((const float4*)(Ws + k*64))[tx];
        #pragma unroll
        for (int r = 0; r < 8; r++) {
            float av = Xs[(ty + r*8)*64 + k];
            acc[r][0] += av*bv.x; acc[r][1] += av*bv.y;
            acc[r][2] += av*bv.z; acc[r][3] += av*bv.w;
        }
    }

    float bb0 = b[tx*4+0], bb1 = b[tx*4+1], bb2 = b[tx*4+2], bb3 = b[tx*4+3];
    float aa0 = a[tx*4+0], aa1 = a[tx*4+1], aa2 = a[tx*4+2], aa3 = a[tx*4+3];
    #pragma unroll
    for (int r = 0; r < 8; r++) {
        int row = base + ty + r*8;
        float o0 = acc[r][0]+bb0, o1 = acc[r][1]+bb1;
        float o2 = acc[r][2]+bb2, o3 = acc[r][3]+bb3;
        if (row < NT) {
            float* hr = g_h + (size_t)row*64 + tx*4;
            hr[0]=o0; hr[1]=o1; hr[2]=o2; hr[3]=o3;
        }
        float dot = o0*aa0 + o1*aa1 + o2*aa2 + o3*aa3;
        #pragma unroll
        for (int m = 8; m >= 1; m >>= 1)
            dot += __shfl_xor_sync(0xFFFFFFFFu, dot, m);
        if (tx == 0 && row < NT) g_s[row] = dot;
    }
}

// ---------------- fused per-dst attention softmax + aggregation -----------
__global__ void __launch_bounds__(128) k_agg(
    int ty, const int* __restrict__ ei, const float* __restrict__ ea, int first)
{
    int n = blockIdx.x;
    int tid = threadIdx.x;
    int r0 = g_rowptr[ty][n], r1 = g_rowptr[ty][n+1];
    const int* srcA = ei + ty*2*EE;      // src indices for this type

    __shared__ float red[8][16];
    __shared__ float smax[10], sden[10];
    __shared__ float wsh[16][10];
    __shared__ int   ssrc[16];

    int ts = tid & 15, es = tid >> 4;

    // pass 1: per-t max over incoming edges
    float mx = -1e30f;
    if (ts < 10) {
        for (int j = r0 + es; j < r1; j += 8) {
            int src = srcA[g_eord[ty][j]];
            float v = g_s[src*TT + ts];
            float sc = v > 0.f ? v : 0.2f*v;
            mx = fmaxf(mx, sc);
        }
    }
    red[es][ts] = mx;
    __syncthreads();
    if (tid < 10) {
        float m = red[0][tid];
        #pragma unroll
        for (int i = 1; i < 8; i++) m = fmaxf(m, red[i][tid]);
        smax[tid] = m;
    }
    __syncthreads();

    // pass 2: denominator
    float den = 0.f;
    if (ts < 10) {
        float m = smax[ts];
        for (int j = r0 + es; j < r1; j += 8) {
            int src = srcA[g_eord[ty][j]];
            float v = g_s[src*TT + ts];
            float sc = v > 0.f ? v : 0.2f*v;
            den += __expf(sc - m);
        }
    }
    red[es][ts] = den;
    __syncthreads();
    if (tid < 10) {
        float d = 0.f;
        #pragma unroll
        for (int i = 0; i < 8; i++) d += red[i][tid];
        sden[tid] = d;
    }
    __syncthreads();

    // pass 3: chunked weighted aggregation, acc in registers
    float acc[5] = {0.f, 0.f, 0.f, 0.f, 0.f};
    for (int j0 = r0; j0 < r1; j0 += 16) {
        int cnt = min(16, r1 - j0);
        for (int p = tid; p < cnt*10; p += 128) {
            int ce = p / 10, ct = p % 10;
            int e = g_eord[ty][j0 + ce];
            int src = srcA[e];
            if (ct == 0) ssrc[ce] = src;
            float v = g_s[src*TT + ct];
            float sc = v > 0.f ? v : 0.2f*v;
            wsh[ce][ct] = __expf(sc - smax[ct]) / (sden[ct] + 1e-16f) * ea[e];
        }
        __syncthreads();
        for (int c = 0; c < cnt; c++) {
            const float* hrow = g_h + (size_t)ssrc[c]*ROWF;
            #pragma unroll
            for (int i = 0; i < 5; i++) {
                int pos = tid + i*128;
                acc[i] += wsh[c][pos >> 6] * hrow[pos];
            }
        }
        __syncthreads();
    }

    float* Mr = g_M + (size_t)n*ROWF;
    #pragma unroll
    for (int i = 0; i < 5; i++) {
        int pos = tid + i*128;
        if (first) Mr[pos] = acc[i];
        else       Mr[pos] += acc[i];
    }
}

// ---------------- residual + LayerNorm (warp per row) ----------------------
__global__ void __launch_bounds__(256) k_ln(
    const float* __restrict__ xin, int useX,
    const float* __restrict__ g, const float* __restrict__ bsh)
{
    const float* X = useX ? xin : (const float*)g_X;
    int warp = (blockIdx.x*blockDim.x + threadIdx.x) >> 5;
    int lane = threadIdx.x & 31;
    if (warp >= NT) return;
    size_t base = (size_t)warp * 64;
    float v0 = X[base + lane]      + 0.5f*g_M[base + lane];
    float v1 = X[base + lane + 32] + 0.5f*g_M[base + lane + 32];
    float s = v0 + v1;
    #pragma unroll
    for (int m = 16; m >= 1; m >>= 1) s += __shfl_xor_sync(0xFFFFFFFFu, s, m);
    float mean = s * (1.f/64.f);
    float d0 = v0 - mean, d1 = v1 - mean;
    float q = d0*d0 + d1*d1;
    #pragma unroll
    for (int m = 16; m >= 1; m >>= 1) q += __shfl_xor_sync(0xFFFFFFFFu, q, m);
    float inv = rsqrtf(q*(1.f/64.f) + 1e-5f);
    g_X[base + lane]      = d0*inv*g[lane]      + bsh[lane];
    g_X[base + lane + 32] = d1*inv*g[lane + 32] + bsh[lane + 32];
}

// ---------------- decoder v2: reads conv weights DIRECTLY from inputs ------
// 128 threads per node. No staged weight transpose (R5 diag showed the old
// staged path yielded exactly-zero output). Weights are small (cw1 48KB,
// cw2 24KB) and L1-resident; each warp's weight loads are broadcasts.
__global__ void k_dec2(
    const float* __restrict__ cw1, const float* __restrict__ cb1,
    const float* __restrict__ bn1g, const float* __restrict__ bn1b,
    const float* __restrict__ cw2, const float* __restrict__ cb2,
    const float* __restrict__ bn2g, const float* __restrict__ bn2b,
    const float* __restrict__ cw3, const float* __restrict__ cb3,
    float* __restrict__ out)
{
    int n = blockIdx.x;
    int tid = threadIdx.x;

    __shared__ float xts[12][64];       // [tpad][h], rows 0 and 11 are zero pad
    __shared__ float c1s[12][64];
    __shared__ float c2part[4][32][10];
    __shared__ float c2s[12][32];

    const float* xr = g_X + (size_t)n*ROWF;     // layout [t][h]
    for (int p = tid; p < 640; p += 128) {
        int t = p >> 6, h = p & 63;
        xts[t+1][h] = xr[p];
    }
    if (tid < 64) { xts[0][tid] = 0.f; xts[11][tid] = 0.f; }
    __syncthreads();

    // conv1 (64->64,k=3,pad=1) + BN + ReLU.
    // thread = (o = tid>>1, half-of-t = tid&1), 5 t-values per thread.
    {
        int o = tid >> 1, t0 = (tid & 1) * 5;
        float bias = cb1[o];
        float acc0 = bias, acc1 = bias, acc2 = bias, acc3 = bias, acc4 = bias;
        const float* wrow = cw1 + o*192;        // [o][i][k] row-major
        #pragma unroll 4
        for (int i = 0; i < 64; i++) {
            float x0 = xts[t0+0][i], x1 = xts[t0+1][i], x2 = xts[t0+2][i];
            float x3 = xts[t0+3][i], x4 = xts[t0+4][i], x5 = xts[t0+5][i];
            float x6 = xts[t0+6][i];
            float w0 = wrow[i*3+0], w1 = wrow[i*3+1], w2 = wrow[i*3+2];
            acc0 += w0*x0 + w1*x1 + w2*x2;
            acc1 += w0*x1 + w1*x2 + w2*x3;
            acc2 += w0*x2 + w1*x3 + w2*x4;
            acc3 += w0*x3 + w1*x4 + w2*x5;
            acc4 += w0*x4 + w1*x5 + w2*x6;
        }
        float sc = bn1g[o]*BN_SCALE_C, sb = bn1b[o];
        float v;
        v = acc0*sc + sb; c1s[t0+1][o] = v > 0.f ? v : 0.f;
        v = acc1*sc + sb; c1s[t0+2][o] = v > 0.f ? v : 0.f;
        v = acc2*sc + sb; c1s[t0+3][o] = v > 0.f ? v : 0.f;
        v = acc3*sc + sb; c1s[t0+4][o] = v > 0.f ? v : 0.f;
        v = acc4*sc + sb; c1s[t0+5][o] = v > 0.f ? v : 0.f;
    }
    if (tid < 64) { c1s[0][tid] = 0.f; c1s[11][tid] = 0.f; }
    __syncthreads();

    // conv2 (64->32,k=3,pad=1): thread = (o = tid&31, seg = tid>>5);
    // each warp covers one 16-wide i-segment for all 32 output channels.
    {
        int o = tid & 31, seg = tid >> 5;
        float acc[10];
        #pragma unroll
        for (int t = 0; t < 10; t++) acc[t] = 0.f;
        const float* wrow = cw2 + o*192;
        int i0 = seg*16;
        #pragma unroll 4
        for (int i = i0; i < i0+16; i++) {
            float w0 = wrow[i*3+0], w1 = wrow[i*3+1], w2 = wrow[i*3+2];
            #pragma unroll
            for (int t = 0; t < 10; t++)
                acc[t] += w0*c1s[t][i] + w1*c1s[t+1][i] + w2*c1s[t+2][i];
        }
        #pragma unroll
        for (int t = 0; t < 10; t++) c2part[seg][o][t] = acc[t];
    }
    __syncthreads();
    if (tid < 32) {
        int o = tid;
        float sc = bn2g[o]*BN_SCALE_C, sb = bn2b[o], bias = cb2[o];
        #pragma unroll
        for (int t = 0; t < 10; t++) {
            float v = (c2part[0][o][t] + c2part[1][o][t] +
                       c2part[2][o][t] + c2part[3][o][t] + bias)*sc + sb;
            c2s[t+1][o] = v > 0.f ? v : 0.f;
        }
        c2s[0][o] = 0.f; c2s[11][o] = 0.f;
    }
    __syncthreads();

    // conv3 (32->1,k=3,pad=1): one thread per t
    if (tid < 10) {
        float acc = cb3[0];
        #pragma unroll 4
        for (int i = 0; i < 32; i++) {
            acc += cw3[i*3+0]*c2s[tid  ][i]
                 + cw3[i*3+1]*c2s[tid+1][i]
                 + cw3[i*3+2]*c2s[tid+2][i];
        }
        out[(size_t)n*10 + tid] = acc;
    }
}

// ---------------- launch ----------------------------------------------------
extern "C" void kernel_launch(void* const* d_in, const int* in_sizes, int n_in,
                              void* d_out, int out_size)
{
    // R5 diagnostic confirmed: inputs are in exact setup_inputs() dict order,
    // edge_index is int32 [ETY,2,E], counts are element counts.
    const float* x    = (const float*)d_in[0];
    const int*   ei   = (const int*)  d_in[1];
    const float* ea   = (const float*)d_in[2];
    const float* W    = (const float*)d_in[3];
    const float* bp   = (const float*)d_in[4];
    const float* ap   = (const float*)d_in[5];
    const float* lng  = (const float*)d_in[6];
    const float* lnb  = (const float*)d_in[7];
    const float* cw1  = (const float*)d_in[8];
    const float* cb1  = (const float*)d_in[9];
    const float* bn1g = (const float*)d_in[10];
    const float* bn1b = (const float*)d_in[11];
    const float* cw2  = (const float*)d_in[12];
    const float* cb2  = (const float*)d_in[13];
    const float* bn2g = (const float*)d_in[14];
    const float* bn2b = (const float*)d_in[15];
    const float* cw3  = (const float*)d_in[16];
    const float* cb3  = (const float*)d_in[17];
    float* out = (float*)d_out;

    // CSR build
    k_zero_deg<<<(2*NN + 255)/256, 256>>>();
    k_count<<<(2*EE + 255)/256, 256>>>(ei);
    k_scan<<<2, 1024>>>();
    k_zero_deg<<<(2*NN + 255)/256, 256>>>();
    k_scatter<<<(2*EE + 255)/256, 256>>>(ei);

    int gemm_grid = (NT + 63)/64;
    for (int l = 0; l < 2; l++) {
        int useX = (l == 0) ? 1 : 0;
        for (int e = 0; e < 2; e++) {
            int idx = l*2 + e;
            k_gemm<<<gemm_grid, 128>>>(x, useX, W + idx*64*64, bp + idx*64, ap + idx*64);
            k_agg<<<NN, 128>>>(e, ei, ea + e*EE, (e == 0) ? 1 : 0);
        }
        k_ln<<<(NT + 7)/8, 256>>>(x, useX, lng + l*64, lnb + l*64);
    }

    k_dec2<<<NN, 128>>>(cw1, cb1, bn1g, bn1b,
                        cw2, cb2, bn2g, bn2b,
                        cw3, cb3, out);
}

// round 7
// speedup vs baseline: 1.9119x; 1.9119x over previous
#include <cuda_runtime.h>
#include <math.h>

#define NN 20000
#define TT 10
#define HH 64
#define EE 200000
#define NT (NN*TT)          // 200000 rows
#define ROWF 640            // T*H floats per node
#define BN_SCALE_C 0.99999500003749971893f

// ---------------- scratch (static device globals: allocation-free) ----------
__device__ __align__(256) float g_h0[NT*HH];      // projected features, type 0
__device__ __align__(256) float g_h1[NT*HH];      // projected features, type 1
__device__ __align__(256) float g_s0[NT];         // attention logits, type 0
__device__ __align__(256) float g_s1[NT];         // attention logits, type 1
__device__ __align__(256) float g_M[NT*HH];       // message accumulator
__device__ __align__(256) float g_X[NT*HH];       // node state between layers
__device__ __align__(256) int   g_deg[2][NN];
__device__ __align__(256) int   g_rowptr[2][NN+1];
__device__ __align__(256) int   g_eord[2][EE];

// ---------------- CSR build ----------------
__global__ void k_zero_deg() {
    int i = blockIdx.x*blockDim.x + threadIdx.x;
    if (i < 2*NN) ((int*)g_deg)[i] = 0;
}

__global__ void k_count(const int* __restrict__ ei) {
    int idx = blockIdx.x*blockDim.x + threadIdx.x;
    if (idx >= 2*EE) return;
    int ty = idx / EE, e = idx % EE;
    int dst = ei[ty*2*EE + EE + e];
    atomicAdd(&g_deg[ty][dst], 1);
}

__global__ void k_scan() {   // one block per edge type, exclusive scan
    int ty = blockIdx.x;
    __shared__ int sh[1024];
    __shared__ int carry;
    if (threadIdx.x == 0) carry = 0;
    __syncthreads();
    for (int base = 0; base < NN; base += 1024) {
        int i = base + threadIdx.x;
        int v = (i < NN) ? g_deg[ty][i] : 0;
        sh[threadIdx.x] = v;
        __syncthreads();
        for (int off = 1; off < 1024; off <<= 1) {
            int t = (threadIdx.x >= off) ? sh[threadIdx.x - off] : 0;
            __syncthreads();
            sh[threadIdx.x] += t;
            __syncthreads();
        }
        if (i < NN) g_rowptr[ty][i] = carry + sh[threadIdx.x] - v;
        __syncthreads();
        if (threadIdx.x == 0) carry += sh[1023];
        __syncthreads();
    }
    if (threadIdx.x == 0) g_rowptr[ty][NN] = carry;
}

__global__ void k_scatter(const int* __restrict__ ei) {
    int idx = blockIdx.x*blockDim.x + threadIdx.x;
    if (idx >= 2*EE) return;
    int ty = idx / EE, e = idx % EE;
    int dst = ei[ty*2*EE + EE + e];
    int pos = g_rowptr[ty][dst] + atomicAdd(&g_deg[ty][dst], 1);
    g_eord[ty][pos] = e;
}

// ---------------- GEMM: h = X @ W + b, s = h . a  (fused epilogue) ---------
__global__ void __launch_bounds__(128) k_gemm(
    const float* __restrict__ Xin, int useX,
    const float* __restrict__ W, const float* __restrict__ b,
    const float* __restrict__ a,
    float* __restrict__ hout, float* __restrict__ sout)
{
    __shared__ float Xs[64*64];
    __shared__ float Ws[64*64];
    const float* X = useX ? Xin : (const float*)g_X;

    int tid = threadIdx.x;
    int tx = tid & 15, ty = tid >> 4;     // ty in [0,8)
    int base = blockIdx.x * 64;

    const float4* Xg = (const float4*)(X + (size_t)base*64);
    float4* Xs4 = (float4*)Xs;
    const float4* Wg = (const float4*)W;
    float4* Ws4 = (float4*)Ws;
    #pragma unroll
    for (int v = 0; v < 8; v++) {
        int idx = tid + v*128;            // float4 idx; row = idx/16
        int row = idx >> 4;
        float4 val = make_float4(0.f,0.f,0.f,0.f);
        if (base + row < NT) val = Xg[idx];
        Xs4[idx] = val;
        Ws4[idx] = Wg[idx];
    }
    __syncthreads();

    float acc[8][4];
    #pragma unroll
    for (int r = 0; r < 8; r++)
        #pragma unroll
        for (int c = 0; c < 4; c++) acc[r][c] = 0.f;

    #pragma unroll 4
    for (int k = 0; k < 64; k++) {
        float4 bv = ((const float4*)(Ws + k*64))[tx];
        #pragma unroll
        for (int r = 0; r < 8; r++) {
            float av = Xs[(ty + r*8)*64 + k];
            acc[r][0] += av*bv.x; acc[r][1] += av*bv.y;
            acc[r][2] += av*bv.z; acc[r][3] += av*bv.w;
        }
    }

    float bb0 = b[tx*4+0], bb1 = b[tx*4+1], bb2 = b[tx*4+2], bb3 = b[tx*4+3];
    float aa0 = a[tx*4+0], aa1 = a[tx*4+1], aa2 = a[tx*4+2], aa3 = a[tx*4+3];
    #pragma unroll
    for (int r = 0; r < 8; r++) {
        int row = base + ty + r*8;
        float o0 = acc[r][0]+bb0, o1 = acc[r][1]+bb1;
        float o2 = acc[r][2]+bb2, o3 = acc[r][3]+bb3;
        if (row < NT) {
            float* hr = hout + (size_t)row*64 + tx*4;
            hr[0]=o0; hr[1]=o1; hr[2]=o2; hr[3]=o3;
        }
        float dot = o0*aa0 + o1*aa1 + o2*aa2 + o3*aa3;
        #pragma unroll
        for (int m = 8; m >= 1; m >>= 1)
            dot += __shfl_xor_sync(0xFFFFFFFFu, dot, m);
        if (tx == 0 && row < NT) sout[row] = dot;
    }
}

// ---------------- fused attention softmax + aggregation, BOTH edge types ---
// One block per destination node; loops over the two edge types sequentially,
// accumulating messages in registers; single write of g_M per node.
__global__ void __launch_bounds__(128) k_agg2(
    const int* __restrict__ ei, const float* __restrict__ ea)
{
    int n = blockIdx.x;
    int tid = threadIdx.x;

    __shared__ float red[8][16];
    __shared__ float smax[10], sden[10];
    __shared__ float wsh[16][10];
    __shared__ int   ssrc[16];

    int ts = tid & 15, es = tid >> 4;
    float acc[5] = {0.f, 0.f, 0.f, 0.f, 0.f};

    #pragma unroll
    for (int ty = 0; ty < 2; ty++) {
        const float* sA  = ty ? (const float*)g_s1 : (const float*)g_s0;
        const float* hA  = ty ? (const float*)g_h1 : (const float*)g_h0;
        const float* eaA = ea + ty*EE;
        const int*   srcA = ei + ty*2*EE;
        const int*   eord = g_eord[ty];
        int r0 = g_rowptr[ty][n], r1 = g_rowptr[ty][n+1];
        __syncthreads();   // red/smax/sden safe to reuse across types

        // pass 1: per-t max over incoming edges
        float mx = -1e30f;
        if (ts < 10) {
            for (int j = r0 + es; j < r1; j += 8) {
                int src = srcA[eord[j]];
                float v = sA[src*TT + ts];
                float sc = v > 0.f ? v : 0.2f*v;
                mx = fmaxf(mx, sc);
            }
        }
        red[es][ts] = mx;
        __syncthreads();
        if (tid < 10) {
            float m = red[0][tid];
            #pragma unroll
            for (int i = 1; i < 8; i++) m = fmaxf(m, red[i][tid]);
            smax[tid] = m;
        }
        __syncthreads();

        // pass 2: denominator
        float den = 0.f;
        if (ts < 10) {
            float m = smax[ts];
            for (int j = r0 + es; j < r1; j += 8) {
                int src = srcA[eord[j]];
                float v = sA[src*TT + ts];
                float sc = v > 0.f ? v : 0.2f*v;
                den += __expf(sc - m);
            }
        }
        red[es][ts] = den;
        __syncthreads();
        if (tid < 10) {
            float d = 0.f;
            #pragma unroll
            for (int i = 0; i < 8; i++) d += red[i][tid];
            sden[tid] = d;
        }
        __syncthreads();

        // pass 3: chunked weighted aggregation
        for (int j0 = r0; j0 < r1; j0 += 16) {
            int cnt = min(16, r1 - j0);
            for (int p = tid; p < cnt*10; p += 128) {
                int ce = p / 10, ct = p % 10;
                int e = eord[j0 + ce];
                int src = srcA[e];
                if (ct == 0) ssrc[ce] = src;
                float v = sA[src*TT + ct];
                float sc = v > 0.f ? v : 0.2f*v;
                wsh[ce][ct] = __expf(sc - smax[ct]) / (sden[ct] + 1e-16f) * eaA[e];
            }
            __syncthreads();
            for (int c = 0; c < cnt; c++) {
                const float* hrow = hA + (size_t)ssrc[c]*ROWF;
                #pragma unroll
                for (int i = 0; i < 5; i++) {
                    int pos = tid + i*128;
                    acc[i] += wsh[c][pos >> 6] * hrow[pos];
                }
            }
            __syncthreads();
        }
    }

    float* Mr = g_M + (size_t)n*ROWF;
    #pragma unroll
    for (int i = 0; i < 5; i++) Mr[tid + i*128] = acc[i];
}

// ---------------- residual + LayerNorm (warp per row) ----------------------
__global__ void __launch_bounds__(256) k_ln(
    const float* __restrict__ xin, int useX,
    const float* __restrict__ g, const float* __restrict__ bsh)
{
    const float* X = useX ? xin : (const float*)g_X;
    int warp = (blockIdx.x*blockDim.x + threadIdx.x) >> 5;
    int lane = threadIdx.x & 31;
    if (warp >= NT) return;
    size_t base = (size_t)warp * 64;
    float v0 = X[base + lane]      + 0.5f*g_M[base + lane];
    float v1 = X[base + lane + 32] + 0.5f*g_M[base + lane + 32];
    float s = v0 + v1;
    #pragma unroll
    for (int m = 16; m >= 1; m >>= 1) s += __shfl_xor_sync(0xFFFFFFFFu, s, m);
    float mean = s * (1.f/64.f);
    float d0 = v0 - mean, d1 = v1 - mean;
    float q = d0*d0 + d1*d1;
    #pragma unroll
    for (int m = 16; m >= 1; m >>= 1) q += __shfl_xor_sync(0xFFFFFFFFu, q, m);
    float inv = rsqrtf(q*(1.f/64.f) + 1e-5f);
    g_X[base + lane]      = d0*inv*g[lane]      + bsh[lane];
    g_X[base + lane + 32] = d1*inv*g[lane + 32] + bsh[lane + 32];
}

// ---------------- decoder v3: smem-staged transposed conv weights ----------
// 256 threads = 2 nodes per block. Weights staged once per block into shared
// memory in [i*3+k][o] layout with bank-padding (stride 65 / 33), so conv
// weight reads are conflict-free LDS broadcasts instead of 16-32-line LDGs.
// Dynamic smem: 12480 + 6336 + 2*3200 = 25216 floats = 100864 bytes.
#define DEC_SMEM_FLOATS 25216
__global__ void __launch_bounds__(256) k_dec3(
    const float* __restrict__ cw1, const float* __restrict__ cb1,
    const float* __restrict__ bn1g, const float* __restrict__ bn1b,
    const float* __restrict__ cw2, const float* __restrict__ cb2,
    const float* __restrict__ bn2g, const float* __restrict__ bn2b,
    const float* __restrict__ cw3, const float* __restrict__ cb3,
    float* __restrict__ out)
{
    extern __shared__ float sm[];
    float* ws1 = sm;                    // [r*65 + o], r = i*3+k, 192x64
    float* ws2 = sm + 12480;            // [r*33 + o], 192x32
    int tid = threadIdx.x;
    int nd  = tid >> 7;                 // node slot 0/1
    int wt  = tid & 127;
    float* nb  = sm + 18816 + nd*3200;
    float* xts = nb;                    // [12][64]  (t-padded)
    float* c1s = nb + 768;              // [12][64]
    float* c2p = nb + 1536;             // [4][32][10]
    float* c2s = nb + 2816;             // [12][32]

    // stage + transpose weights (whole block, coalesced reads)
    for (int idx = tid; idx < 12288; idx += 256) {
        int o = idx / 192, r = idx % 192;
        ws1[r*65 + o] = cw1[idx];
    }
    for (int idx = tid; idx < 6144; idx += 256) {
        int o = idx / 192, r = idx % 192;
        ws2[r*33 + o] = cw2[idx];
    }

    int n = blockIdx.x*2 + nd;
    const float* xr = g_X + (size_t)n*ROWF;   // [t][h]
    for (int p = wt; p < 640; p += 128) {
        int t = p >> 6, h = p & 63;
        xts[(t+1)*64 + h] = xr[p];
    }
    if (wt < 64) { xts[wt] = 0.f; xts[11*64 + wt] = 0.f; }
    __syncthreads();

    // conv1 (64->64,k=3,pad=1) + BN + ReLU; thread=(o=wt>>1, t-half=wt&1)
    {
        int o = wt >> 1, t0 = (wt & 1)*5;
        float bias = cb1[o];
        float a0=bias, a1=bias, a2=bias, a3=bias, a4=bias;
        #pragma unroll 4
        for (int i = 0; i < 64; i++) {
            float x0=xts[(t0+0)*64+i], x1=xts[(t0+1)*64+i], x2=xts[(t0+2)*64+i];
            float x3=xts[(t0+3)*64+i], x4=xts[(t0+4)*64+i], x5=xts[(t0+5)*64+i];
            float x6=xts[(t0+6)*64+i];
            float w0=ws1[(i*3+0)*65+o], w1=ws1[(i*3+1)*65+o], w2=ws1[(i*3+2)*65+o];
            a0 += w0*x0 + w1*x1 + w2*x2;
            a1 += w0*x1 + w1*x2 + w2*x3;
            a2 += w0*x2 + w1*x3 + w2*x4;
            a3 += w0*x3 + w1*x4 + w2*x5;
            a4 += w0*x4 + w1*x5 + w2*x6;
        }
        float sc = bn1g[o]*BN_SCALE_C, sb = bn1b[o];
        float v;
        v = a0*sc + sb; c1s[(t0+1)*64+o] = v > 0.f ? v : 0.f;
        v = a1*sc + sb; c1s[(t0+2)*64+o] = v > 0.f ? v : 0.f;
        v = a2*sc + sb; c1s[(t0+3)*64+o] = v > 0.f ? v : 0.f;
        v = a3*sc + sb; c1s[(t0+4)*64+o] = v > 0.f ? v : 0.f;
        v = a4*sc + sb; c1s[(t0+5)*64+o] = v > 0.f ? v : 0.f;
    }
    if (wt < 64) { c1s[wt] = 0.f; c1s[11*64 + wt] = 0.f; }
    __syncthreads();

    // conv2 (64->32,k=3,pad=1); thread=(o=wt&31, i-segment=wt>>5)
    {
        int o = wt & 31, seg = wt >> 5;
        float acc[10];
        #pragma unroll
        for (int t = 0; t < 10; t++) acc[t] = 0.f;
        int i0 = seg*16;
        #pragma unroll 4
        for (int i = i0; i < i0+16; i++) {
            float w0=ws2[(i*3+0)*33+o], w1=ws2[(i*3+1)*33+o], w2=ws2[(i*3+2)*33+o];
            #pragma unroll
            for (int t = 0; t < 10; t++)
                acc[t] += w0*c1s[t*64+i] + w1*c1s[(t+1)*64+i] + w2*c1s[(t+2)*64+i];
        }
        #pragma unroll
        for (int t = 0; t < 10; t++) c2p[seg*320 + o*10 + t] = acc[t];
    }
    __syncthreads();
    if (wt < 32) {
        int o = wt;
        float sc = bn2g[o]*BN_SCALE_C, sb = bn2b[o], bias = cb2[o];
        #pragma unroll
        for (int t = 0; t < 10; t++) {
            float v = (c2p[o*10+t] + c2p[320+o*10+t] +
                       c2p[640+o*10+t] + c2p[960+o*10+t] + bias)*sc + sb;
            c2s[(t+1)*32+o] = v > 0.f ? v : 0.f;
        }
        c2s[o] = 0.f; c2s[11*32+o] = 0.f;
    }
    __syncthreads();

    // conv3 (32->1,k=3,pad=1): one thread per t
    if (wt < 10) {
        float acc = cb3[0];
        #pragma unroll 4
        for (int i = 0; i < 32; i++) {
            acc += cw3[i*3+0]*c2s[wt*32+i]
                 + cw3[i*3+1]*c2s[(wt+1)*32+i]
                 + cw3[i*3+2]*c2s[(wt+2)*32+i];
        }
        out[(size_t)n*10 + wt] = acc;
    }
}

// ---------------- launch ----------------------------------------------------
extern "C" void kernel_launch(void* const* d_in, const int* in_sizes, int n_in,
                              void* d_out, int out_size)
{
    const float* x    = (const float*)d_in[0];
    const int*   ei   = (const int*)  d_in[1];
    const float* ea   = (const float*)d_in[2];
    const float* W    = (const float*)d_in[3];
    const float* bp   = (const float*)d_in[4];
    const float* ap   = (const float*)d_in[5];
    const float* lng  = (const float*)d_in[6];
    const float* lnb  = (const float*)d_in[7];
    const float* cw1  = (const float*)d_in[8];
    const float* cb1  = (const float*)d_in[9];
    const float* bn1g = (const float*)d_in[10];
    const float* bn1b = (const float*)d_in[11];
    const float* cw2  = (const float*)d_in[12];
    const float* cb2  = (const float*)d_in[13];
    const float* bn2g = (const float*)d_in[14];
    const float* bn2b = (const float*)d_in[15];
    const float* cw3  = (const float*)d_in[16];
    const float* cb3  = (const float*)d_in[17];
    float* out = (float*)d_out;

    static int smem_set = 0;
    if (!smem_set) {
        cudaFuncSetAttribute(k_dec3, cudaFuncAttributeMaxDynamicSharedMemorySize,
                             DEC_SMEM_FLOATS*4);
        smem_set = 1;
    }

    // CSR build
    k_zero_deg<<<(2*NN + 255)/256, 256>>>();
    k_count<<<(2*EE + 255)/256, 256>>>(ei);
    k_scan<<<2, 1024>>>();
    k_zero_deg<<<(2*NN + 255)/256, 256>>>();
    k_scatter<<<(2*EE + 255)/256, 256>>>(ei);

    int gemm_grid = (NT + 63)/64;
    float* hbuf[2] = { (float*)0, (float*)0 };
    for (int l = 0; l < 2; l++) {
        int useX = (l == 0) ? 1 : 0;
        // projections for both edge types (separate h/s buffers)
        {
            int idx = l*2 + 0;
            float *h0p, *s0p;
            cudaGetSymbolAddress((void**)&h0p, g_h0);
            cudaGetSymbolAddress((void**)&s0p, g_s0);
            k_gemm<<<gemm_grid, 128>>>(x, useX, W + idx*64*64, bp + idx*64,
                                       ap + idx*64, h0p, s0p);
        }
        {
            int idx = l*2 + 1;
            float *h1p, *s1p;
            cudaGetSymbolAddress((void**)&h1p, g_h1);
            cudaGetSymbolAddress((void**)&s1p, g_s1);
            k_gemm<<<gemm_grid, 128>>>(x, useX, W + idx*64*64, bp + idx*64,
                                       ap + idx*64, h1p, s1p);
        }
        k_agg2<<<NN, 128>>>(ei, ea);
        k_ln<<<(NT + 7)/8, 256>>>(x, useX, lng + l*64, lnb + l*64);
    }

    k_dec3<<<NN/2, 256, DEC_SMEM_FLOATS*4>>>(cw1, cb1, bn1g, bn1b,
                                             cw2, cb2, bn2g, bn2b,
                                             cw3, cb3, out);
}

// round 9
// speedup vs baseline: 2.0737x; 1.0846x over previous
#include <cuda_runtime.h>
#include <math.h>

#define NN 20000
#define TT 10
#define HH 64
#define EE 200000
#define NT (NN*TT)          // 200000 rows
#define ROWF 640            // T*H floats per node
#define BN_SCALE_C 0.99999500003749971893f

// ---------------- scratch (static device globals: allocation-free) ----------
__device__ __align__(256) float g_h0[NT*HH];      // projected features, type 0
__device__ __align__(256) float g_h1[NT*HH];      // projected features, type 1
__device__ __align__(256) float g_s0[NT];         // attention logits, type 0
__device__ __align__(256) float g_s1[NT];         // attention logits, type 1
__device__ __align__(256) float g_X[NT*HH];       // node state between layers
__device__ __align__(256) int   g_deg[2][NN];
__device__ __align__(256) int   g_rowptr[2][NN+1];
__device__ __align__(256) int   g_eord[2][EE];

// ---------------- CSR build ----------------
__global__ void k_zero_deg() {
    int i = blockIdx.x*blockDim.x + threadIdx.x;
    if (i < 2*NN) ((int*)g_deg)[i] = 0;
}

__global__ void k_count(const int* __restrict__ ei) {
    int idx = blockIdx.x*blockDim.x + threadIdx.x;
    if (idx >= 2*EE) return;
    int ty = idx / EE, e = idx % EE;
    int dst = ei[ty*2*EE + EE + e];
    atomicAdd(&g_deg[ty][dst], 1);
}

__global__ void k_scan() {   // one block per edge type, exclusive scan
    int ty = blockIdx.x;
    __shared__ int sh[1024];
    __shared__ int carry;
    if (threadIdx.x == 0) carry = 0;
    __syncthreads();
    for (int base = 0; base < NN; base += 1024) {
        int i = base + threadIdx.x;
        int v = (i < NN) ? g_deg[ty][i] : 0;
        sh[threadIdx.x] = v;
        __syncthreads();
        for (int off = 1; off < 1024; off <<= 1) {
            int t = (threadIdx.x >= off) ? sh[threadIdx.x - off] : 0;
            __syncthreads();
            sh[threadIdx.x] += t;
            __syncthreads();
        }
        if (i < NN) g_rowptr[ty][i] = carry + sh[threadIdx.x] - v;
        __syncthreads();
        if (threadIdx.x == 0) carry += sh[1023];
        __syncthreads();
    }
    if (threadIdx.x == 0) g_rowptr[ty][NN] = carry;
}

__global__ void k_scatter(const int* __restrict__ ei) {
    int idx = blockIdx.x*blockDim.x + threadIdx.x;
    if (idx >= 2*EE) return;
    int ty = idx / EE, e = idx % EE;
    int dst = ei[ty*2*EE + EE + e];
    int pos = g_rowptr[ty][dst] + atomicAdd(&g_deg[ty][dst], 1);
    g_eord[ty][pos] = e;
}

// ---------------- GEMM x2: both edge types per layer, X read once ----------
// h_t = X @ W_t + b_t ; s_t = h_t . a_t  for t in {0,1}. 48KB dynamic smem.
__global__ void __launch_bounds__(128) k_gemm2(
    const float* __restrict__ Xin, int useX,
    const float* __restrict__ W, const float* __restrict__ bp,
    const float* __restrict__ ap, int l)
{
    extern __shared__ float smg[];
    float* Xs  = smg;            // 64x64
    float* Ws0 = smg + 4096;     // 64x64
    float* Ws1 = smg + 8192;     // 64x64
    const float* X = useX ? Xin : (const float*)g_X;
    const float* W0 = W + (size_t)(l*2+0)*4096;
    const float* W1 = W + (size_t)(l*2+1)*4096;

    int tid = threadIdx.x;
    int tx = tid & 15, ty = tid >> 4;     // ty in [0,8)
    int base = blockIdx.x * 64;

    const float4* Xg = (const float4*)(X + (size_t)base*64);
    #pragma unroll
    for (int v = 0; v < 8; v++) {
        int idx = tid + v*128;
        int row = idx >> 4;
        float4 val = make_float4(0.f,0.f,0.f,0.f);
        if (base + row < NT) val = Xg[idx];
        ((float4*)Xs)[idx] = val;
        ((float4*)Ws0)[idx] = ((const float4*)W0)[idx];
        ((float4*)Ws1)[idx] = ((const float4*)W1)[idx];
    }
    __syncthreads();

    float acc0[8][4], acc1[8][4];
    #pragma unroll
    for (int r = 0; r < 8; r++)
        #pragma unroll
        for (int c = 0; c < 4; c++) { acc0[r][c] = 0.f; acc1[r][c] = 0.f; }

    #pragma unroll 2
    for (int k = 0; k < 64; k++) {
        float4 b0 = ((const float4*)(Ws0 + k*64))[tx];
        float4 b1 = ((const float4*)(Ws1 + k*64))[tx];
        #pragma unroll
        for (int r = 0; r < 8; r++) {
            float av = Xs[(ty + r*8)*64 + k];
            acc0[r][0] += av*b0.x; acc0[r][1] += av*b0.y;
            acc0[r][2] += av*b0.z; acc0[r][3] += av*b0.w;
            acc1[r][0] += av*b1.x; acc1[r][1] += av*b1.y;
            acc1[r][2] += av*b1.z; acc1[r][3] += av*b1.w;
        }
    }

    const float* b0p = bp + (l*2+0)*64;
    const float* b1p = bp + (l*2+1)*64;
    const float* a0p = ap + (l*2+0)*64;
    const float* a1p = ap + (l*2+1)*64;
    float bb00=b0p[tx*4+0], bb01=b0p[tx*4+1], bb02=b0p[tx*4+2], bb03=b0p[tx*4+3];
    float aa00=a0p[tx*4+0], aa01=a0p[tx*4+1], aa02=a0p[tx*4+2], aa03=a0p[tx*4+3];
    float bb10=b1p[tx*4+0], bb11=b1p[tx*4+1], bb12=b1p[tx*4+2], bb13=b1p[tx*4+3];
    float aa10=a1p[tx*4+0], aa11=a1p[tx*4+1], aa12=a1p[tx*4+2], aa13=a1p[tx*4+3];

    #pragma unroll
    for (int r = 0; r < 8; r++) {
        int row = base + ty + r*8;
        float o0 = acc0[r][0]+bb00, o1 = acc0[r][1]+bb01;
        float o2 = acc0[r][2]+bb02, o3 = acc0[r][3]+bb03;
        float p0 = acc1[r][0]+bb10, p1 = acc1[r][1]+bb11;
        float p2 = acc1[r][2]+bb12, p3 = acc1[r][3]+bb13;
        if (row < NT) {
            float* h0r = g_h0 + (size_t)row*64 + tx*4;
            h0r[0]=o0; h0r[1]=o1; h0r[2]=o2; h0r[3]=o3;
            float* h1r = g_h1 + (size_t)row*64 + tx*4;
            h1r[0]=p0; h1r[1]=p1; h1r[2]=p2; h1r[3]=p3;
        }
        float d0 = o0*aa00 + o1*aa01 + o2*aa02 + o3*aa03;
        float d1 = p0*aa10 + p1*aa11 + p2*aa12 + p3*aa13;
        #pragma unroll
        for (int m = 8; m >= 1; m >>= 1) {
            d0 += __shfl_xor_sync(0xFFFFFFFFu, d0, m);
            d1 += __shfl_xor_sync(0xFFFFFFFFu, d1, m);
        }
        if (tx == 0 && row < NT) { g_s0[row] = d0; g_s1[row] = d1; }
    }
}

// ---------------- fused attention (both types) + residual + LayerNorm ------
// One block per destination node. Online softmax (single scalar pass), full
// h-row gather, then residual + LN entirely in registers/shuffles. Writes
// only g_X — the g_M round-trip is gone.
__global__ void __launch_bounds__(128) k_agg3(
    const float* __restrict__ xin, int useX,
    const int* __restrict__ ei, const float* __restrict__ ea,
    const float* __restrict__ lng, const float* __restrict__ lnb)
{
    int n = blockIdx.x;
    int tid = threadIdx.x;

    __shared__ float red_m[8][16], red_d[8][16];
    __shared__ float smax[10], sden[10];
    __shared__ float wsh[16][10];
    __shared__ int   ssrc[16];
    __shared__ float wsum[4][5], wsq[4][5];

    int ts = tid & 15, es = tid >> 4;
    float acc[5] = {0.f, 0.f, 0.f, 0.f, 0.f};

    #pragma unroll
    for (int ty = 0; ty < 2; ty++) {
        const float* sA   = ty ? (const float*)g_s1 : (const float*)g_s0;
        const float* hA   = ty ? (const float*)g_h1 : (const float*)g_h0;
        const float* eaA  = ea + ty*EE;
        const int*   srcA = ei + ty*2*EE;
        const int*   eord = g_eord[ty];
        int r0 = g_rowptr[ty][n], r1 = g_rowptr[ty][n+1];

        // online max + denominator in one pass
        float m = -1e30f, d = 0.f;
        if (ts < 10) {
            for (int j = r0 + es; j < r1; j += 8) {
                int src = srcA[eord[j]];
                float v = sA[src*TT + ts];
                float sc = v > 0.f ? v : 0.2f*v;
                if (sc > m) { d = d*__expf(m - sc) + 1.f; m = sc; }
                else        { d += __expf(sc - m); }
            }
        }
        red_m[es][ts] = m;
        red_d[es][ts] = d;
        __syncthreads();
        if (tid < 10) {
            float M = red_m[0][tid];
            #pragma unroll
            for (int i = 1; i < 8; i++) M = fmaxf(M, red_m[i][tid]);
            float D = 0.f;
            #pragma unroll
            for (int i = 0; i < 8; i++) D += red_d[i][tid]*__expf(red_m[i][tid] - M);
            smax[tid] = M;
            sden[tid] = D;
        }
        __syncthreads();

        // chunked weighted aggregation
        for (int j0 = r0; j0 < r1; j0 += 16) {
            int cnt = min(16, r1 - j0);
            for (int p = tid; p < cnt*10; p += 128) {
                int ce = p / 10, ct = p % 10;
                int e = eord[j0 + ce];
                int src = srcA[e];
                if (ct == 0) ssrc[ce] = src;
                float v = sA[src*TT + ct];
                float sc = v > 0.f ? v : 0.2f*v;
                wsh[ce][ct] = __expf(sc - smax[ct]) / (sden[ct] + 1e-16f) * eaA[e];
            }
            __syncthreads();
            for (int c = 0; c < cnt; c++) {
                const float* hrow = hA + (size_t)ssrc[c]*ROWF;
                #pragma unroll
                for (int i = 0; i < 5; i++) {
                    int pos = tid + i*128;
                    acc[i] += wsh[c][pos >> 6] * hrow[pos];
                }
            }
            __syncthreads();
        }
    }

    // residual + LayerNorm. pos = tid + i*128; row t = pos>>6; h = tid&63.
    const float* Xsrc = useX ? xin : (const float*)g_X;
    size_t nb = (size_t)n*ROWF;
    float val[5];
    #pragma unroll
    for (int i = 0; i < 5; i++)
        val[i] = Xsrc[nb + tid + i*128] + 0.5f*acc[i];

    int warp = tid >> 5, lane = tid & 31;
    #pragma unroll
    for (int i = 0; i < 5; i++) {
        float a = val[i], b = val[i]*val[i];
        #pragma unroll
        for (int m = 16; m >= 1; m >>= 1) {
            a += __shfl_xor_sync(0xFFFFFFFFu, a, m);
            b += __shfl_xor_sync(0xFFFFFFFFu, b, m);
        }
        if (lane == 0) { wsum[warp][i] = a; wsq[warp][i] = b; }
    }
    __syncthreads();
    float gw = lng[tid & 63], bw = lnb[tid & 63];
    #pragma unroll
    for (int i = 0; i < 5; i++) {
        float s = wsum[warp][i] + wsum[warp^1][i];
        float q = wsq[warp][i]  + wsq[warp^1][i];
        float mean = s * (1.f/64.f);
        float var  = q * (1.f/64.f) - mean*mean;
        float inv  = rsqrtf(var + 1e-5f);
        g_X[nb + tid + i*128] = (val[i] - mean)*inv*gw + bw;
    }
}

// ---------------- decoder v4: persistent blocks, weights staged once -------
#define DEC_SMEM_FLOATS 25216
#define DEC_GRID 296
__global__ void __launch_bounds__(256) k_dec4(
    const float* __restrict__ cw1, const float* __restrict__ cb1,
    const float* __restrict__ bn1g, const float* __restrict__ bn1b,
    const float* __restrict__ cw2, const float* __restrict__ cb2,
    const float* __restrict__ bn2g, const float* __restrict__ bn2b,
    const float* __restrict__ cw3, const float* __restrict__ cb3,
    float* __restrict__ out)
{
    extern __shared__ float sm[];
    float* ws1 = sm;                    // [r*65 + o], r = i*3+k, 192x64
    float* ws2 = sm + 12480;            // [r*33 + o], 192x32
    int tid = threadIdx.x;
    int nd  = tid >> 7;                 // node slot 0/1
    int wt  = tid & 127;
    float* nb  = sm + 18816 + nd*3200;
    float* xts = nb;                    // [12][64]
    float* c1s = nb + 768;              // [12][64]
    float* c2p = nb + 1536;             // [4][32][10]
    float* c2s = nb + 2816;             // [12][32]

    // stage + transpose weights once per block
    for (int idx = tid; idx < 12288; idx += 256) {
        int o = idx / 192, r = idx % 192;
        ws1[r*65 + o] = cw1[idx];
    }
    for (int idx = tid; idx < 6144; idx += 256) {
        int o = idx / 192, r = idx % 192;
        ws2[r*33 + o] = cw2[idx];
    }

    // per-thread loop-invariant params
    int o1 = wt >> 1, t0 = (wt & 1)*5;          // conv1 mapping
    float cb1v = cb1[o1];
    float sc1 = bn1g[o1]*BN_SCALE_C, sb1 = bn1b[o1];
    int o2 = wt & 31, seg = wt >> 5;            // conv2 mapping
    float sc2 = bn2g[o2]*BN_SCALE_C, sb2 = bn2b[o2], cb2v = cb2[o2];

    for (int pair = blockIdx.x; pair < NN/2; pair += DEC_GRID) {
        int n = pair*2 + nd;
        const float* xr = g_X + (size_t)n*ROWF;   // [t][h]
        for (int p = wt; p < 640; p += 128) {
            int t = p >> 6, h = p & 63;
            xts[(t+1)*64 + h] = xr[p];
        }
        if (wt < 64) { xts[wt] = 0.f; xts[11*64 + wt] = 0.f; }
        __syncthreads();

        // conv1 (64->64,k=3,pad=1) + BN + ReLU
        {
            float a0=cb1v, a1=cb1v, a2=cb1v, a3=cb1v, a4=cb1v;
            #pragma unroll 4
            for (int i = 0; i < 64; i++) {
                float x0=xts[(t0+0)*64+i], x1=xts[(t0+1)*64+i], x2=xts[(t0+2)*64+i];
                float x3=xts[(t0+3)*64+i], x4=xts[(t0+4)*64+i], x5=xts[(t0+5)*64+i];
                float x6=xts[(t0+6)*64+i];
                float w0=ws1[(i*3+0)*65+o1], w1=ws1[(i*3+1)*65+o1], w2=ws1[(i*3+2)*65+o1];
                a0 += w0*x0 + w1*x1 + w2*x2;
                a1 += w0*x1 + w1*x2 + w2*x3;
                a2 += w0*x2 + w1*x3 + w2*x4;
                a3 += w0*x3 + w1*x4 + w2*x5;
                a4 += w0*x4 + w1*x5 + w2*x6;
            }
            float v;
            v = a0*sc1 + sb1; c1s[(t0+1)*64+o1] = v > 0.f ? v : 0.f;
            v = a1*sc1 + sb1; c1s[(t0+2)*64+o1] = v > 0.f ? v : 0.f;
            v = a2*sc1 + sb1; c1s[(t0+3)*64+o1] = v > 0.f ? v : 0.f;
            v = a3*sc1 + sb1; c1s[(t0+4)*64+o1] = v > 0.f ? v : 0.f;
            v = a4*sc1 + sb1; c1s[(t0+5)*64+o1] = v > 0.f ? v : 0.f;
        }
        if (wt < 64) { c1s[wt] = 0.f; c1s[11*64 + wt] = 0.f; }
        __syncthreads();

        // conv2 (64->32,k=3,pad=1)
        {
            float acc2[10];
            #pragma unroll
            for (int t = 0; t < 10; t++) acc2[t] = 0.f;
            int i0 = seg*16;
            #pragma unroll 4
            for (int i = i0; i < i0+16; i++) {
                float w0=ws2[(i*3+0)*33+o2], w1=ws2[(i*3+1)*33+o2], w2=ws2[(i*3+2)*33+o2];
                #pragma unroll
                for (int t = 0; t < 10; t++)
                    acc2[t] += w0*c1s[t*64+i] + w1*c1s[(t+1)*64+i] + w2*c1s[(t+2)*64+i];
            }
            #pragma unroll
            for (int t = 0; t < 10; t++) c2p[seg*320 + o2*10 + t] = acc2[t];
        }
        __syncthreads();
        if (wt < 32) {
            int o = wt;
            #pragma unroll
            for (int t = 0; t < 10; t++) {
                float v = (c2p[o*10+t] + c2p[320+o*10+t] +
                           c2p[640+o*10+t] + c2p[960+o*10+t] + cb2v)*sc2 + sb2;
                c2s[(t+1)*32+o] = v > 0.f ? v : 0.f;
            }
            c2s[o] = 0.f; c2s[11*32+o] = 0.f;
        }
        __syncthreads();

        // conv3 (32->1,k=3,pad=1)
        if (wt < 10) {
            float acc3 = cb3[0];
            #pragma unroll 4
            for (int i = 0; i < 32; i++) {
                acc3 += cw3[i*3+0]*c2s[wt*32+i]
                      + cw3[i*3+1]*c2s[(wt+1)*32+i]
                      + cw3[i*3+2]*c2s[(wt+2)*32+i];
            }
            out[(size_t)n*10 + wt] = acc3;
        }
        __syncthreads();   // before next iteration overwrites smem
    }
}

// ---------------- launch ----------------------------------------------------
extern "C" void kernel_launch(void* const* d_in, const int* in_sizes, int n_in,
                              void* d_out, int out_size)
{
    const float* x    = (const float*)d_in[0];
    const int*   ei   = (const int*)  d_in[1];
    const float* ea   = (const float*)d_in[2];
    const float* W    = (const float*)d_in[3];
    const float* bp   = (const float*)d_in[4];
    const float* ap   = (const float*)d_in[5];
    const float* lng  = (const float*)d_in[6];
    const float* lnb  = (const float*)d_in[7];
    const float* cw1  = (const float*)d_in[8];
    const float* cb1  = (const float*)d_in[9];
    const float* bn1g = (const float*)d_in[10];
    const float* bn1b = (const float*)d_in[11];
    const float* cw2  = (const float*)d_in[12];
    const float* cb2  = (const float*)d_in[13];
    const float* bn2g = (const float*)d_in[14];
    const float* bn2b = (const float*)d_in[15];
    const float* cw3  = (const float*)d_in[16];
    const float* cb3  = (const float*)d_in[17];
    float* out = (float*)d_out;

    static int attr_set = 0;
    if (!attr_set) {
        cudaFuncSetAttribute(k_dec4, cudaFuncAttributeMaxDynamicSharedMemorySize,
                             DEC_SMEM_FLOATS*4);
        cudaFuncSetAttribute(k_gemm2, cudaFuncAttributeMaxDynamicSharedMemorySize,
                             49152);
        attr_set = 1;
    }

    // CSR build
    k_zero_deg<<<(2*NN + 255)/256, 256>>>();
    k_count<<<(2*EE + 255)/256, 256>>>(ei);
    k_scan<<<2, 1024>>>();
    k_zero_deg<<<(2*NN + 255)/256, 256>>>();
    k_scatter<<<(2*EE + 255)/256, 256>>>(ei);

    int gemm_grid = (NT + 63)/64;
    for (int l = 0; l < 2; l++) {
        int useX = (l == 0) ? 1 : 0;
        k_gemm2<<<gemm_grid, 128, 49152>>>(x, useX, W, bp, ap, l);
        k_agg3<<<NN, 128>>>(x, useX, ei, ea, lng + l*64, lnb + l*64);
    }

    k_dec4<<<DEC_GRID, 256, DEC_SMEM_FLOATS*4>>>(cw1, cb1, bn1g, bn1b,
                                                 cw2, cb2, bn2g, bn2b,
                                                 cw3, cb3, out);
}

// round 10
// speedup vs baseline: 2.2579x; 1.0888x over previous
#include <cuda_runtime.h>
#include <cuda_bf16.h>
#include <math.h>
#include <stdint.h>

#define NN 20000
#define TT 10
#define HH 64
#define EE 200000
#define NT (NN*TT)          // 200000 rows (NT % 64 == 0 -> no tile bounds checks)
#define ROWF 640            // T*H floats per node
#define BN_SCALE_C 0.99999500003749971893f

// ---------------- scratch (static device globals: allocation-free) ----------
__device__ __align__(256) float g_h0[NT*HH];      // projected features, type 0
__device__ __align__(256) float g_h1[NT*HH];      // projected features, type 1
__device__ __align__(256) float g_s0[NT];         // attention logits, type 0
__device__ __align__(256) float g_s1[NT];         // attention logits, type 1
__device__ __align__(256) float g_X[NT*HH];       // node state between layers
__device__ __align__(256) int   g_deg[2][NN];     // zero-init; self-restoring
__device__ __align__(256) int   g_rowptr[2][NN+1];
__device__ __align__(256) int   g_eord[2][EE];

// ---------------- CSR build (no zeroing kernels: deg self-restores) --------
__global__ void k_count(const int* __restrict__ ei) {
    int idx = blockIdx.x*blockDim.x + threadIdx.x;
    if (idx >= 2*EE) return;
    int ty = idx / EE, e = idx % EE;
    int dst = ei[ty*2*EE + EE + e];
    atomicAdd(&g_deg[ty][dst], 1);
}

__global__ void k_scan() {   // one block per edge type, exclusive scan
    int ty = blockIdx.x;
    __shared__ int sh[1024];
    __shared__ int carry;
    if (threadIdx.x == 0) carry = 0;
    __syncthreads();
    for (int base = 0; base < NN; base += 1024) {
        int i = base + threadIdx.x;
        int v = (i < NN) ? g_deg[ty][i] : 0;
        sh[threadIdx.x] = v;
        __syncthreads();
        for (int off = 1; off < 1024; off <<= 1) {
            int t = (threadIdx.x >= off) ? sh[threadIdx.x - off] : 0;
            __syncthreads();
            sh[threadIdx.x] += t;
            __syncthreads();
        }
        if (i < NN) g_rowptr[ty][i] = carry + sh[threadIdx.x] - v;
        __syncthreads();
        if (threadIdx.x == 0) carry += sh[1023];
        __syncthreads();
    }
    if (threadIdx.x == 0) g_rowptr[ty][NN] = carry;
}

__global__ void k_scatter(const int* __restrict__ ei) {
    int idx = blockIdx.x*blockDim.x + threadIdx.x;
    if (idx >= 2*EE) return;
    int ty = idx / EE, e = idx % EE;
    int dst = ei[ty*2*EE + EE + e];
    // decrement: deg returns to 0 after this kernel (deterministic precondition)
    int pos = g_rowptr[ty][dst] + (atomicSub(&g_deg[ty][dst], 1) - 1);
    g_eord[ty][pos] = e;
}

// ---------------- tensor-core GEMM (bf16x3 split), both edge types ---------
// h_t = X @ W_t + b_t ; s_t = h_t . a_t.  64x64 tile, 128 threads (4 warps),
// mma.sync m16n8k16 bf16, fp32 accum. X,W split hi/lo bf16; 3 MMAs recover
// ~1e-5 relative accuracy. smem rows padded to 72 bf16 (144B) => ldmatrix
// row addresses hit distinct banks.
#define GEMM_SMEM_BYTES 55296
__global__ void __launch_bounds__(128) k_gemm4(
    const float* __restrict__ Xin, int useX,
    const float* __restrict__ W, const float* __restrict__ bp,
    const float* __restrict__ ap, int l)
{
    extern __shared__ __nv_bfloat16 smb[];
    __nv_bfloat16* Xh = smb;                 // [64][72]
    __nv_bfloat16* Xl = smb + 4608;          // [64][72]
    __nv_bfloat16* Wt = smb + 9216;          // 4 x [64][72]: Wh0,Wl0,Wh1,Wl1

    const float* X = useX ? Xin : (const float*)g_X;
    int tid = threadIdx.x;
    int base = blockIdx.x * 64;

    // ---- convert X tile fp32 -> (hi,lo) bf16 in smem ----
    {
        const float4* Xg = (const float4*)(X + (size_t)base*64);
        #pragma unroll
        for (int v = 0; v < 8; v++) {
            int idx = tid + v*128;           // 1024 float4 = 4096 floats
            float4 x4 = Xg[idx];
            int row = idx >> 4, c = (idx & 15)*4;
            __nv_bfloat16 h0 = __float2bfloat16(x4.x);
            __nv_bfloat16 h1 = __float2bfloat16(x4.y);
            __nv_bfloat16 h2 = __float2bfloat16(x4.z);
            __nv_bfloat16 h3 = __float2bfloat16(x4.w);
            *(__nv_bfloat162*)(Xh + row*72 + c)     = __nv_bfloat162(h0, h1);
            *(__nv_bfloat162*)(Xh + row*72 + c + 2) = __nv_bfloat162(h2, h3);
            __nv_bfloat16 l0 = __float2bfloat16(x4.x - __bfloat162float(h0));
            __nv_bfloat16 l1 = __float2bfloat16(x4.y - __bfloat162float(h1));
            __nv_bfloat16 l2 = __float2bfloat16(x4.z - __bfloat162float(h2));
            __nv_bfloat16 l3 = __float2bfloat16(x4.w - __bfloat162float(h3));
            *(__nv_bfloat162*)(Xl + row*72 + c)     = __nv_bfloat162(l0, l1);
            *(__nv_bfloat162*)(Xl + row*72 + c + 2) = __nv_bfloat162(l2, l3);
        }
    }
    // ---- convert W tiles (both types) ----
    #pragma unroll
    for (int t = 0; t < 2; t++) {
        const float4* Wg = (const float4*)(W + (size_t)(l*2+t)*4096);
        __nv_bfloat16* wh = Wt + t*2*4608;
        __nv_bfloat16* wl = wh + 4608;
        #pragma unroll
        for (int v = 0; v < 8; v++) {
            int idx = tid + v*128;
            float4 w4 = Wg[idx];
            int row = idx >> 4, c = (idx & 15)*4;
            __nv_bfloat16 h0 = __float2bfloat16(w4.x);
            __nv_bfloat16 h1 = __float2bfloat16(w4.y);
            __nv_bfloat16 h2 = __float2bfloat16(w4.z);
            __nv_bfloat16 h3 = __float2bfloat16(w4.w);
            *(__nv_bfloat162*)(wh + row*72 + c)     = __nv_bfloat162(h0, h1);
            *(__nv_bfloat162*)(wh + row*72 + c + 2) = __nv_bfloat162(h2, h3);
            __nv_bfloat16 l0 = __float2bfloat16(w4.x - __bfloat162float(h0));
            __nv_bfloat16 l1 = __float2bfloat16(w4.y - __bfloat162float(h1));
            __nv_bfloat16 l2 = __float2bfloat16(w4.z - __bfloat162float(h2));
            __nv_bfloat16 l3 = __float2bfloat16(w4.w - __bfloat162float(h3));
            *(__nv_bfloat162*)(wl + row*72 + c)     = __nv_bfloat162(l0, l1);
            *(__nv_bfloat162*)(wl + row*72 + c + 2) = __nv_bfloat162(l2, l3);
        }
    }
    __syncthreads();

    int warp = tid >> 5, lane = tid & 31;
    int g = lane >> 2, tg = lane & 3;
    int m0 = warp*16;

    // per-lane ldmatrix row addresses
    // A (x4): lanes 0-15 -> rows m0+(lane&15) col 0; lanes 16-31 -> same rows col 8
    int a_row = m0 + (lane & 15);
    int a_col = (lane & 16) ? 8 : 0;
    uint32_t addrXh = (uint32_t)__cvta_generic_to_shared(Xh + a_row*72 + a_col);
    uint32_t addrXl = (uint32_t)__cvta_generic_to_shared(Xl + a_row*72 + a_col);
    // B (x2.trans): lanes 0-15 -> k-row (lane&15); col set per n-tile
    int b_row = (lane & 15);

    #pragma unroll
    for (int t = 0; t < 2; t++) {
        const __nv_bfloat16* wh = Wt + t*2*4608;
        const __nv_bfloat16* wl = wh + 4608;
        float c[8][4];
        #pragma unroll
        for (int n = 0; n < 8; n++)
            #pragma unroll
            for (int i = 0; i < 4; i++) c[n][i] = 0.f;

        #pragma unroll
        for (int ks = 0; ks < 4; ks++) {
            uint32_t ah0, ah1, ah2, ah3, al0, al1, al2, al3;
            asm volatile("ldmatrix.sync.aligned.m8n8.x4.shared.b16 {%0,%1,%2,%3}, [%4];"
                : "=r"(ah0), "=r"(ah1), "=r"(ah2), "=r"(ah3)
                : "r"(addrXh + ks*32));
            asm volatile("ldmatrix.sync.aligned.m8n8.x4.shared.b16 {%0,%1,%2,%3}, [%4];"
                : "=r"(al0), "=r"(al1), "=r"(al2), "=r"(al3)
                : "r"(addrXl + ks*32));
            uint32_t wbase_h = (uint32_t)__cvta_generic_to_shared(
                wh + (ks*16 + b_row)*72);
            uint32_t wbase_l = (uint32_t)__cvta_generic_to_shared(
                wl + (ks*16 + b_row)*72);
            #pragma unroll
            for (int n = 0; n < 8; n++) {
                uint32_t bh0, bh1, bl0, bl1;
                asm volatile("ldmatrix.sync.aligned.m8n8.x2.trans.shared.b16 {%0,%1}, [%2];"
                    : "=r"(bh0), "=r"(bh1) : "r"(wbase_h + n*16));
                asm volatile("ldmatrix.sync.aligned.m8n8.x2.trans.shared.b16 {%0,%1}, [%2];"
                    : "=r"(bl0), "=r"(bl1) : "r"(wbase_l + n*16));
                asm volatile("mma.sync.aligned.m16n8k16.row.col.f32.bf16.bf16.f32 "
                    "{%0,%1,%2,%3}, {%4,%5,%6,%7}, {%8,%9}, {%0,%1,%2,%3};"
                    : "+f"(c[n][0]), "+f"(c[n][1]), "+f"(c[n][2]), "+f"(c[n][3])
                    : "r"(ah0), "r"(ah1), "r"(ah2), "r"(ah3), "r"(bh0), "r"(bh1));
                asm volatile("mma.sync.aligned.m16n8k16.row.col.f32.bf16.bf16.f32 "
                    "{%0,%1,%2,%3}, {%4,%5,%6,%7}, {%8,%9}, {%0,%1,%2,%3};"
                    : "+f"(c[n][0]), "+f"(c[n][1]), "+f"(c[n][2]), "+f"(c[n][3])
                    : "r"(ah0), "r"(ah1), "r"(ah2), "r"(ah3), "r"(bl0), "r"(bl1));
                asm volatile("mma.sync.aligned.m16n8k16.row.col.f32.bf16.bf16.f32 "
                    "{%0,%1,%2,%3}, {%4,%5,%6,%7}, {%8,%9}, {%0,%1,%2,%3};"
                    : "+f"(c[n][0]), "+f"(c[n][1]), "+f"(c[n][2]), "+f"(c[n][3])
                    : "r"(al0), "r"(al1), "r"(al2), "r"(al3), "r"(bh0), "r"(bh1));
            }
        }

        // epilogue: bias, store h, fused s = h . a
        const float* bP = bp + (l*2+t)*64;
        const float* aP = ap + (l*2+t)*64;
        float* hout = t ? (float*)g_h1 : (float*)g_h0;
        float* sout = t ? (float*)g_s1 : (float*)g_s0;
        int r0 = base + m0 + g, r1 = r0 + 8;
        float sd0 = 0.f, sd1 = 0.f;
        #pragma unroll
        for (int n = 0; n < 8; n++) {
            int col = n*8 + tg*2;
            float bb0 = bP[col], bb1 = bP[col+1];
            float h00 = c[n][0] + bb0, h01 = c[n][1] + bb1;
            float h10 = c[n][2] + bb0, h11 = c[n][3] + bb1;
            *(float2*)(hout + (size_t)r0*64 + col) = make_float2(h00, h01);
            *(float2*)(hout + (size_t)r1*64 + col) = make_float2(h10, h11);
            float a0 = aP[col], a1 = aP[col+1];
            sd0 += h00*a0 + h01*a1;
            sd1 += h10*a0 + h11*a1;
        }
        sd0 += __shfl_xor_sync(0xFFFFFFFFu, sd0, 1);
        sd0 += __shfl_xor_sync(0xFFFFFFFFu, sd0, 2);
        sd1 += __shfl_xor_sync(0xFFFFFFFFu, sd1, 1);
        sd1 += __shfl_xor_sync(0xFFFFFFFFu, sd1, 2);
        if (tg == 0) { sout[r0] = sd0; sout[r1] = sd1; }
    }
}

// ---------------- fused attention (both types) + residual + LayerNorm ------
__global__ void __launch_bounds__(128) k_agg3(
    const float* __restrict__ xin, int useX,
    const int* __restrict__ ei, const float* __restrict__ ea,
    const float* __restrict__ lng, const float* __restrict__ lnb)
{
    int n = blockIdx.x;
    int tid = threadIdx.x;

    __shared__ float red_m[8][16], red_d[8][16];
    __shared__ float smax[10], sden[10];
    __shared__ float wsh[16][10];
    __shared__ int   ssrc[16];
    __shared__ float wsum[4][5], wsq[4][5];

    int ts = tid & 15, es = tid >> 4;
    float acc[5] = {0.f, 0.f, 0.f, 0.f, 0.f};

    #pragma unroll
    for (int ty = 0; ty < 2; ty++) {
        const float* sA   = ty ? (const float*)g_s1 : (const float*)g_s0;
        const float* hA   = ty ? (const float*)g_h1 : (const float*)g_h0;
        const float* eaA  = ea + ty*EE;
        const int*   srcA = ei + ty*2*EE;
        const int*   eord = g_eord[ty];
        int r0 = g_rowptr[ty][n], r1 = g_rowptr[ty][n+1];

        // online max + denominator in one pass
        float m = -1e30f, d = 0.f;
        if (ts < 10) {
            for (int j = r0 + es; j < r1; j += 8) {
                int src = srcA[eord[j]];
                float v = sA[src*TT + ts];
                float sc = v > 0.f ? v : 0.2f*v;
                if (sc > m) { d = d*__expf(m - sc) + 1.f; m = sc; }
                else        { d += __expf(sc - m); }
            }
        }
        red_m[es][ts] = m;
        red_d[es][ts] = d;
        __syncthreads();
        if (tid < 10) {
            float M = red_m[0][tid];
            #pragma unroll
            for (int i = 1; i < 8; i++) M = fmaxf(M, red_m[i][tid]);
            float D = 0.f;
            #pragma unroll
            for (int i = 0; i < 8; i++) D += red_d[i][tid]*__expf(red_m[i][tid] - M);
            smax[tid] = M;
            sden[tid] = D;
        }
        __syncthreads();

        // chunked weighted aggregation
        for (int j0 = r0; j0 < r1; j0 += 16) {
            int cnt = min(16, r1 - j0);
            for (int p = tid; p < cnt*10; p += 128) {
                int ce = p / 10, ct = p % 10;
                int e = eord[j0 + ce];
                int src = srcA[e];
                if (ct == 0) ssrc[ce] = src;
                float v = sA[src*TT + ct];
                float sc = v > 0.f ? v : 0.2f*v;
                wsh[ce][ct] = __expf(sc - smax[ct]) / (sden[ct] + 1e-16f) * eaA[e];
            }
            __syncthreads();
            for (int c = 0; c < cnt; c++) {
                const float* hrow = hA + (size_t)ssrc[c]*ROWF;
                #pragma unroll
                for (int i = 0; i < 5; i++) {
                    int pos = tid + i*128;
                    acc[i] += wsh[c][pos >> 6] * hrow[pos];
                }
            }
            __syncthreads();
        }
    }

    // residual + LayerNorm (in registers/shuffles)
    const float* Xsrc = useX ? xin : (const float*)g_X;
    size_t nb = (size_t)n*ROWF;
    float val[5];
    #pragma unroll
    for (int i = 0; i < 5; i++)
        val[i] = Xsrc[nb + tid + i*128] + 0.5f*acc[i];

    int warp = tid >> 5, lane = tid & 31;
    #pragma unroll
    for (int i = 0; i < 5; i++) {
        float a = val[i], b = val[i]*val[i];
        #pragma unroll
        for (int m = 16; m >= 1; m >>= 1) {
            a += __shfl_xor_sync(0xFFFFFFFFu, a, m);
            b += __shfl_xor_sync(0xFFFFFFFFu, b, m);
        }
        if (lane == 0) { wsum[warp][i] = a; wsq[warp][i] = b; }
    }
    __syncthreads();
    float gw = lng[tid & 63], bw = lnb[tid & 63];
    #pragma unroll
    for (int i = 0; i < 5; i++) {
        float s = wsum[warp][i] + wsum[warp^1][i];
        float q = wsq[warp][i]  + wsq[warp^1][i];
        float mean = s * (1.f/64.f);
        float var  = q * (1.f/64.f) - mean*mean;
        float inv  = rsqrtf(var + 1e-5f);
        g_X[nb + tid + i*128] = (val[i] - mean)*inv*gw + bw;
    }
}

// ---------------- decoder v4: persistent blocks, weights staged once -------
#define DEC_SMEM_FLOATS 25216
#define DEC_GRID 296
__global__ void __launch_bounds__(256) k_dec4(
    const float* __restrict__ cw1, const float* __restrict__ cb1,
    const float* __restrict__ bn1g, const float* __restrict__ bn1b,
    const float* __restrict__ cw2, const float* __restrict__ cb2,
    const float* __restrict__ bn2g, const float* __restrict__ bn2b,
    const float* __restrict__ cw3, const float* __restrict__ cb3,
    float* __restrict__ out)
{
    extern __shared__ float sm[];
    float* ws1 = sm;                    // [r*65 + o], r = i*3+k, 192x64
    float* ws2 = sm + 12480;            // [r*33 + o], 192x32
    int tid = threadIdx.x;
    int nd  = tid >> 7;
    int wt  = tid & 127;
    float* nb  = sm + 18816 + nd*3200;
    float* xts = nb;                    // [12][64]
    float* c1s = nb + 768;              // [12][64]
    float* c2p = nb + 1536;             // [4][32][10]
    float* c2s = nb + 2816;             // [12][32]

    for (int idx = tid; idx < 12288; idx += 256) {
        int o = idx / 192, r = idx % 192;
        ws1[r*65 + o] = cw1[idx];
    }
    for (int idx = tid; idx < 6144; idx += 256) {
        int o = idx / 192, r = idx % 192;
        ws2[r*33 + o] = cw2[idx];
    }

    int o1 = wt >> 1, t0 = (wt & 1)*5;
    float cb1v = cb1[o1];
    float sc1 = bn1g[o1]*BN_SCALE_C, sb1 = bn1b[o1];
    int o2 = wt & 31, seg = wt >> 5;
    float sc2 = bn2g[o2]*BN_SCALE_C, sb2 = bn2b[o2], cb2v = cb2[o2];

    for (int pair = blockIdx.x; pair < NN/2; pair += DEC_GRID) {
        int n = pair*2 + nd;
        const float* xr = g_X + (size_t)n*ROWF;
        for (int p = wt; p < 640; p += 128) {
            int t = p >> 6, h = p & 63;
            xts[(t+1)*64 + h] = xr[p];
        }
        if (wt < 64) { xts[wt] = 0.f; xts[11*64 + wt] = 0.f; }
        __syncthreads();

        // conv1 + BN + ReLU
        {
            float a0=cb1v, a1=cb1v, a2=cb1v, a3=cb1v, a4=cb1v;
            #pragma unroll 4
            for (int i = 0; i < 64; i++) {
                float x0=xts[(t0+0)*64+i], x1=xts[(t0+1)*64+i], x2=xts[(t0+2)*64+i];
                float x3=xts[(t0+3)*64+i], x4=xts[(t0+4)*64+i], x5=xts[(t0+5)*64+i];
                float x6=xts[(t0+6)*64+i];
                float w0=ws1[(i*3+0)*65+o1], w1=ws1[(i*3+1)*65+o1], w2=ws1[(i*3+2)*65+o1];
                a0 += w0*x0 + w1*x1 + w2*x2;
                a1 += w0*x1 + w1*x2 + w2*x3;
                a2 += w0*x2 + w1*x3 + w2*x4;
                a3 += w0*x3 + w1*x4 + w2*x5;
                a4 += w0*x4 + w1*x5 + w2*x6;
            }
            float v;
            v = a0*sc1 + sb1; c1s[(t0+1)*64+o1] = v > 0.f ? v : 0.f;
            v = a1*sc1 + sb1; c1s[(t0+2)*64+o1] = v > 0.f ? v : 0.f;
            v = a2*sc1 + sb1; c1s[(t0+3)*64+o1] = v > 0.f ? v : 0.f;
            v = a3*sc1 + sb1; c1s[(t0+4)*64+o1] = v > 0.f ? v : 0.f;
            v = a4*sc1 + sb1; c1s[(t0+5)*64+o1] = v > 0.f ? v : 0.f;
        }
        if (wt < 64) { c1s[wt] = 0.f; c1s[11*64 + wt] = 0.f; }
        __syncthreads();

        // conv2
        {
            float acc2[10];
            #pragma unroll
            for (int t = 0; t < 10; t++) acc2[t] = 0.f;
            int i0 = seg*16;
            #pragma unroll 4
            for (int i = i0; i < i0+16; i++) {
                float w0=ws2[(i*3+0)*33+o2], w1=ws2[(i*3+1)*33+o2], w2=ws2[(i*3+2)*33+o2];
                #pragma unroll
                for (int t = 0; t < 10; t++)
                    acc2[t] += w0*c1s[t*64+i] + w1*c1s[(t+1)*64+i] + w2*c1s[(t+2)*64+i];
            }
            #pragma unroll
            for (int t = 0; t < 10; t++) c2p[seg*320 + o2*10 + t] = acc2[t];
        }
        __syncthreads();
        if (wt < 32) {
            int o = wt;
            #pragma unroll
            for (int t = 0; t < 10; t++) {
                float v = (c2p[o*10+t] + c2p[320+o*10+t] +
                           c2p[640+o*10+t] + c2p[960+o*10+t] + cb2v)*sc2 + sb2;
                c2s[(t+1)*32+o] = v > 0.f ? v : 0.f;
            }
            c2s[o] = 0.f; c2s[11*32+o] = 0.f;
        }
        __syncthreads();

        // conv3
        if (wt < 10) {
            float acc3 = cb3[0];
            #pragma unroll 4
            for (int i = 0; i < 32; i++) {
                acc3 += cw3[i*3+0]*c2s[wt*32+i]
                      + cw3[i*3+1]*c2s[(wt+1)*32+i]
                      + cw3[i*3+2]*c2s[(wt+2)*32+i];
            }
            out[(size_t)n*10 + wt] = acc3;
        }
        __syncthreads();
    }
}

// ---------------- launch ----------------------------------------------------
extern "C" void kernel_launch(void* const* d_in, const int* in_sizes, int n_in,
                              void* d_out, int out_size)
{
    const float* x    = (const float*)d_in[0];
    const int*   ei   = (const int*)  d_in[1];
    const float* ea   = (const float*)d_in[2];
    const float* W    = (const float*)d_in[3];
    const float* bp   = (const float*)d_in[4];
    const float* ap   = (const float*)d_in[5];
    const float* lng  = (const float*)d_in[6];
    const float* lnb  = (const float*)d_in[7];
    const float* cw1  = (const float*)d_in[8];
    const float* cb1  = (const float*)d_in[9];
    const float* bn1g = (const float*)d_in[10];
    const float* bn1b = (const float*)d_in[11];
    const float* cw2  = (const float*)d_in[12];
    const float* cb2  = (const float*)d_in[13];
    const float* bn2g = (const float*)d_in[14];
    const float* bn2b = (const float*)d_in[15];
    const float* cw3  = (const float*)d_in[16];
    const float* cb3  = (const float*)d_in[17];
    float* out = (float*)d_out;

    static int attr_set = 0;
    if (!attr_set) {
        cudaFuncSetAttribute(k_dec4, cudaFuncAttributeMaxDynamicSharedMemorySize,
                             DEC_SMEM_FLOATS*4);
        cudaFuncSetAttribute(k_gemm4, cudaFuncAttributeMaxDynamicSharedMemorySize,
                             GEMM_SMEM_BYTES);
        attr_set = 1;
    }

    // CSR build (g_deg statically zero; scatter restores it to zero)
    k_count<<<(2*EE + 255)/256, 256>>>(ei);
    k_scan<<<2, 1024>>>();
    k_scatter<<<(2*EE + 255)/256, 256>>>(ei);

    int gemm_grid = NT/64;   // 3125, exact
    for (int l = 0; l < 2; l++) {
        int useX = (l == 0) ? 1 : 0;
        k_gemm4<<<gemm_grid, 128, GEMM_SMEM_BYTES>>>(x, useX, W, bp, ap, l);
        k_agg3<<<NN, 128>>>(x, useX, ei, ea, lng + l*64, lnb + l*64);
    }

    k_dec4<<<DEC_GRID, 256, DEC_SMEM_FLOATS*4>>>(cw1, cb1, bn1g, bn1b,
                                                 cw2, cb2, bn2g, bn2b,
                                                 cw3, cb3, out);
}

// round 11
// speedup vs baseline: 2.8626x; 1.2678x over previous
#include <cuda_runtime.h>
#include <cuda_bf16.h>
#include <math.h>
#include <stdint.h>

#define NN 20000
#define TT 10
#define HH 64
#define EE 200000
#define NT (NN*TT)          // 200000 rows (NT % 64 == 0)
#define ROWF 640
#define BN_SCALE_C 0.99999500003749971893f

// ---------------- scratch ----------------
__device__ __align__(256) float g_h0[NT*HH];
__device__ __align__(256) float g_h1[NT*HH];
__device__ __align__(256) float g_s0[NT];
__device__ __align__(256) float g_s1[NT];
__device__ __align__(256) float g_X[NT*HH];
__device__ __align__(256) float g_c1[NT*64];      // decoder conv1 output
__device__ __align__(256) float g_c2[NT*32];      // decoder conv2 output
__device__ __align__(256) int   g_deg[2][NN];     // zero-init; self-restoring
__device__ __align__(256) int   g_rowptr[2][NN+1];
__device__ __align__(256) int   g_eord[2][EE];

// ---------------- CSR build ----------------
__global__ void k_count(const int* __restrict__ ei) {
    int idx = blockIdx.x*blockDim.x + threadIdx.x;
    if (idx >= 2*EE) return;
    int ty = idx / EE, e = idx % EE;
    int dst = ei[ty*2*EE + EE + e];
    atomicAdd(&g_deg[ty][dst], 1);
}

// warp-shuffle scan: thread-serial 20 elems + 2-level shuffle scan, 2 barriers
__global__ void k_scan() {
    int ty = blockIdx.x;
    __shared__ int wsums[32];
    int tid = threadIdx.x;
    int lane = tid & 31, w = tid >> 5;
    int start = tid * 20;
    int vals[20];
    int local = 0;
    #pragma unroll
    for (int j = 0; j < 20; j++) {
        int i = start + j;
        vals[j] = (i < NN) ? g_deg[ty][i] : 0;
        local += vals[j];
    }
    int pre = local;
    #pragma unroll
    for (int o = 1; o < 32; o <<= 1) {
        int v = __shfl_up_sync(0xFFFFFFFFu, pre, o);
        if (lane >= o) pre += v;
    }
    if (lane == 31) wsums[w] = pre;
    __syncthreads();
    if (w == 0) {
        int v = wsums[lane];
        int p = v;
        #pragma unroll
        for (int o = 1; o < 32; o <<= 1) {
            int t2 = __shfl_up_sync(0xFFFFFFFFu, p, o);
            if (lane >= o) p += t2;
        }
        wsums[lane] = p - v;   // exclusive
    }
    __syncthreads();
    int offset = wsums[w] + pre - local;
    #pragma unroll
    for (int j = 0; j < 20; j++) {
        int i = start + j;
        if (i < NN) g_rowptr[ty][i] = offset;
        offset += vals[j];
    }
    if (tid == 1023) g_rowptr[ty][NN] = offset;
}

__global__ void k_scatter(const int* __restrict__ ei) {
    int idx = blockIdx.x*blockDim.x + threadIdx.x;
    if (idx >= 2*EE) return;
    int ty = idx / EE, e = idx % EE;
    int dst = ei[ty*2*EE + EE + e];
    int pos = g_rowptr[ty][dst] + (atomicSub(&g_deg[ty][dst], 1) - 1);
    g_eord[ty][pos] = e;
}

// ---------------- helpers: fp32 -> bf16 hi/lo split --------------------------
__device__ __forceinline__ void split4(float4 v, __nv_bfloat16* hi, __nv_bfloat16* lo) {
    __nv_bfloat16 h0 = __float2bfloat16(v.x), h1 = __float2bfloat16(v.y);
    __nv_bfloat16 h2 = __float2bfloat16(v.z), h3 = __float2bfloat16(v.w);
    *(__nv_bfloat162*)(hi)     = __nv_bfloat162(h0, h1);
    *(__nv_bfloat162*)(hi + 2) = __nv_bfloat162(h2, h3);
    *(__nv_bfloat162*)(lo)     = __nv_bfloat162(
        __float2bfloat16(v.x - __bfloat162float(h0)),
        __float2bfloat16(v.y - __bfloat162float(h1)));
    *(__nv_bfloat162*)(lo + 2) = __nv_bfloat162(
        __float2bfloat16(v.z - __bfloat162float(h2)),
        __float2bfloat16(v.w - __bfloat162float(h3)));
}

// ---------------- tensor-core GEMM (bf16x3 split), both edge types ---------
#define GEMM_SMEM_BYTES 55296
__global__ void __launch_bounds__(128) k_gemm4(
    const float* __restrict__ Xin, int useX,
    const float* __restrict__ W, const float* __restrict__ bp,
    const float* __restrict__ ap, int l)
{
    extern __shared__ __nv_bfloat16 smb[];
    __nv_bfloat16* Xh = smb;                 // [64][72]
    __nv_bfloat16* Xl = smb + 4608;
    __nv_bfloat16* Wt = smb + 9216;          // Wh0,Wl0,Wh1,Wl1

    const float* X = useX ? Xin : (const float*)g_X;
    int tid = threadIdx.x;
    int base = blockIdx.x * 64;

    {
        const float4* Xg = (const float4*)(X + (size_t)base*64);
        #pragma unroll
        for (int v = 0; v < 8; v++) {
            int idx = tid + v*128;
            float4 x4 = Xg[idx];
            int row = idx >> 4, c = (idx & 15)*4;
            split4(x4, Xh + row*72 + c, Xl + row*72 + c);
        }
    }
    #pragma unroll
    for (int t = 0; t < 2; t++) {
        const float4* Wg = (const float4*)(W + (size_t)(l*2+t)*4096);
        __nv_bfloat16* wh = Wt + t*2*4608;
        __nv_bfloat16* wl = wh + 4608;
        #pragma unroll
        for (int v = 0; v < 8; v++) {
            int idx = tid + v*128;
            float4 w4 = Wg[idx];
            int row = idx >> 4, c = (idx & 15)*4;
            split4(w4, wh + row*72 + c, wl + row*72 + c);
        }
    }
    __syncthreads();

    int warp = tid >> 5, lane = tid & 31;
    int g = lane >> 2, tg = lane & 3;
    int m0 = warp*16;
    int a_row = m0 + (lane & 15);
    int a_col = (lane & 16) ? 8 : 0;
    uint32_t addrXh = (uint32_t)__cvta_generic_to_shared(Xh + a_row*72 + a_col);
    uint32_t addrXl = (uint32_t)__cvta_generic_to_shared(Xl + a_row*72 + a_col);
    int b_row = (lane & 15);

    #pragma unroll
    for (int t = 0; t < 2; t++) {
        const __nv_bfloat16* wh = Wt + t*2*4608;
        const __nv_bfloat16* wl = wh + 4608;
        float c[8][4];
        #pragma unroll
        for (int n = 0; n < 8; n++)
            #pragma unroll
            for (int i = 0; i < 4; i++) c[n][i] = 0.f;

        #pragma unroll
        for (int ks = 0; ks < 4; ks++) {
            uint32_t ah0, ah1, ah2, ah3, al0, al1, al2, al3;
            asm volatile("ldmatrix.sync.aligned.m8n8.x4.shared.b16 {%0,%1,%2,%3}, [%4];"
                : "=r"(ah0), "=r"(ah1), "=r"(ah2), "=r"(ah3) : "r"(addrXh + ks*32));
            asm volatile("ldmatrix.sync.aligned.m8n8.x4.shared.b16 {%0,%1,%2,%3}, [%4];"
                : "=r"(al0), "=r"(al1), "=r"(al2), "=r"(al3) : "r"(addrXl + ks*32));
            uint32_t wbh = (uint32_t)__cvta_generic_to_shared(wh + (ks*16 + b_row)*72);
            uint32_t wbl = (uint32_t)__cvta_generic_to_shared(wl + (ks*16 + b_row)*72);
            #pragma unroll
            for (int n = 0; n < 8; n++) {
                uint32_t bh0, bh1, bl0, bl1;
                asm volatile("ldmatrix.sync.aligned.m8n8.x2.trans.shared.b16 {%0,%1}, [%2];"
                    : "=r"(bh0), "=r"(bh1) : "r"(wbh + n*16));
                asm volatile("ldmatrix.sync.aligned.m8n8.x2.trans.shared.b16 {%0,%1}, [%2];"
                    : "=r"(bl0), "=r"(bl1) : "r"(wbl + n*16));
                asm volatile("mma.sync.aligned.m16n8k16.row.col.f32.bf16.bf16.f32 "
                    "{%0,%1,%2,%3}, {%4,%5,%6,%7}, {%8,%9}, {%0,%1,%2,%3};"
                    : "+f"(c[n][0]), "+f"(c[n][1]), "+f"(c[n][2]), "+f"(c[n][3])
                    : "r"(ah0), "r"(ah1), "r"(ah2), "r"(ah3), "r"(bh0), "r"(bh1));
                asm volatile("mma.sync.aligned.m16n8k16.row.col.f32.bf16.bf16.f32 "
                    "{%0,%1,%2,%3}, {%4,%5,%6,%7}, {%8,%9}, {%0,%1,%2,%3};"
                    : "+f"(c[n][0]), "+f"(c[n][1]), "+f"(c[n][2]), "+f"(c[n][3])
                    : "r"(ah0), "r"(ah1), "r"(ah2), "r"(ah3), "r"(bl0), "r"(bl1));
                asm volatile("mma.sync.aligned.m16n8k16.row.col.f32.bf16.bf16.f32 "
                    "{%0,%1,%2,%3}, {%4,%5,%6,%7}, {%8,%9}, {%0,%1,%2,%3};"
                    : "+f"(c[n][0]), "+f"(c[n][1]), "+f"(c[n][2]), "+f"(c[n][3])
                    : "r"(al0), "r"(al1), "r"(al2), "r"(al3), "r"(bh0), "r"(bh1));
            }
        }

        const float* bP = bp + (l*2+t)*64;
        const float* aP = ap + (l*2+t)*64;
        float* hout = t ? (float*)g_h1 : (float*)g_h0;
        float* sout = t ? (float*)g_s1 : (float*)g_s0;
        int r0 = base + m0 + g, r1 = r0 + 8;
        float sd0 = 0.f, sd1 = 0.f;
        #pragma unroll
        for (int n = 0; n < 8; n++) {
            int col = n*8 + tg*2;
            float bb0 = bP[col], bb1 = bP[col+1];
            float h00 = c[n][0] + bb0, h01 = c[n][1] + bb1;
            float h10 = c[n][2] + bb0, h11 = c[n][3] + bb1;
            *(float2*)(hout + (size_t)r0*64 + col) = make_float2(h00, h01);
            *(float2*)(hout + (size_t)r1*64 + col) = make_float2(h10, h11);
            float a0 = aP[col], a1 = aP[col+1];
            sd0 += h00*a0 + h01*a1;
            sd1 += h10*a0 + h11*a1;
        }
        sd0 += __shfl_xor_sync(0xFFFFFFFFu, sd0, 1);
        sd0 += __shfl_xor_sync(0xFFFFFFFFu, sd0, 2);
        sd1 += __shfl_xor_sync(0xFFFFFFFFu, sd1, 1);
        sd1 += __shfl_xor_sync(0xFFFFFFFFu, sd1, 2);
        if (tg == 0) { sout[r0] = sd0; sout[r1] = sd1; }
    }
}

// ---------------- fused attention (both types) + residual + LayerNorm ------
__global__ void __launch_bounds__(128) k_agg3(
    const float* __restrict__ xin, int useX,
    const int* __restrict__ ei, const float* __restrict__ ea,
    const float* __restrict__ lng, const float* __restrict__ lnb)
{
    int n = blockIdx.x;
    int tid = threadIdx.x;

    __shared__ float red_m[8][16], red_d[8][16];
    __shared__ float smax[10], sden[10];
    __shared__ float wsh[16][10];
    __shared__ int   ssrc[16];
    __shared__ float wsum[4][5], wsq[4][5];

    int ts = tid & 15, es = tid >> 4;
    float acc[5] = {0.f, 0.f, 0.f, 0.f, 0.f};

    #pragma unroll
    for (int ty = 0; ty < 2; ty++) {
        const float* sA   = ty ? (const float*)g_s1 : (const float*)g_s0;
        const float* hA   = ty ? (const float*)g_h1 : (const float*)g_h0;
        const float* eaA  = ea + ty*EE;
        const int*   srcA = ei + ty*2*EE;
        const int*   eord = g_eord[ty];
        int r0 = g_rowptr[ty][n], r1 = g_rowptr[ty][n+1];

        float m = -1e30f, d = 0.f;
        if (ts < 10) {
            for (int j = r0 + es; j < r1; j += 8) {
                int src = srcA[eord[j]];
                float v = sA[src*TT + ts];
                float sc = v > 0.f ? v : 0.2f*v;
                if (sc > m) { d = d*__expf(m - sc) + 1.f; m = sc; }
                else        { d += __expf(sc - m); }
            }
        }
        red_m[es][ts] = m;
        red_d[es][ts] = d;
        __syncthreads();
        if (tid < 10) {
            float M = red_m[0][tid];
            #pragma unroll
            for (int i = 1; i < 8; i++) M = fmaxf(M, red_m[i][tid]);
            float D = 0.f;
            #pragma unroll
            for (int i = 0; i < 8; i++) D += red_d[i][tid]*__expf(red_m[i][tid] - M);
            smax[tid] = M;
            sden[tid] = D;
        }
        __syncthreads();

        for (int j0 = r0; j0 < r1; j0 += 16) {
            int cnt = min(16, r1 - j0);
            for (int p = tid; p < cnt*10; p += 128) {
                int ce = p / 10, ct = p % 10;
                int e = eord[j0 + ce];
                int src = srcA[e];
                if (ct == 0) ssrc[ce] = src;
                float v = sA[src*TT + ct];
                float sc = v > 0.f ? v : 0.2f*v;
                wsh[ce][ct] = __expf(sc - smax[ct]) / (sden[ct] + 1e-16f) * eaA[e];
            }
            __syncthreads();
            for (int c = 0; c < cnt; c++) {
                const float* hrow = hA + (size_t)ssrc[c]*ROWF;
                #pragma unroll
                for (int i = 0; i < 5; i++) {
                    int pos = tid + i*128;
                    acc[i] += wsh[c][pos >> 6] * hrow[pos];
                }
            }
            __syncthreads();
        }
    }

    const float* Xsrc = useX ? xin : (const float*)g_X;
    size_t nb = (size_t)n*ROWF;
    float val[5];
    #pragma unroll
    for (int i = 0; i < 5; i++)
        val[i] = Xsrc[nb + tid + i*128] + 0.5f*acc[i];

    int warp = tid >> 5, lane = tid & 31;
    #pragma unroll
    for (int i = 0; i < 5; i++) {
        float a = val[i], b = val[i]*val[i];
        #pragma unroll
        for (int m = 16; m >= 1; m >>= 1) {
            a += __shfl_xor_sync(0xFFFFFFFFu, a, m);
            b += __shfl_xor_sync(0xFFFFFFFFu, b, m);
        }
        if (lane == 0) { wsum[warp][i] = a; wsq[warp][i] = b; }
    }
    __syncthreads();
    float gw = lng[tid & 63], bw = lnb[tid & 63];
    #pragma unroll
    for (int i = 0; i < 5; i++) {
        float s = wsum[warp][i] + wsum[warp^1][i];
        float q = wsq[warp][i]  + wsq[warp^1][i];
        float mean = s * (1.f/64.f);
        float var  = q * (1.f/64.f) - mean*mean;
        float inv  = rsqrtf(var + 1e-5f);
        g_X[nb + tid + i*128] = (val[i] - mean)*inv*gw + bw;
    }
}

// ---------------- tensorized decoder conv1 (64->64, k=3) --------------------
// Persistent 296 blocks. Per tile: 3 time-shifted A tiles (boundary-zeroed),
// accumulate 3 shifted GEMMs into one accumulator set. W staged/split once.
#define CONV_SMEM_BYTES 110592
#define CONV_GRID 296
__global__ void __launch_bounds__(128) k_conv1(
    const float* __restrict__ cw1, const float* __restrict__ cb1,
    const float* __restrict__ bn1g, const float* __restrict__ bn1b)
{
    extern __shared__ __nv_bfloat16 smc[];
    __nv_bfloat16* A  = smc;            // [shift][hi/lo][64*72] : 6*4608
    __nv_bfloat16* Wk = smc + 27648;    // [k][hi/lo][64*72]     : 6*4608
    int tid = threadIdx.x;

    // stage + split W once per block: Wk slice k holds [i][o]
    for (int idx = tid; idx < 4096; idx += 128) {
        int i = idx >> 6, o = idx & 63;
        #pragma unroll
        for (int k = 0; k < 3; k++) {
            float w = cw1[o*192 + i*3 + k];
            __nv_bfloat16 h = __float2bfloat16(w);
            Wk[(k*2+0)*4608 + i*72 + o] = h;
            Wk[(k*2+1)*4608 + i*72 + o] = __float2bfloat16(w - __bfloat162float(h));
        }
    }
    __syncthreads();

    int warp = tid >> 5, lane = tid & 31;
    int g = lane >> 2, tg = lane & 3;
    int m0 = warp*16;
    int a_row = m0 + (lane & 15);
    int a_col = (lane & 16) ? 8 : 0;
    int b_row = (lane & 15);

    for (int tile = blockIdx.x; tile < NT/64; tile += CONV_GRID) {
        int base = tile*64;
        // build 3 shifted A tiles
        for (int idx = tid; idx < 1024; idx += 128) {
            int row = idx >> 4, c4 = (idx & 15)*4;
            int t = (base + row) % 10;
            #pragma unroll
            for (int s = 0; s < 3; s++) {
                int dt = s - 1;
                float4 x4 = make_float4(0.f,0.f,0.f,0.f);
                if ((unsigned)(t + dt) < 10u)
                    x4 = *(const float4*)(g_X + (size_t)(base + row + dt)*64 + c4);
                split4(x4, A + (s*2+0)*4608 + row*72 + c4,
                           A + (s*2+1)*4608 + row*72 + c4);
            }
        }
        __syncthreads();

        float c[8][4];
        #pragma unroll
        for (int n = 0; n < 8; n++)
            #pragma unroll
            for (int i = 0; i < 4; i++) c[n][i] = 0.f;

        #pragma unroll
        for (int s = 0; s < 3; s++) {
            uint32_t aH = (uint32_t)__cvta_generic_to_shared(
                A + (s*2+0)*4608 + a_row*72 + a_col);
            uint32_t aL = (uint32_t)__cvta_generic_to_shared(
                A + (s*2+1)*4608 + a_row*72 + a_col);
            #pragma unroll
            for (int ks = 0; ks < 4; ks++) {
                uint32_t ah0, ah1, ah2, ah3, al0, al1, al2, al3;
                asm volatile("ldmatrix.sync.aligned.m8n8.x4.shared.b16 {%0,%1,%2,%3}, [%4];"
                    : "=r"(ah0), "=r"(ah1), "=r"(ah2), "=r"(ah3) : "r"(aH + ks*32));
                asm volatile("ldmatrix.sync.aligned.m8n8.x4.shared.b16 {%0,%1,%2,%3}, [%4];"
                    : "=r"(al0), "=r"(al1), "=r"(al2), "=r"(al3) : "r"(aL + ks*32));
                uint32_t wbh = (uint32_t)__cvta_generic_to_shared(
                    Wk + (s*2+0)*4608 + (ks*16 + b_row)*72);
                uint32_t wbl = (uint32_t)__cvta_generic_to_shared(
                    Wk + (s*2+1)*4608 + (ks*16 + b_row)*72);
                #pragma unroll
                for (int n = 0; n < 8; n++) {
                    uint32_t bh0, bh1, bl0, bl1;
                    asm volatile("ldmatrix.sync.aligned.m8n8.x2.trans.shared.b16 {%0,%1}, [%2];"
                        : "=r"(bh0), "=r"(bh1) : "r"(wbh + n*16));
                    asm volatile("ldmatrix.sync.aligned.m8n8.x2.trans.shared.b16 {%0,%1}, [%2];"
                        : "=r"(bl0), "=r"(bl1) : "r"(wbl + n*16));
                    asm volatile("mma.sync.aligned.m16n8k16.row.col.f32.bf16.bf16.f32 "
                        "{%0,%1,%2,%3}, {%4,%5,%6,%7}, {%8,%9}, {%0,%1,%2,%3};"
                        : "+f"(c[n][0]), "+f"(c[n][1]), "+f"(c[n][2]), "+f"(c[n][3])
                        : "r"(ah0), "r"(ah1), "r"(ah2), "r"(ah3), "r"(bh0), "r"(bh1));
                    asm volatile("mma.sync.aligned.m16n8k16.row.col.f32.bf16.bf16.f32 "
                        "{%0,%1,%2,%3}, {%4,%5,%6,%7}, {%8,%9}, {%0,%1,%2,%3};"
                        : "+f"(c[n][0]), "+f"(c[n][1]), "+f"(c[n][2]), "+f"(c[n][3])
                        : "r"(ah0), "r"(ah1), "r"(ah2), "r"(ah3), "r"(bl0), "r"(bl1));
                    asm volatile("mma.sync.aligned.m16n8k16.row.col.f32.bf16.bf16.f32 "
                        "{%0,%1,%2,%3}, {%4,%5,%6,%7}, {%8,%9}, {%0,%1,%2,%3};"
                        : "+f"(c[n][0]), "+f"(c[n][1]), "+f"(c[n][2]), "+f"(c[n][3])
                        : "r"(al0), "r"(al1), "r"(al2), "r"(al3), "r"(bh0), "r"(bh1));
                }
            }
        }

        int r0 = base + m0 + g, r1 = r0 + 8;
        #pragma unroll
        for (int n = 0; n < 8; n++) {
            int col = n*8 + tg*2;
            float cb0 = cb1[col], cb1v = cb1[col+1];
            float s0 = bn1g[col]*BN_SCALE_C,  t0 = bn1b[col];
            float s1 = bn1g[col+1]*BN_SCALE_C, t1 = bn1b[col+1];
            float y00 = (c[n][0]+cb0)*s0 + t0; y00 = y00 > 0.f ? y00 : 0.f;
            float y01 = (c[n][1]+cb1v)*s1 + t1; y01 = y01 > 0.f ? y01 : 0.f;
            float y10 = (c[n][2]+cb0)*s0 + t0; y10 = y10 > 0.f ? y10 : 0.f;
            float y11 = (c[n][3]+cb1v)*s1 + t1; y11 = y11 > 0.f ? y11 : 0.f;
            *(float2*)(g_c1 + (size_t)r0*64 + col) = make_float2(y00, y01);
            *(float2*)(g_c1 + (size_t)r1*64 + col) = make_float2(y10, y11);
        }
        __syncthreads();   // A reused next tile
    }
}

// ---------------- tensorized decoder conv2 (64->32, k=3) --------------------
__global__ void __launch_bounds__(128) k_conv2(
    const float* __restrict__ cw2, const float* __restrict__ cb2,
    const float* __restrict__ bn2g, const float* __restrict__ bn2b)
{
    extern __shared__ __nv_bfloat16 smc[];
    __nv_bfloat16* A  = smc;            // 6*4608
    __nv_bfloat16* Wk = smc + 27648;    // 6*4608 (only 32 cols used)
    int tid = threadIdx.x;

    for (int idx = tid; idx < 2048; idx += 128) {
        int i = idx >> 5, o = idx & 31;
        #pragma unroll
        for (int k = 0; k < 3; k++) {
            float w = cw2[o*192 + i*3 + k];
            __nv_bfloat16 h = __float2bfloat16(w);
            Wk[(k*2+0)*4608 + i*72 + o] = h;
            Wk[(k*2+1)*4608 + i*72 + o] = __float2bfloat16(w - __bfloat162float(h));
        }
    }
    __syncthreads();

    int warp = tid >> 5, lane = tid & 31;
    int g = lane >> 2, tg = lane & 3;
    int m0 = warp*16;
    int a_row = m0 + (lane & 15);
    int a_col = (lane & 16) ? 8 : 0;
    int b_row = (lane & 15);

    for (int tile = blockIdx.x; tile < NT/64; tile += CONV_GRID) {
        int base = tile*64;
        for (int idx = tid; idx < 1024; idx += 128) {
            int row = idx >> 4, c4 = (idx & 15)*4;
            int t = (base + row) % 10;
            #pragma unroll
            for (int s = 0; s < 3; s++) {
                int dt = s - 1;
                float4 x4 = make_float4(0.f,0.f,0.f,0.f);
                if ((unsigned)(t + dt) < 10u)
                    x4 = *(const float4*)(g_c1 + (size_t)(base + row + dt)*64 + c4);
                split4(x4, A + (s*2+0)*4608 + row*72 + c4,
                           A + (s*2+1)*4608 + row*72 + c4);
            }
        }
        __syncthreads();

        float c[4][4];
        #pragma unroll
        for (int n = 0; n < 4; n++)
            #pragma unroll
            for (int i = 0; i < 4; i++) c[n][i] = 0.f;

        #pragma unroll
        for (int s = 0; s < 3; s++) {
            uint32_t aH = (uint32_t)__cvta_generic_to_shared(
                A + (s*2+0)*4608 + a_row*72 + a_col);
            uint32_t aL = (uint32_t)__cvta_generic_to_shared(
                A + (s*2+1)*4608 + a_row*72 + a_col);
            #pragma unroll
            for (int ks = 0; ks < 4; ks++) {
                uint32_t ah0, ah1, ah2, ah3, al0, al1, al2, al3;
                asm volatile("ldmatrix.sync.aligned.m8n8.x4.shared.b16 {%0,%1,%2,%3}, [%4];"
                    : "=r"(ah0), "=r"(ah1), "=r"(ah2), "=r"(ah3) : "r"(aH + ks*32));
                asm volatile("ldmatrix.sync.aligned.m8n8.x4.shared.b16 {%0,%1,%2,%3}, [%4];"
                    : "=r"(al0), "=r"(al1), "=r"(al2), "=r"(al3) : "r"(aL + ks*32));
                uint32_t wbh = (uint32_t)__cvta_generic_to_shared(
                    Wk + (s*2+0)*4608 + (ks*16 + b_row)*72);
                uint32_t wbl = (uint32_t)__cvta_generic_to_shared(
                    Wk + (s*2+1)*4608 + (ks*16 + b_row)*72);
                #pragma unroll
                for (int n = 0; n < 4; n++) {
                    uint32_t bh0, bh1, bl0, bl1;
                    asm volatile("ldmatrix.sync.aligned.m8n8.x2.trans.shared.b16 {%0,%1}, [%2];"
                        : "=r"(bh0), "=r"(bh1) : "r"(wbh + n*16));
                    asm volatile("ldmatrix.sync.aligned.m8n8.x2.trans.shared.b16 {%0,%1}, [%2];"
                        : "=r"(bl0), "=r"(bl1) : "r"(wbl + n*16));
                    asm volatile("mma.sync.aligned.m16n8k16.row.col.f32.bf16.bf16.f32 "
                        "{%0,%1,%2,%3}, {%4,%5,%6,%7}, {%8,%9}, {%0,%1,%2,%3};"
                        : "+f"(c[n][0]), "+f"(c[n][1]), "+f"(c[n][2]), "+f"(c[n][3])
                        : "r"(ah0), "r"(ah1), "r"(ah2), "r"(ah3), "r"(bh0), "r"(bh1));
                    asm volatile("mma.sync.aligned.m16n8k16.row.col.f32.bf16.bf16.f32 "
                        "{%0,%1,%2,%3}, {%4,%5,%6,%7}, {%8,%9}, {%0,%1,%2,%3};"
                        : "+f"(c[n][0]), "+f"(c[n][1]), "+f"(c[n][2]), "+f"(c[n][3])
                        : "r"(ah0), "r"(ah1), "r"(ah2), "r"(ah3), "r"(bl0), "r"(bl1));
                    asm volatile("mma.sync.aligned.m16n8k16.row.col.f32.bf16.bf16.f32 "
                        "{%0,%1,%2,%3}, {%4,%5,%6,%7}, {%8,%9}, {%0,%1,%2,%3};"
                        : "+f"(c[n][0]), "+f"(c[n][1]), "+f"(c[n][2]), "+f"(c[n][3])
                        : "r"(al0), "r"(al1), "r"(al2), "r"(al3), "r"(bh0), "r"(bh1));
                }
            }
        }

        int r0 = base + m0 + g, r1 = r0 + 8;
        #pragma unroll
        for (int n = 0; n < 4; n++) {
            int col = n*8 + tg*2;
            float cb0 = cb2[col], cb1v = cb2[col+1];
            float s0 = bn2g[col]*BN_SCALE_C,  t0 = bn2b[col];
            float s1 = bn2g[col+1]*BN_SCALE_C, t1 = bn2b[col+1];
            float y00 = (c[n][0]+cb0)*s0 + t0; y00 = y00 > 0.f ? y00 : 0.f;
            float y01 = (c[n][1]+cb1v)*s1 + t1; y01 = y01 > 0.f ? y01 : 0.f;
            float y10 = (c[n][2]+cb0)*s0 + t0; y10 = y10 > 0.f ? y10 : 0.f;
            float y11 = (c[n][3]+cb1v)*s1 + t1; y11 = y11 > 0.f ? y11 : 0.f;
            *(float2*)(g_c2 + (size_t)r0*32 + col) = make_float2(y00, y01);
            *(float2*)(g_c2 + (size_t)r1*32 + col) = make_float2(y10, y11);
        }
        __syncthreads();
    }
}

// ---------------- decoder conv3 (32->1, k=3): warp per output row ----------
__global__ void __launch_bounds__(256) k_conv3(
    const float* __restrict__ cw3, const float* __restrict__ cb3,
    float* __restrict__ out)
{
    int gw = (blockIdx.x*blockDim.x + threadIdx.x) >> 5;
    int lane = threadIdx.x & 31;
    if (gw >= NT) return;
    int t = gw % 10;
    float cm = (t > 0) ? g_c2[(size_t)(gw-1)*32 + lane] : 0.f;
    float c0 = g_c2[(size_t)gw*32 + lane];
    float cp = (t < 9) ? g_c2[(size_t)(gw+1)*32 + lane] : 0.f;
    float acc = cw3[lane*3+0]*cm + cw3[lane*3+1]*c0 + cw3[lane*3+2]*cp;
    #pragma unroll
    for (int m = 16; m >= 1; m >>= 1)
        acc += __shfl_xor_sync(0xFFFFFFFFu, acc, m);
    if (lane == 0) out[gw] = acc + cb3[0];
}

// ---------------- launch ----------------------------------------------------
extern "C" void kernel_launch(void* const* d_in, const int* in_sizes, int n_in,
                              void* d_out, int out_size)
{
    const float* x    = (const float*)d_in[0];
    const int*   ei   = (const int*)  d_in[1];
    const float* ea   = (const float*)d_in[2];
    const float* W    = (const float*)d_in[3];
    const float* bp   = (const float*)d_in[4];
    const float* ap   = (const float*)d_in[5];
    const float* lng  = (const float*)d_in[6];
    const float* lnb  = (const float*)d_in[7];
    const float* cw1  = (const float*)d_in[8];
    const float* cb1  = (const float*)d_in[9];
    const float* bn1g = (const float*)d_in[10];
    const float* bn1b = (const float*)d_in[11];
    const float* cw2  = (const float*)d_in[12];
    const float* cb2  = (const float*)d_in[13];
    const float* bn2g = (const float*)d_in[14];
    const float* bn2b = (const float*)d_in[15];
    const float* cw3  = (const float*)d_in[16];
    const float* cb3  = (const float*)d_in[17];
    float* out = (float*)d_out;

    static int attr_set = 0;
    if (!attr_set) {
        cudaFuncSetAttribute(k_gemm4, cudaFuncAttributeMaxDynamicSharedMemorySize,
                             GEMM_SMEM_BYTES);
        cudaFuncSetAttribute(k_conv1, cudaFuncAttributeMaxDynamicSharedMemorySize,
                             CONV_SMEM_BYTES);
        cudaFuncSetAttribute(k_conv2, cudaFuncAttributeMaxDynamicSharedMemorySize,
                             CONV_SMEM_BYTES);
        attr_set = 1;
    }

    k_count<<<(2*EE + 255)/256, 256>>>(ei);
    k_scan<<<2, 1024>>>();
    k_scatter<<<(2*EE + 255)/256, 256>>>(ei);

    int gemm_grid = NT/64;
    for (int l = 0; l < 2; l++) {
        int useX = (l == 0) ? 1 : 0;
        k_gemm4<<<gemm_grid, 128, GEMM_SMEM_BYTES>>>(x, useX, W, bp, ap, l);
        k_agg3<<<NN, 128>>>(x, useX, ei, ea, lng + l*64, lnb + l*64);
    }

    k_conv1<<<CONV_GRID, 128, CONV_SMEM_BYTES>>>(cw1, cb1, bn1g, bn1b);
    k_conv2<<<CONV_GRID, 128, CONV_SMEM_BYTES>>>(cw2, cb2, bn2g, bn2b);
    k_conv3<<<NT/8, 256>>>(cw3, cb3, out);
}

// round 13
// speedup vs baseline: 3.1654x; 1.1058x over previous
#include <cuda_runtime.h>
#include <cuda_bf16.h>
#include <math.h>
#include <stdint.h>

#define NN 20000
#define TT 10
#define HH 64
#define EE 200000
#define NT (NN*TT)          // 200000 rows (NT % 64 == 0)
#define ROWF 640
#define BN_SCALE_C 0.99999500003749971893f

// ---------------- scratch ----------------
__device__ __align__(256) float g_h0[NT*HH];
__device__ __align__(256) float g_h1[NT*HH];
__device__ __align__(256) float g_s0[NT];
__device__ __align__(256) float g_s1[NT];
__device__ __align__(256) float g_X[NT*HH];
__device__ __align__(256) float g_M[NT*HH];       // type-0 message accumulator
__device__ __align__(256) float g_c1[NT*64];
__device__ __align__(256) float g_c2[NT*32];
__device__ __align__(256) int   g_deg[2][NN];     // zero-init; self-restoring
__device__ __align__(256) int   g_rowptr[2][NN+1];
__device__ __align__(256) int   g_eord[2][EE];

// ---------------- CSR build ----------------
__global__ void k_count(const int* __restrict__ ei) {
    int idx = blockIdx.x*blockDim.x + threadIdx.x;
    if (idx >= 2*EE) return;
    int ty = idx / EE, e = idx % EE;
    int dst = ei[ty*2*EE + EE + e];
    atomicAdd(&g_deg[ty][dst], 1);
}

__global__ void k_scan() {
    int ty = blockIdx.x;
    __shared__ int wsums[32];
    int tid = threadIdx.x;
    int lane = tid & 31, w = tid >> 5;
    int start = tid * 20;
    int vals[20];
    int local = 0;
    #pragma unroll
    for (int j = 0; j < 20; j++) {
        int i = start + j;
        vals[j] = (i < NN) ? g_deg[ty][i] : 0;
        local += vals[j];
    }
    int pre = local;
    #pragma unroll
    for (int o = 1; o < 32; o <<= 1) {
        int v = __shfl_up_sync(0xFFFFFFFFu, pre, o);
        if (lane >= o) pre += v;
    }
    if (lane == 31) wsums[w] = pre;
    __syncthreads();
    if (w == 0) {
        int v = wsums[lane];
        int p = v;
        #pragma unroll
        for (int o = 1; o < 32; o <<= 1) {
            int t2 = __shfl_up_sync(0xFFFFFFFFu, p, o);
            if (lane >= o) p += t2;
        }
        wsums[lane] = p - v;
    }
    __syncthreads();
    int offset = wsums[w] + pre - local;
    #pragma unroll
    for (int j = 0; j < 20; j++) {
        int i = start + j;
        if (i < NN) g_rowptr[ty][i] = offset;
        offset += vals[j];
    }
    if (tid == 1023) g_rowptr[ty][NN] = offset;
}

__global__ void k_scatter(const int* __restrict__ ei) {
    int idx = blockIdx.x*blockDim.x + threadIdx.x;
    if (idx >= 2*EE) return;
    int ty = idx / EE, e = idx % EE;
    int dst = ei[ty*2*EE + EE + e];
    int pos = g_rowptr[ty][dst] + (atomicSub(&g_deg[ty][dst], 1) - 1);
    g_eord[ty][pos] = e;
}

// ---------------- helpers ----------------
__device__ __forceinline__ void split4(float4 v, __nv_bfloat16* hi, __nv_bfloat16* lo) {
    __nv_bfloat16 h0 = __float2bfloat16(v.x), h1 = __float2bfloat16(v.y);
    __nv_bfloat16 h2 = __float2bfloat16(v.z), h3 = __float2bfloat16(v.w);
    *(__nv_bfloat162*)(hi)     = __nv_bfloat162(h0, h1);
    *(__nv_bfloat162*)(hi + 2) = __nv_bfloat162(h2, h3);
    *(__nv_bfloat162*)(lo)     = __nv_bfloat162(
        __float2bfloat16(v.x - __bfloat162float(h0)),
        __float2bfloat16(v.y - __bfloat162float(h1)));
    *(__nv_bfloat162*)(lo + 2) = __nv_bfloat162(
        __float2bfloat16(v.z - __bfloat162float(h2)),
        __float2bfloat16(v.w - __bfloat162float(h3)));
}

// ---------------- tensor-core GEMM (bf16x3), ONE edge type -----------------
#define GEMM5_SMEM_BYTES 36864
__global__ void __launch_bounds__(128) k_gemm5(
    const float* __restrict__ Xin, int useX,
    const float* __restrict__ W, const float* __restrict__ bp,
    const float* __restrict__ ap, int idx4, int t)
{
    extern __shared__ __nv_bfloat16 smb[];
    __nv_bfloat16* Xh = smb;                 // [64][72]
    __nv_bfloat16* Xl = smb + 4608;
    __nv_bfloat16* Wh = smb + 9216;
    __nv_bfloat16* Wl = smb + 13824;

    const float* X = useX ? Xin : (const float*)g_X;
    int tid = threadIdx.x;
    int base = blockIdx.x * 64;

    {
        const float4* Xg = (const float4*)(X + (size_t)base*64);
        #pragma unroll
        for (int v = 0; v < 8; v++) {
            int idx = tid + v*128;
            float4 x4 = Xg[idx];
            int row = idx >> 4, c = (idx & 15)*4;
            split4(x4, Xh + row*72 + c, Xl + row*72 + c);
        }
    }
    {
        const float4* Wg = (const float4*)(W + (size_t)idx4*4096);
        // FULL 64x64 tile = 1024 float4 (R12 bug: only covered half)
        #pragma unroll
        for (int v = 0; v < 8; v++) {
            int idx = tid + v*128;
            float4 w4 = Wg[idx];
            int row = idx >> 4, c = (idx & 15)*4;
            split4(w4, Wh + row*72 + c, Wl + row*72 + c);
        }
    }
    __syncthreads();

    int warp = tid >> 5, lane = tid & 31;
    int g = lane >> 2, tg = lane & 3;
    int m0 = warp*16;
    int a_row = m0 + (lane & 15);
    int a_col = (lane & 16) ? 8 : 0;
    uint32_t addrXh = (uint32_t)__cvta_generic_to_shared(Xh + a_row*72 + a_col);
    uint32_t addrXl = (uint32_t)__cvta_generic_to_shared(Xl + a_row*72 + a_col);
    int b_row = (lane & 15);

    float c[8][4];
    #pragma unroll
    for (int n = 0; n < 8; n++)
        #pragma unroll
        for (int i = 0; i < 4; i++) c[n][i] = 0.f;

    #pragma unroll
    for (int ks = 0; ks < 4; ks++) {
        uint32_t ah0, ah1, ah2, ah3, al0, al1, al2, al3;
        asm volatile("ldmatrix.sync.aligned.m8n8.x4.shared.b16 {%0,%1,%2,%3}, [%4];"
            : "=r"(ah0), "=r"(ah1), "=r"(ah2), "=r"(ah3) : "r"(addrXh + ks*32));
        asm volatile("ldmatrix.sync.aligned.m8n8.x4.shared.b16 {%0,%1,%2,%3}, [%4];"
            : "=r"(al0), "=r"(al1), "=r"(al2), "=r"(al3) : "r"(addrXl + ks*32));
        uint32_t wbh = (uint32_t)__cvta_generic_to_shared(Wh + (ks*16 + b_row)*72);
        uint32_t wbl = (uint32_t)__cvta_generic_to_shared(Wl + (ks*16 + b_row)*72);
        #pragma unroll
        for (int n = 0; n < 8; n++) {
            uint32_t bh0, bh1, bl0, bl1;
            asm volatile("ldmatrix.sync.aligned.m8n8.x2.trans.shared.b16 {%0,%1}, [%2];"
                : "=r"(bh0), "=r"(bh1) : "r"(wbh + n*16));
            asm volatile("ldmatrix.sync.aligned.m8n8.x2.trans.shared.b16 {%0,%1}, [%2];"
                : "=r"(bl0), "=r"(bl1) : "r"(wbl + n*16));
            asm volatile("mma.sync.aligned.m16n8k16.row.col.f32.bf16.bf16.f32 "
                "{%0,%1,%2,%3}, {%4,%5,%6,%7}, {%8,%9}, {%0,%1,%2,%3};"
                : "+f"(c[n][0]), "+f"(c[n][1]), "+f"(c[n][2]), "+f"(c[n][3])
                : "r"(ah0), "r"(ah1), "r"(ah2), "r"(ah3), "r"(bh0), "r"(bh1));
            asm volatile("mma.sync.aligned.m16n8k16.row.col.f32.bf16.bf16.f32 "
                "{%0,%1,%2,%3}, {%4,%5,%6,%7}, {%8,%9}, {%0,%1,%2,%3};"
                : "+f"(c[n][0]), "+f"(c[n][1]), "+f"(c[n][2]), "+f"(c[n][3])
                : "r"(ah0), "r"(ah1), "r"(ah2), "r"(ah3), "r"(bl0), "r"(bl1));
            asm volatile("mma.sync.aligned.m16n8k16.row.col.f32.bf16.bf16.f32 "
                "{%0,%1,%2,%3}, {%4,%5,%6,%7}, {%8,%9}, {%0,%1,%2,%3};"
                : "+f"(c[n][0]), "+f"(c[n][1]), "+f"(c[n][2]), "+f"(c[n][3])
                : "r"(al0), "r"(al1), "r"(al2), "r"(al3), "r"(bh0), "r"(bh1));
        }
    }

    const float* bP = bp + idx4*64;
    const float* aP = ap + idx4*64;
    float* hout = t ? (float*)g_h1 : (float*)g_h0;
    float* sout = t ? (float*)g_s1 : (float*)g_s0;
    int r0 = base + m0 + g, r1 = r0 + 8;
    float sd0 = 0.f, sd1 = 0.f;
    #pragma unroll
    for (int n = 0; n < 8; n++) {
        int col = n*8 + tg*2;
        float bb0 = bP[col], bb1 = bP[col+1];
        float h00 = c[n][0] + bb0, h01 = c[n][1] + bb1;
        float h10 = c[n][2] + bb0, h11 = c[n][3] + bb1;
        *(float2*)(hout + (size_t)r0*64 + col) = make_float2(h00, h01);
        *(float2*)(hout + (size_t)r1*64 + col) = make_float2(h10, h11);
        float a0 = aP[col], a1 = aP[col+1];
        sd0 += h00*a0 + h01*a1;
        sd1 += h10*a0 + h11*a1;
    }
    sd0 += __shfl_xor_sync(0xFFFFFFFFu, sd0, 1);
    sd0 += __shfl_xor_sync(0xFFFFFFFFu, sd0, 2);
    sd1 += __shfl_xor_sync(0xFFFFFFFFu, sd1, 1);
    sd1 += __shfl_xor_sync(0xFFFFFFFFu, sd1, 2);
    if (tg == 0) { sout[r0] = sd0; sout[r1] = sd1; }
}

// ---------------- per-type attention gather -----------------
// phase 0 (ty=0): write message to g_M.
// phase 1 (ty=1): val = X + 0.5*(g_M + msg); LayerNorm; write g_X.
__global__ void __launch_bounds__(128) k_agg4(
    const float* __restrict__ xin, int useX,
    const int* __restrict__ ei, const float* __restrict__ ea,
    const float* __restrict__ lng, const float* __restrict__ lnb,
    int ty, int phase)
{
    int n = blockIdx.x;
    int tid = threadIdx.x;

    __shared__ float red_m[8][16], red_d[8][16];
    __shared__ float smax[10], sden[10];
    __shared__ float wsh[16][10];
    __shared__ int   ssrc[16];
    __shared__ float wsum[4][5], wsq[4][5];

    int ts = tid & 15, es = tid >> 4;
    float acc[5] = {0.f, 0.f, 0.f, 0.f, 0.f};

    const float* sA   = ty ? (const float*)g_s1 : (const float*)g_s0;
    const float* hA   = ty ? (const float*)g_h1 : (const float*)g_h0;
    const float* eaA  = ea + ty*EE;
    const int*   srcA = ei + ty*2*EE;
    const int*   eord = g_eord[ty];
    int r0 = g_rowptr[ty][n], r1 = g_rowptr[ty][n+1];

    float m = -1e30f, d = 0.f;
    if (ts < 10) {
        for (int j = r0 + es; j < r1; j += 8) {
            int src = srcA[eord[j]];
            float v = sA[src*TT + ts];
            float sc = v > 0.f ? v : 0.2f*v;
            if (sc > m) { d = d*__expf(m - sc) + 1.f; m = sc; }
            else        { d += __expf(sc - m); }
        }
    }
    red_m[es][ts] = m;
    red_d[es][ts] = d;
    __syncthreads();
    if (tid < 10) {
        float M = red_m[0][tid];
        #pragma unroll
        for (int i = 1; i < 8; i++) M = fmaxf(M, red_m[i][tid]);
        float D = 0.f;
        #pragma unroll
        for (int i = 0; i < 8; i++) D += red_d[i][tid]*__expf(red_m[i][tid] - M);
        smax[tid] = M;
        sden[tid] = D;
    }
    __syncthreads();

    for (int j0 = r0; j0 < r1; j0 += 16) {
        int cnt = min(16, r1 - j0);
        for (int p = tid; p < cnt*10; p += 128) {
            int ce = p / 10, ct = p % 10;
            int e = eord[j0 + ce];
            int src = srcA[e];
            if (ct == 0) ssrc[ce] = src;
            float v = sA[src*TT + ct];
            float sc = v > 0.f ? v : 0.2f*v;
            wsh[ce][ct] = __expf(sc - smax[ct]) / (sden[ct] + 1e-16f) * eaA[e];
        }
        __syncthreads();
        for (int c = 0; c < cnt; c++) {
            const float* hrow = hA + (size_t)ssrc[c]*ROWF;
            #pragma unroll
            for (int i = 0; i < 5; i++) {
                int pos = tid + i*128;
                acc[i] += wsh[c][pos >> 6] * hrow[pos];
            }
        }
        __syncthreads();
    }

    size_t nb = (size_t)n*ROWF;
    if (phase == 0) {
        #pragma unroll
        for (int i = 0; i < 5; i++) g_M[nb + tid + i*128] = acc[i];
        return;
    }

    // phase 1: residual + LayerNorm
    const float* Xsrc = useX ? xin : (const float*)g_X;
    float val[5];
    #pragma unroll
    for (int i = 0; i < 5; i++)
        val[i] = Xsrc[nb + tid + i*128] + 0.5f*(g_M[nb + tid + i*128] + acc[i]);

    int warp = tid >> 5, lane = tid & 31;
    #pragma unroll
    for (int i = 0; i < 5; i++) {
        float a = val[i], b = val[i]*val[i];
        #pragma unroll
        for (int mm = 16; mm >= 1; mm >>= 1) {
            a += __shfl_xor_sync(0xFFFFFFFFu, a, mm);
            b += __shfl_xor_sync(0xFFFFFFFFu, b, mm);
        }
        if (lane == 0) { wsum[warp][i] = a; wsq[warp][i] = b; }
    }
    __syncthreads();
    float gw = lng[tid & 63], bw = lnb[tid & 63];
    #pragma unroll
    for (int i = 0; i < 5; i++) {
        float s = wsum[warp][i] + wsum[warp^1][i];
        float q = wsq[warp][i]  + wsq[warp^1][i];
        float mean = s * (1.f/64.f);
        float var  = q * (1.f/64.f) - mean*mean;
        float inv  = rsqrtf(var + 1e-5f);
        g_X[nb + tid + i*128] = (val[i] - mean)*inv*gw + bw;
    }
}

// ---------------- tensorized decoder conv1 (64->64, k=3) --------------------
#define CONV_SMEM_BYTES 110592
#define CONV_GRID 296
__global__ void __launch_bounds__(128) k_conv1(
    const float* __restrict__ cw1, const float* __restrict__ cb1,
    const float* __restrict__ bn1g, const float* __restrict__ bn1b)
{
    extern __shared__ __nv_bfloat16 smc[];
    __nv_bfloat16* A  = smc;            // [shift][hi/lo][64*72]
    __nv_bfloat16* Wk = smc + 27648;
    int tid = threadIdx.x;

    for (int idx = tid; idx < 4096; idx += 128) {
        int i = idx >> 6, o = idx & 63;
        #pragma unroll
        for (int k = 0; k < 3; k++) {
            float w = cw1[o*192 + i*3 + k];
            __nv_bfloat16 h = __float2bfloat16(w);
            Wk[(k*2+0)*4608 + i*72 + o] = h;
            Wk[(k*2+1)*4608 + i*72 + o] = __float2bfloat16(w - __bfloat162float(h));
        }
    }
    __syncthreads();

    int warp = tid >> 5, lane = tid & 31;
    int g = lane >> 2, tg = lane & 3;
    int m0 = warp*16;
    int a_row = m0 + (lane & 15);
    int a_col = (lane & 16) ? 8 : 0;
    int b_row = (lane & 15);

    for (int tile = blockIdx.x; tile < NT/64; tile += CONV_GRID) {
        int base = tile*64;
        for (int idx = tid; idx < 1024; idx += 128) {
            int row = idx >> 4, c4 = (idx & 15)*4;
            int t = (base + row) % 10;
            #pragma unroll
            for (int s = 0; s < 3; s++) {
                int dt = s - 1;
                float4 x4 = make_float4(0.f,0.f,0.f,0.f);
                if ((unsigned)(t + dt) < 10u)
                    x4 = *(const float4*)(g_X + (size_t)(base + row + dt)*64 + c4);
                split4(x4, A + (s*2+0)*4608 + row*72 + c4,
                           A + (s*2+1)*4608 + row*72 + c4);
            }
        }
        __syncthreads();

        float c[8][4];
        #pragma unroll
        for (int n = 0; n < 8; n++)
            #pragma unroll
            for (int i = 0; i < 4; i++) c[n][i] = 0.f;

        #pragma unroll
        for (int s = 0; s < 3; s++) {
            uint32_t aH = (uint32_t)__cvta_generic_to_shared(
                A + (s*2+0)*4608 + a_row*72 + a_col);
            uint32_t aL = (uint32_t)__cvta_generic_to_shared(
                A + (s*2+1)*4608 + a_row*72 + a_col);
            #pragma unroll
            for (int ks = 0; ks < 4; ks++) {
                uint32_t ah0, ah1, ah2, ah3, al0, al1, al2, al3;
                asm volatile("ldmatrix.sync.aligned.m8n8.x4.shared.b16 {%0,%1,%2,%3}, [%4];"
                    : "=r"(ah0), "=r"(ah1), "=r"(ah2), "=r"(ah3) : "r"(aH + ks*32));
                asm volatile("ldmatrix.sync.aligned.m8n8.x4.shared.b16 {%0,%1,%2,%3}, [%4];"
                    : "=r"(al0), "=r"(al1), "=r"(al2), "=r"(al3) : "r"(aL + ks*32));
                uint32_t wbh = (uint32_t)__cvta_generic_to_shared(
                    Wk + (s*2+0)*4608 + (ks*16 + b_row)*72);
                uint32_t wbl = (uint32_t)__cvta_generic_to_shared(
                    Wk + (s*2+1)*4608 + (ks*16 + b_row)*72);
                #pragma unroll
                for (int n = 0; n < 8; n++) {
                    uint32_t bh0, bh1, bl0, bl1;
                    asm volatile("ldmatrix.sync.aligned.m8n8.x2.trans.shared.b16 {%0,%1}, [%2];"
                        : "=r"(bh0), "=r"(bh1) : "r"(wbh + n*16));
                    asm volatile("ldmatrix.sync.aligned.m8n8.x2.trans.shared.b16 {%0,%1}, [%2];"
                        : "=r"(bl0), "=r"(bl1) : "r"(wbl + n*16));
                    asm volatile("mma.sync.aligned.m16n8k16.row.col.f32.bf16.bf16.f32 "
                        "{%0,%1,%2,%3}, {%4,%5,%6,%7}, {%8,%9}, {%0,%1,%2,%3};"
                        : "+f"(c[n][0]), "+f"(c[n][1]), "+f"(c[n][2]), "+f"(c[n][3])
                        : "r"(ah0), "r"(ah1), "r"(ah2), "r"(ah3), "r"(bh0), "r"(bh1));
                    asm volatile("mma.sync.aligned.m16n8k16.row.col.f32.bf16.bf16.f32 "
                        "{%0,%1,%2,%3}, {%4,%5,%6,%7}, {%8,%9}, {%0,%1,%2,%3};"
                        : "+f"(c[n][0]), "+f"(c[n][1]), "+f"(c[n][2]), "+f"(c[n][3])
                        : "r"(ah0), "r"(ah1), "r"(ah2), "r"(ah3), "r"(bl0), "r"(bl1));
                    asm volatile("mma.sync.aligned.m16n8k16.row.col.f32.bf16.bf16.f32 "
                        "{%0,%1,%2,%3}, {%4,%5,%6,%7}, {%8,%9}, {%0,%1,%2,%3};"
                        : "+f"(c[n][0]), "+f"(c[n][1]), "+f"(c[n][2]), "+f"(c[n][3])
                        : "r"(al0), "r"(al1), "r"(al2), "r"(al3), "r"(bh0), "r"(bh1));
                }
            }
        }

        int r0 = base + m0 + g, r1 = r0 + 8;
        #pragma unroll
        for (int n = 0; n < 8; n++) {
            int col = n*8 + tg*2;
            float cb0 = cb1[col], cb1v = cb1[col+1];
            float s0 = bn1g[col]*BN_SCALE_C,  t0 = bn1b[col];
            float s1 = bn1g[col+1]*BN_SCALE_C, t1 = bn1b[col+1];
            float y00 = (c[n][0]+cb0)*s0 + t0; y00 = y00 > 0.f ? y00 : 0.f;
            float y01 = (c[n][1]+cb1v)*s1 + t1; y01 = y01 > 0.f ? y01 : 0.f;
            float y10 = (c[n][2]+cb0)*s0 + t0; y10 = y10 > 0.f ? y10 : 0.f;
            float y11 = (c[n][3]+cb1v)*s1 + t1; y11 = y11 > 0.f ? y11 : 0.f;
            *(float2*)(g_c1 + (size_t)r0*64 + col) = make_float2(y00, y01);
            *(float2*)(g_c1 + (size_t)r1*64 + col) = make_float2(y10, y11);
        }
        __syncthreads();
    }
}

// ---------------- tensorized decoder conv2 (64->32, k=3) --------------------
__global__ void __launch_bounds__(128) k_conv2(
    const float* __restrict__ cw2, const float* __restrict__ cb2,
    const float* __restrict__ bn2g, const float* __restrict__ bn2b)
{
    extern __shared__ __nv_bfloat16 smc[];
    __nv_bfloat16* A  = smc;
    __nv_bfloat16* Wk = smc + 27648;
    int tid = threadIdx.x;

    for (int idx = tid; idx < 2048; idx += 128) {
        int i = idx >> 5, o = idx & 31;
        #pragma unroll
        for (int k = 0; k < 3; k++) {
            float w = cw2[o*192 + i*3 + k];
            __nv_bfloat16 h = __float2bfloat16(w);
            Wk[(k*2+0)*4608 + i*72 + o] = h;
            Wk[(k*2+1)*4608 + i*72 + o] = __float2bfloat16(w - __bfloat162float(h));
        }
    }
    __syncthreads();

    int warp = tid >> 5, lane = tid & 31;
    int g = lane >> 2, tg = lane & 3;
    int m0 = warp*16;
    int a_row = m0 + (lane & 15);
    int a_col = (lane & 16) ? 8 : 0;
    int b_row = (lane & 15);

    for (int tile = blockIdx.x; tile < NT/64; tile += CONV_GRID) {
        int base = tile*64;
        for (int idx = tid; idx < 1024; idx += 128) {
            int row = idx >> 4, c4 = (idx & 15)*4;
            int t = (base + row) % 10;
            #pragma unroll
            for (int s = 0; s < 3; s++) {
                int dt = s - 1;
                float4 x4 = make_float4(0.f,0.f,0.f,0.f);
                if ((unsigned)(t + dt) < 10u)
                    x4 = *(const float4*)(g_c1 + (size_t)(base + row + dt)*64 + c4);
                split4(x4, A + (s*2+0)*4608 + row*72 + c4,
                           A + (s*2+1)*4608 + row*72 + c4);
            }
        }
        __syncthreads();

        float c[4][4];
        #pragma unroll
        for (int n = 0; n < 4; n++)
            #pragma unroll
            for (int i = 0; i < 4; i++) c[n][i] = 0.f;

        #pragma unroll
        for (int s = 0; s < 3; s++) {
            uint32_t aH = (uint32_t)__cvta_generic_to_shared(
                A + (s*2+0)*4608 + a_row*72 + a_col);
            uint32_t aL = (uint32_t)__cvta_generic_to_shared(
                A + (s*2+1)*4608 + a_row*72 + a_col);
            #pragma unroll
            for (int ks = 0; ks < 4; ks++) {
                uint32_t ah0, ah1, ah2, ah3, al0, al1, al2, al3;
                asm volatile("ldmatrix.sync.aligned.m8n8.x4.shared.b16 {%0,%1,%2,%3}, [%4];"
                    : "=r"(ah0), "=r"(ah1), "=r"(ah2), "=r"(ah3) : "r"(aH + ks*32));
                asm volatile("ldmatrix.sync.aligned.m8n8.x4.shared.b16 {%0,%1,%2,%3}, [%4];"
                    : "=r"(al0), "=r"(al1), "=r"(al2), "=r"(al3) : "r"(aL + ks*32));
                uint32_t wbh = (uint32_t)__cvta_generic_to_shared(
                    Wk + (s*2+0)*4608 + (ks*16 + b_row)*72);
                uint32_t wbl = (uint32_t)__cvta_generic_to_shared(
                    Wk + (s*2+1)*4608 + (ks*16 + b_row)*72);
                #pragma unroll
                for (int n = 0; n < 4; n++) {
                    uint32_t bh0, bh1, bl0, bl1;
                    asm volatile("ldmatrix.sync.aligned.m8n8.x2.trans.shared.b16 {%0,%1}, [%2];"
                        : "=r"(bh0), "=r"(bh1) : "r"(wbh + n*16));
                    asm volatile("ldmatrix.sync.aligned.m8n8.x2.trans.shared.b16 {%0,%1}, [%2];"
                        : "=r"(bl0), "=r"(bl1) : "r"(wbl + n*16));
                    asm volatile("mma.sync.aligned.m16n8k16.row.col.f32.bf16.bf16.f32 "
                        "{%0,%1,%2,%3}, {%4,%5,%6,%7}, {%8,%9}, {%0,%1,%2,%3};"
                        : "+f"(c[n][0]), "+f"(c[n][1]), "+f"(c[n][2]), "+f"(c[n][3])
                        : "r"(ah0), "r"(ah1), "r"(ah2), "r"(ah3), "r"(bh0), "r"(bh1));
                    asm volatile("mma.sync.aligned.m16n8k16.row.col.f32.bf16.bf16.f32 "
                        "{%0,%1,%2,%3}, {%4,%5,%6,%7}, {%8,%9}, {%0,%1,%2,%3};"
                        : "+f"(c[n][0]), "+f"(c[n][1]), "+f"(c[n][2]), "+f"(c[n][3])
                        : "r"(ah0), "r"(ah1), "r"(ah2), "r"(ah3), "r"(bl0), "r"(bl1));
                    asm volatile("mma.sync.aligned.m16n8k16.row.col.f32.bf16.bf16.f32 "
                        "{%0,%1,%2,%3}, {%4,%5,%6,%7}, {%8,%9}, {%0,%1,%2,%3};"
                        : "+f"(c[n][0]), "+f"(c[n][1]), "+f"(c[n][2]), "+f"(c[n][3])
                        : "r"(al0), "r"(al1), "r"(al2), "r"(al3), "r"(bh0), "r"(bh1));
                }
            }
        }

        int r0 = base + m0 + g, r1 = r0 + 8;
        #pragma unroll
        for (int n = 0; n < 4; n++) {
            int col = n*8 + tg*2;
            float cb0 = cb2[col], cb1v = cb2[col+1];
            float s0 = bn2g[col]*BN_SCALE_C,  t0 = bn2b[col];
            float s1 = bn2g[col+1]*BN_SCALE_C, t1 = bn2b[col+1];
            float y00 = (c[n][0]+cb0)*s0 + t0; y00 = y00 > 0.f ? y00 : 0.f;
            float y01 = (c[n][1]+cb1v)*s1 + t1; y01 = y01 > 0.f ? y01 : 0.f;
            float y10 = (c[n][2]+cb0)*s0 + t0; y10 = y10 > 0.f ? y10 : 0.f;
            float y11 = (c[n][3]+cb1v)*s1 + t1; y11 = y11 > 0.f ? y11 : 0.f;
            *(float2*)(g_c2 + (size_t)r0*32 + col) = make_float2(y00, y01);
            *(float2*)(g_c2 + (size_t)r1*32 + col) = make_float2(y10, y11);
        }
        __syncthreads();
    }
}

// ---------------- decoder conv3 (32->1, k=3): warp per output row ----------
__global__ void __launch_bounds__(256) k_conv3(
    const float* __restrict__ cw3, const float* __restrict__ cb3,
    float* __restrict__ out)
{
    int gw = (blockIdx.x*blockDim.x + threadIdx.x) >> 5;
    int lane = threadIdx.x & 31;
    if (gw >= NT) return;
    int t = gw % 10;
    float cm = (t > 0) ? g_c2[(size_t)(gw-1)*32 + lane] : 0.f;
    float c0 = g_c2[(size_t)gw*32 + lane];
    float cp = (t < 9) ? g_c2[(size_t)(gw+1)*32 + lane] : 0.f;
    float acc = cw3[lane*3+0]*cm + cw3[lane*3+1]*c0 + cw3[lane*3+2]*cp;
    #pragma unroll
    for (int m = 16; m >= 1; m >>= 1)
        acc += __shfl_xor_sync(0xFFFFFFFFu, acc, m);
    if (lane == 0) out[gw] = acc + cb3[0];
}

// ---------------- launch ----------------------------------------------------
extern "C" void kernel_launch(void* const* d_in, const int* in_sizes, int n_in,
                              void* d_out, int out_size)
{
    const float* x    = (const float*)d_in[0];
    const int*   ei   = (const int*)  d_in[1];
    const float* ea   = (const float*)d_in[2];
    const float* W    = (const float*)d_in[3];
    const float* bp   = (const float*)d_in[4];
    const float* ap   = (const float*)d_in[5];
    const float* lng  = (const float*)d_in[6];
    const float* lnb  = (const float*)d_in[7];
    const float* cw1  = (const float*)d_in[8];
    const float* cb1  = (const float*)d_in[9];
    const float* bn1g = (const float*)d_in[10];
    const float* bn1b = (const float*)d_in[11];
    const float* cw2  = (const float*)d_in[12];
    const float* cb2  = (const float*)d_in[13];
    const float* bn2g = (const float*)d_in[14];
    const float* bn2b = (const float*)d_in[15];
    const float* cw3  = (const float*)d_in[16];
    const float* cb3  = (const float*)d_in[17];
    float* out = (float*)d_out;

    static int attr_set = 0;
    if (!attr_set) {
        cudaFuncSetAttribute(k_gemm5, cudaFuncAttributeMaxDynamicSharedMemorySize,
                             GEMM5_SMEM_BYTES);
        cudaFuncSetAttribute(k_conv1, cudaFuncAttributeMaxDynamicSharedMemorySize,
                             CONV_SMEM_BYTES);
        cudaFuncSetAttribute(k_conv2, cudaFuncAttributeMaxDynamicSharedMemorySize,
                             CONV_SMEM_BYTES);
        attr_set = 1;
    }

    k_count<<<(2*EE + 255)/256, 256>>>(ei);
    k_scan<<<2, 1024>>>();
    k_scatter<<<(2*EE + 255)/256, 256>>>(ei);

    int gemm_grid = NT/64;
    // layer 0: gemm,gemm,agg,agg (6th launch overall = agg4 ty0 -> ncu lands on it)
    k_gemm5<<<gemm_grid, 128, GEMM5_SMEM_BYTES>>>(x, 1, W, bp, ap, 0, 0);
    k_gemm5<<<gemm_grid, 128, GEMM5_SMEM_BYTES>>>(x, 1, W, bp, ap, 1, 1);
    k_agg4<<<NN, 128>>>(x, 1, ei, ea, lng, lnb, 0, 0);
    k_agg4<<<NN, 128>>>(x, 1, ei, ea, lng, lnb, 1, 1);
    // layer 1: interleave for L2 residency of each h buffer
    k_gemm5<<<gemm_grid, 128, GEMM5_SMEM_BYTES>>>(x, 0, W, bp, ap, 2, 0);
    k_agg4<<<NN, 128>>>(x, 0, ei, ea, lng + 64, lnb + 64, 0, 0);
    k_gemm5<<<gemm_grid, 128, GEMM5_SMEM_BYTES>>>(x, 0, W, bp, ap, 3, 1);
    k_agg4<<<NN, 128>>>(x, 0, ei, ea, lng + 64, lnb + 64, 1, 1);

    k_conv1<<<CONV_GRID, 128, CONV_SMEM_BYTES>>>(cw1, cb1, bn1g, bn1b);
    k_conv2<<<CONV_GRID, 128, CONV_SMEM_BYTES>>>(cw2, cb2, bn2g, bn2b);
    k_conv3<<<NT/8, 256>>>(cw3, cb3, out);
}

// round 14
// speedup vs baseline: 3.3899x; 1.0709x over previous
#include <cuda_runtime.h>
#include <cuda_bf16.h>
#include <math.h>
#include <stdint.h>

#define NN 20000
#define TT 10
#define HH 64
#define EE 200000
#define NT (NN*TT)          // 200000 rows (NT % 64 == 0)
#define ROWF 640
#define BN_SCALE_C 0.99999500003749971893f

// ---------------- scratch ----------------
__device__ __align__(256) float g_h0[NT*HH];
__device__ __align__(256) float g_h1[NT*HH];
__device__ __align__(256) float g_s0[NT];
__device__ __align__(256) float g_s1[NT];
__device__ __align__(256) float g_X[NT*HH];
__device__ __align__(256) float g_M[NT*HH];       // type-0 message accumulator
__device__ __align__(256) float g_c1[NT*64];
__device__ __align__(256) float g_c2[NT*32];
__device__ __align__(256) int   g_deg[2][NN];     // zero-init; self-restoring
__device__ __align__(256) int   g_rowptr[2][NN+1];
__device__ __align__(256) int   g_eord[2][EE];

// ---------------- CSR build ----------------
__global__ void k_count(const int* __restrict__ ei) {
    int idx = blockIdx.x*blockDim.x + threadIdx.x;
    if (idx >= 2*EE) return;
    int ty = idx / EE, e = idx % EE;
    int dst = ei[ty*2*EE + EE + e];
    atomicAdd(&g_deg[ty][dst], 1);
}

__global__ void k_scan() {
    int ty = blockIdx.x;
    __shared__ int wsums[32];
    int tid = threadIdx.x;
    int lane = tid & 31, w = tid >> 5;
    int start = tid * 20;
    int vals[20];
    int local = 0;
    #pragma unroll
    for (int j = 0; j < 20; j++) {
        int i = start + j;
        vals[j] = (i < NN) ? g_deg[ty][i] : 0;
        local += vals[j];
    }
    int pre = local;
    #pragma unroll
    for (int o = 1; o < 32; o <<= 1) {
        int v = __shfl_up_sync(0xFFFFFFFFu, pre, o);
        if (lane >= o) pre += v;
    }
    if (lane == 31) wsums[w] = pre;
    __syncthreads();
    if (w == 0) {
        int v = wsums[lane];
        int p = v;
        #pragma unroll
        for (int o = 1; o < 32; o <<= 1) {
            int t2 = __shfl_up_sync(0xFFFFFFFFu, p, o);
            if (lane >= o) p += t2;
        }
        wsums[lane] = p - v;
    }
    __syncthreads();
    int offset = wsums[w] + pre - local;
    #pragma unroll
    for (int j = 0; j < 20; j++) {
        int i = start + j;
        if (i < NN) g_rowptr[ty][i] = offset;
        offset += vals[j];
    }
    if (tid == 1023) g_rowptr[ty][NN] = offset;
}

__global__ void k_scatter(const int* __restrict__ ei) {
    int idx = blockIdx.x*blockDim.x + threadIdx.x;
    if (idx >= 2*EE) return;
    int ty = idx / EE, e = idx % EE;
    int dst = ei[ty*2*EE + EE + e];
    int pos = g_rowptr[ty][dst] + (atomicSub(&g_deg[ty][dst], 1) - 1);
    g_eord[ty][pos] = e;
}

// ---------------- helpers ----------------
__device__ __forceinline__ void split4(float4 v, __nv_bfloat16* hi, __nv_bfloat16* lo) {
    __nv_bfloat16 h0 = __float2bfloat16(v.x), h1 = __float2bfloat16(v.y);
    __nv_bfloat16 h2 = __float2bfloat16(v.z), h3 = __float2bfloat16(v.w);
    *(__nv_bfloat162*)(hi)     = __nv_bfloat162(h0, h1);
    *(__nv_bfloat162*)(hi + 2) = __nv_bfloat162(h2, h3);
    *(__nv_bfloat162*)(lo)     = __nv_bfloat162(
        __float2bfloat16(v.x - __bfloat162float(h0)),
        __float2bfloat16(v.y - __bfloat162float(h1)));
    *(__nv_bfloat162*)(lo + 2) = __nv_bfloat162(
        __float2bfloat16(v.z - __bfloat162float(h2)),
        __float2bfloat16(v.w - __bfloat162float(h3)));
}

// ---------------- tensor-core GEMM (bf16x3), ONE edge type -----------------
#define GEMM5_SMEM_BYTES 36864
__global__ void __launch_bounds__(128) k_gemm5(
    const float* __restrict__ Xin, int useX,
    const float* __restrict__ W, const float* __restrict__ bp,
    const float* __restrict__ ap, int idx4, int t)
{
    extern __shared__ __nv_bfloat16 smb[];
    __nv_bfloat16* Xh = smb;                 // [64][72]
    __nv_bfloat16* Xl = smb + 4608;
    __nv_bfloat16* Wh = smb + 9216;
    __nv_bfloat16* Wl = smb + 13824;

    const float* X = useX ? Xin : (const float*)g_X;
    int tid = threadIdx.x;
    int base = blockIdx.x * 64;

    {
        const float4* Xg = (const float4*)(X + (size_t)base*64);
        #pragma unroll
        for (int v = 0; v < 8; v++) {
            int idx = tid + v*128;
            float4 x4 = Xg[idx];
            int row = idx >> 4, c = (idx & 15)*4;
            split4(x4, Xh + row*72 + c, Xl + row*72 + c);
        }
    }
    {
        const float4* Wg = (const float4*)(W + (size_t)idx4*4096);
        #pragma unroll
        for (int v = 0; v < 8; v++) {
            int idx = tid + v*128;
            float4 w4 = Wg[idx];
            int row = idx >> 4, c = (idx & 15)*4;
            split4(w4, Wh + row*72 + c, Wl + row*72 + c);
        }
    }
    __syncthreads();

    int warp = tid >> 5, lane = tid & 31;
    int g = lane >> 2, tg = lane & 3;
    int m0 = warp*16;
    int a_row = m0 + (lane & 15);
    int a_col = (lane & 16) ? 8 : 0;
    uint32_t addrXh = (uint32_t)__cvta_generic_to_shared(Xh + a_row*72 + a_col);
    uint32_t addrXl = (uint32_t)__cvta_generic_to_shared(Xl + a_row*72 + a_col);
    int b_row = (lane & 15);

    float c[8][4];
    #pragma unroll
    for (int n = 0; n < 8; n++)
        #pragma unroll
        for (int i = 0; i < 4; i++) c[n][i] = 0.f;

    #pragma unroll
    for (int ks = 0; ks < 4; ks++) {
        uint32_t ah0, ah1, ah2, ah3, al0, al1, al2, al3;
        asm volatile("ldmatrix.sync.aligned.m8n8.x4.shared.b16 {%0,%1,%2,%3}, [%4];"
            : "=r"(ah0), "=r"(ah1), "=r"(ah2), "=r"(ah3) : "r"(addrXh + ks*32));
        asm volatile("ldmatrix.sync.aligned.m8n8.x4.shared.b16 {%0,%1,%2,%3}, [%4];"
            : "=r"(al0), "=r"(al1), "=r"(al2), "=r"(al3) : "r"(addrXl + ks*32));
        uint32_t wbh = (uint32_t)__cvta_generic_to_shared(Wh + (ks*16 + b_row)*72);
        uint32_t wbl = (uint32_t)__cvta_generic_to_shared(Wl + (ks*16 + b_row)*72);
        #pragma unroll
        for (int n = 0; n < 8; n++) {
            uint32_t bh0, bh1, bl0, bl1;
            asm volatile("ldmatrix.sync.aligned.m8n8.x2.trans.shared.b16 {%0,%1}, [%2];"
                : "=r"(bh0), "=r"(bh1) : "r"(wbh + n*16));
            asm volatile("ldmatrix.sync.aligned.m8n8.x2.trans.shared.b16 {%0,%1}, [%2];"
                : "=r"(bl0), "=r"(bl1) : "r"(wbl + n*16));
            asm volatile("mma.sync.aligned.m16n8k16.row.col.f32.bf16.bf16.f32 "
                "{%0,%1,%2,%3}, {%4,%5,%6,%7}, {%8,%9}, {%0,%1,%2,%3};"
                : "+f"(c[n][0]), "+f"(c[n][1]), "+f"(c[n][2]), "+f"(c[n][3])
                : "r"(ah0), "r"(ah1), "r"(ah2), "r"(ah3), "r"(bh0), "r"(bh1));
            asm volatile("mma.sync.aligned.m16n8k16.row.col.f32.bf16.bf16.f32 "
                "{%0,%1,%2,%3}, {%4,%5,%6,%7}, {%8,%9}, {%0,%1,%2,%3};"
                : "+f"(c[n][0]), "+f"(c[n][1]), "+f"(c[n][2]), "+f"(c[n][3])
                : "r"(ah0), "r"(ah1), "r"(ah2), "r"(ah3), "r"(bl0), "r"(bl1));
            asm volatile("mma.sync.aligned.m16n8k16.row.col.f32.bf16.bf16.f32 "
                "{%0,%1,%2,%3}, {%4,%5,%6,%7}, {%8,%9}, {%0,%1,%2,%3};"
                : "+f"(c[n][0]), "+f"(c[n][1]), "+f"(c[n][2]), "+f"(c[n][3])
                : "r"(al0), "r"(al1), "r"(al2), "r"(al3), "r"(bh0), "r"(bh1));
        }
    }

    const float* bP = bp + idx4*64;
    const float* aP = ap + idx4*64;
    float* hout = t ? (float*)g_h1 : (float*)g_h0;
    float* sout = t ? (float*)g_s1 : (float*)g_s0;
    int r0 = base + m0 + g, r1 = r0 + 8;
    float sd0 = 0.f, sd1 = 0.f;
    #pragma unroll
    for (int n = 0; n < 8; n++) {
        int col = n*8 + tg*2;
        float bb0 = bP[col], bb1 = bP[col+1];
        float h00 = c[n][0] + bb0, h01 = c[n][1] + bb1;
        float h10 = c[n][2] + bb0, h11 = c[n][3] + bb1;
        *(float2*)(hout + (size_t)r0*64 + col) = make_float2(h00, h01);
        *(float2*)(hout + (size_t)r1*64 + col) = make_float2(h10, h11);
        float a0 = aP[col], a1 = aP[col+1];
        sd0 += h00*a0 + h01*a1;
        sd1 += h10*a0 + h11*a1;
    }
    sd0 += __shfl_xor_sync(0xFFFFFFFFu, sd0, 1);
    sd0 += __shfl_xor_sync(0xFFFFFFFFu, sd0, 2);
    sd1 += __shfl_xor_sync(0xFFFFFFFFu, sd1, 1);
    sd1 += __shfl_xor_sync(0xFFFFFFFFu, sd1, 2);
    if (tg == 0) { sout[r0] = sd0; sout[r1] = sd1; }
}

// ---------------- per-type attention gather (float4 paths) -----------------
// phase 0 (ty=0): write message to g_M.
// phase 1 (ty=1): val = X + 0.5*(g_M + msg); LayerNorm; write g_X.
// Gather/M/X all float4; per-t LN stats via 16-lane shuffle groups.
__global__ void __launch_bounds__(128) k_agg4(
    const float* __restrict__ xin, int useX,
    const int* __restrict__ ei, const float* __restrict__ ea,
    const float* __restrict__ lng, const float* __restrict__ lnb,
    int ty, int phase)
{
    int n = blockIdx.x;
    int tid = threadIdx.x;

    __shared__ float red_m[8][16], red_d[8][16];
    __shared__ float smax[10], srcp[10];
    __shared__ float wsh[16][10];
    __shared__ int   ssrc[16];
    __shared__ float ssum[10], ssq[10];

    int ts = tid & 15, es = tid >> 4;

    const float* sA   = ty ? (const float*)g_s1 : (const float*)g_s0;
    const float* hA   = ty ? (const float*)g_h1 : (const float*)g_h0;
    const float* eaA  = ea + ty*EE;
    const int*   srcA = ei + ty*2*EE;
    const int*   eord = g_eord[ty];
    int r0 = g_rowptr[ty][n], r1 = g_rowptr[ty][n+1];

    // online max + denominator in one pass
    float m = -1e30f, d = 0.f;
    if (ts < 10) {
        for (int j = r0 + es; j < r1; j += 8) {
            int src = srcA[eord[j]];
            float v = sA[src*TT + ts];
            float sc = v > 0.f ? v : 0.2f*v;
            if (sc > m) { d = d*__expf(m - sc) + 1.f; m = sc; }
            else        { d += __expf(sc - m); }
        }
    }
    red_m[es][ts] = m;
    red_d[es][ts] = d;
    __syncthreads();
    if (tid < 10) {
        float M = red_m[0][tid];
        #pragma unroll
        for (int i = 1; i < 8; i++) M = fmaxf(M, red_m[i][tid]);
        float D = 0.f;
        #pragma unroll
        for (int i = 0; i < 8; i++) D += red_d[i][tid]*__expf(red_m[i][tid] - M);
        smax[tid] = M;
        srcp[tid] = 1.f/(D + 1e-16f);
    }
    __syncthreads();

    // chunked weighted aggregation, float4 registers
    float4 a0 = make_float4(0.f,0.f,0.f,0.f);
    float4 a1 = make_float4(0.f,0.f,0.f,0.f);
    int t0 = tid >> 4;            // t of a0 block (pos = tid*4)
    for (int j0 = r0; j0 < r1; j0 += 16) {
        int cnt = min(16, r1 - j0);
        for (int p = tid; p < cnt*10; p += 128) {
            int ce = p / 10, ct = p % 10;
            int e = eord[j0 + ce];
            int src = srcA[e];
            if (ct == 0) ssrc[ce] = src;
            float v = sA[src*TT + ct];
            float sc = v > 0.f ? v : 0.2f*v;
            wsh[ce][ct] = __expf(sc - smax[ct]) * srcp[ct] * eaA[e];
        }
        __syncthreads();
        for (int c = 0; c < cnt; c++) {
            const float4* hr = (const float4*)(hA + (size_t)ssrc[c]*ROWF);
            float w0 = wsh[c][t0];
            float4 v = hr[tid];
            a0.x += w0*v.x; a0.y += w0*v.y; a0.z += w0*v.z; a0.w += w0*v.w;
            if (tid < 32) {
                float w1 = wsh[c][8 + t0];
                float4 v1 = hr[128 + tid];
                a1.x += w1*v1.x; a1.y += w1*v1.y; a1.z += w1*v1.z; a1.w += w1*v1.w;
            }
        }
        __syncthreads();
    }

    size_t nb = (size_t)n*ROWF;
    if (phase == 0) {
        float4* Mr4 = (float4*)(g_M + nb);
        Mr4[tid] = a0;
        if (tid < 32) Mr4[128 + tid] = a1;
        return;
    }

    // phase 1: residual + LayerNorm (float4)
    const float* Xsrc = useX ? xin : (const float*)g_X;
    const float4* Xr4 = (const float4*)(Xsrc + nb);
    const float4* Mr4 = (const float4*)(g_M + nb);
    float4 xv = Xr4[tid], mv = Mr4[tid];
    float4 v0;
    v0.x = xv.x + 0.5f*(mv.x + a0.x);
    v0.y = xv.y + 0.5f*(mv.y + a0.y);
    v0.z = xv.z + 0.5f*(mv.z + a0.z);
    v0.w = xv.w + 0.5f*(mv.w + a0.w);
    float4 v1 = make_float4(0.f,0.f,0.f,0.f);
    if (tid < 32) {
        float4 xv1 = Xr4[128 + tid], mv1 = Mr4[128 + tid];
        v1.x = xv1.x + 0.5f*(mv1.x + a1.x);
        v1.y = xv1.y + 0.5f*(mv1.y + a1.y);
        v1.z = xv1.z + 0.5f*(mv1.z + a1.z);
        v1.w = xv1.w + 0.5f*(mv1.w + a1.w);
    }

    // per-t stats: 16-lane shuffle groups (xor 1,2,4,8 stays in group)
    float s = v0.x + v0.y + v0.z + v0.w;
    float q = v0.x*v0.x + v0.y*v0.y + v0.z*v0.z + v0.w*v0.w;
    #pragma unroll
    for (int o = 8; o >= 1; o >>= 1) {
        s += __shfl_xor_sync(0xFFFFFFFFu, s, o);
        q += __shfl_xor_sync(0xFFFFFFFFu, q, o);
    }
    if ((tid & 15) == 0) { ssum[t0] = s; ssq[t0] = q; }
    {
        float s1 = v1.x + v1.y + v1.z + v1.w;
        float q1 = v1.x*v1.x + v1.y*v1.y + v1.z*v1.z + v1.w*v1.w;
        #pragma unroll
        for (int o = 8; o >= 1; o >>= 1) {
            s1 += __shfl_xor_sync(0xFFFFFFFFu, s1, o);
            q1 += __shfl_xor_sync(0xFFFFFFFFu, q1, o);
        }
        if (tid < 32 && (tid & 15) == 0) { ssum[8 + t0] = s1; ssq[8 + t0] = q1; }
    }
    __syncthreads();

    float4 gw = ((const float4*)lng)[tid & 15];
    float4 bw = ((const float4*)lnb)[tid & 15];
    float4* Xo4 = (float4*)(g_X + nb);
    {
        float mean = ssum[t0]*(1.f/64.f);
        float var  = ssq[t0]*(1.f/64.f) - mean*mean;
        float inv  = rsqrtf(var + 1e-5f);
        float4 o;
        o.x = (v0.x - mean)*inv*gw.x + bw.x;
        o.y = (v0.y - mean)*inv*gw.y + bw.y;
        o.z = (v0.z - mean)*inv*gw.z + bw.z;
        o.w = (v0.w - mean)*inv*gw.w + bw.w;
        Xo4[tid] = o;
    }
    if (tid < 32) {
        int t1 = 8 + t0;
        float mean = ssum[t1]*(1.f/64.f);
        float var  = ssq[t1]*(1.f/64.f) - mean*mean;
        float inv  = rsqrtf(var + 1e-5f);
        float4 o;
        o.x = (v1.x - mean)*inv*gw.x + bw.x;
        o.y = (v1.y - mean)*inv*gw.y + bw.y;
        o.z = (v1.z - mean)*inv*gw.z + bw.z;
        o.w = (v1.w - mean)*inv*gw.w + bw.w;
        Xo4[128 + tid] = o;
    }
}

// ---------------- tensorized decoder conv1 (64->64, k=3) --------------------
#define CONV_SMEM_BYTES 110592
#define CONV_GRID 296
__global__ void __launch_bounds__(128) k_conv1(
    const float* __restrict__ cw1, const float* __restrict__ cb1,
    const float* __restrict__ bn1g, const float* __restrict__ bn1b)
{
    extern __shared__ __nv_bfloat16 smc[];
    __nv_bfloat16* A  = smc;            // [shift][hi/lo][64*72]
    __nv_bfloat16* Wk = smc + 27648;
    int tid = threadIdx.x;

    for (int idx = tid; idx < 4096; idx += 128) {
        int i = idx >> 6, o = idx & 63;
        #pragma unroll
        for (int k = 0; k < 3; k++) {
            float w = cw1[o*192 + i*3 + k];
            __nv_bfloat16 h = __float2bfloat16(w);
            Wk[(k*2+0)*4608 + i*72 + o] = h;
            Wk[(k*2+1)*4608 + i*72 + o] = __float2bfloat16(w - __bfloat162float(h));
        }
    }
    __syncthreads();

    int warp = tid >> 5, lane = tid & 31;
    int g = lane >> 2, tg = lane & 3;
    int m0 = warp*16;
    int a_row = m0 + (lane & 15);
    int a_col = (lane & 16) ? 8 : 0;
    int b_row = (lane & 15);

    for (int tile = blockIdx.x; tile < NT/64; tile += CONV_GRID) {
        int base = tile*64;
        for (int idx = tid; idx < 1024; idx += 128) {
            int row = idx >> 4, c4 = (idx & 15)*4;
            int t = (base + row) % 10;
            #pragma unroll
            for (int s = 0; s < 3; s++) {
                int dt = s - 1;
                float4 x4 = make_float4(0.f,0.f,0.f,0.f);
                if ((unsigned)(t + dt) < 10u)
                    x4 = *(const float4*)(g_X + (size_t)(base + row + dt)*64 + c4);
                split4(x4, A + (s*2+0)*4608 + row*72 + c4,
                           A + (s*2+1)*4608 + row*72 + c4);
            }
        }
        __syncthreads();

        float c[8][4];
        #pragma unroll
        for (int n = 0; n < 8; n++)
            #pragma unroll
            for (int i = 0; i < 4; i++) c[n][i] = 0.f;

        #pragma unroll
        for (int s = 0; s < 3; s++) {
            uint32_t aH = (uint32_t)__cvta_generic_to_shared(
                A + (s*2+0)*4608 + a_row*72 + a_col);
            uint32_t aL = (uint32_t)__cvta_generic_to_shared(
                A + (s*2+1)*4608 + a_row*72 + a_col);
            #pragma unroll
            for (int ks = 0; ks < 4; ks++) {
                uint32_t ah0, ah1, ah2, ah3, al0, al1, al2, al3;
                asm volatile("ldmatrix.sync.aligned.m8n8.x4.shared.b16 {%0,%1,%2,%3}, [%4];"
                    : "=r"(ah0), "=r"(ah1), "=r"(ah2), "=r"(ah3) : "r"(aH + ks*32));
                asm volatile("ldmatrix.sync.aligned.m8n8.x4.shared.b16 {%0,%1,%2,%3}, [%4];"
                    : "=r"(al0), "=r"(al1), "=r"(al2), "=r"(al3) : "r"(aL + ks*32));
                uint32_t wbh = (uint32_t)__cvta_generic_to_shared(
                    Wk + (s*2+0)*4608 + (ks*16 + b_row)*72);
                uint32_t wbl = (uint32_t)__cvta_generic_to_shared(
                    Wk + (s*2+1)*4608 + (ks*16 + b_row)*72);
                #pragma unroll
                for (int n = 0; n < 8; n++) {
                    uint32_t bh0, bh1, bl0, bl1;
                    asm volatile("ldmatrix.sync.aligned.m8n8.x2.trans.shared.b16 {%0,%1}, [%2];"
                        : "=r"(bh0), "=r"(bh1) : "r"(wbh + n*16));
                    asm volatile("ldmatrix.sync.aligned.m8n8.x2.trans.shared.b16 {%0,%1}, [%2];"
                        : "=r"(bl0), "=r"(bl1) : "r"(wbl + n*16));
                    asm volatile("mma.sync.aligned.m16n8k16.row.col.f32.bf16.bf16.f32 "
                        "{%0,%1,%2,%3}, {%4,%5,%6,%7}, {%8,%9}, {%0,%1,%2,%3};"
                        : "+f"(c[n][0]), "+f"(c[n][1]), "+f"(c[n][2]), "+f"(c[n][3])
                        : "r"(ah0), "r"(ah1), "r"(ah2), "r"(ah3), "r"(bh0), "r"(bh1));
                    asm volatile("mma.sync.aligned.m16n8k16.row.col.f32.bf16.bf16.f32 "
                        "{%0,%1,%2,%3}, {%4,%5,%6,%7}, {%8,%9}, {%0,%1,%2,%3};"
                        : "+f"(c[n][0]), "+f"(c[n][1]), "+f"(c[n][2]), "+f"(c[n][3])
                        : "r"(ah0), "r"(ah1), "r"(ah2), "r"(ah3), "r"(bl0), "r"(bl1));
                    asm volatile("mma.sync.aligned.m16n8k16.row.col.f32.bf16.bf16.f32 "
                        "{%0,%1,%2,%3}, {%4,%5,%6,%7}, {%8,%9}, {%0,%1,%2,%3};"
                        : "+f"(c[n][0]), "+f"(c[n][1]), "+f"(c[n][2]), "+f"(c[n][3])
                        : "r"(al0), "r"(al1), "r"(al2), "r"(al3), "r"(bh0), "r"(bh1));
                }
            }
        }

        int r0 = base + m0 + g, r1 = r0 + 8;
        #pragma unroll
        for (int n = 0; n < 8; n++) {
            int col = n*8 + tg*2;
            float cb0 = cb1[col], cb1v = cb1[col+1];
            float s0 = bn1g[col]*BN_SCALE_C,  t0 = bn1b[col];
            float s1 = bn1g[col+1]*BN_SCALE_C, t1 = bn1b[col+1];
            float y00 = (c[n][0]+cb0)*s0 + t0; y00 = y00 > 0.f ? y00 : 0.f;
            float y01 = (c[n][1]+cb1v)*s1 + t1; y01 = y01 > 0.f ? y01 : 0.f;
            float y10 = (c[n][2]+cb0)*s0 + t0; y10 = y10 > 0.f ? y10 : 0.f;
            float y11 = (c[n][3]+cb1v)*s1 + t1; y11 = y11 > 0.f ? y11 : 0.f;
            *(float2*)(g_c1 + (size_t)r0*64 + col) = make_float2(y00, y01);
            *(float2*)(g_c1 + (size_t)r1*64 + col) = make_float2(y10, y11);
        }
        __syncthreads();
    }
}

// ---------------- tensorized decoder conv2 (64->32, k=3) --------------------
__global__ void __launch_bounds__(128) k_conv2(
    const float* __restrict__ cw2, const float* __restrict__ cb2,
    const float* __restrict__ bn2g, const float* __restrict__ bn2b)
{
    extern __shared__ __nv_bfloat16 smc[];
    __nv_bfloat16* A  = smc;
    __nv_bfloat16* Wk = smc + 27648;
    int tid = threadIdx.x;

    for (int idx = tid; idx < 2048; idx += 128) {
        int i = idx >> 5, o = idx & 31;
        #pragma unroll
        for (int k = 0; k < 3; k++) {
            float w = cw2[o*192 + i*3 + k];
            __nv_bfloat16 h = __float2bfloat16(w);
            Wk[(k*2+0)*4608 + i*72 + o] = h;
            Wk[(k*2+1)*4608 + i*72 + o] = __float2bfloat16(w - __bfloat162float(h));
        }
    }
    __syncthreads();

    int warp = tid >> 5, lane = tid & 31;
    int g = lane >> 2, tg = lane & 3;
    int m0 = warp*16;
    int a_row = m0 + (lane & 15);
    int a_col = (lane & 16) ? 8 : 0;
    int b_row = (lane & 15);

    for (int tile = blockIdx.x; tile < NT/64; tile += CONV_GRID) {
        int base = tile*64;
        for (int idx = tid; idx < 1024; idx += 128) {
            int row = idx >> 4, c4 = (idx & 15)*4;
            int t = (base + row) % 10;
            #pragma unroll
            for (int s = 0; s < 3; s++) {
                int dt = s - 1;
                float4 x4 = make_float4(0.f,0.f,0.f,0.f);
                if ((unsigned)(t + dt) < 10u)
                    x4 = *(const float4*)(g_c1 + (size_t)(base + row + dt)*64 + c4);
                split4(x4, A + (s*2+0)*4608 + row*72 + c4,
                           A + (s*2+1)*4608 + row*72 + c4);
            }
        }
        __syncthreads();

        float c[4][4];
        #pragma unroll
        for (int n = 0; n < 4; n++)
            #pragma unroll
            for (int i = 0; i < 4; i++) c[n][i] = 0.f;

        #pragma unroll
        for (int s = 0; s < 3; s++) {
            uint32_t aH = (uint32_t)__cvta_generic_to_shared(
                A + (s*2+0)*4608 + a_row*72 + a_col);
            uint32_t aL = (uint32_t)__cvta_generic_to_shared(
                A + (s*2+1)*4608 + a_row*72 + a_col);
            #pragma unroll
            for (int ks = 0; ks < 4; ks++) {
                uint32_t ah0, ah1, ah2, ah3, al0, al1, al2, al3;
                asm volatile("ldmatrix.sync.aligned.m8n8.x4.shared.b16 {%0,%1,%2,%3}, [%4];"
                    : "=r"(ah0), "=r"(ah1), "=r"(ah2), "=r"(ah3) : "r"(aH + ks*32));
                asm volatile("ldmatrix.sync.aligned.m8n8.x4.shared.b16 {%0,%1,%2,%3}, [%4];"
                    : "=r"(al0), "=r"(al1), "=r"(al2), "=r"(al3) : "r"(aL + ks*32));
                uint32_t wbh = (uint32_t)__cvta_generic_to_shared(
                    Wk + (s*2+0)*4608 + (ks*16 + b_row)*72);
                uint32_t wbl = (uint32_t)__cvta_generic_to_shared(
                    Wk + (s*2+1)*4608 + (ks*16 + b_row)*72);
                #pragma unroll
                for (int n = 0; n < 4; n++) {
                    uint32_t bh0, bh1, bl0, bl1;
                    asm volatile("ldmatrix.sync.aligned.m8n8.x2.trans.shared.b16 {%0,%1}, [%2];"
                        : "=r"(bh0), "=r"(bh1) : "r"(wbh + n*16));
                    asm volatile("ldmatrix.sync.aligned.m8n8.x2.trans.shared.b16 {%0,%1}, [%2];"
                        : "=r"(bl0), "=r"(bl1) : "r"(wbl + n*16));
                    asm volatile("mma.sync.aligned.m16n8k16.row.col.f32.bf16.bf16.f32 "
                        "{%0,%1,%2,%3}, {%4,%5,%6,%7}, {%8,%9}, {%0,%1,%2,%3};"
                        : "+f"(c[n][0]), "+f"(c[n][1]), "+f"(c[n][2]), "+f"(c[n][3])
                        : "r"(ah0), "r"(ah1), "r"(ah2), "r"(ah3), "r"(bh0), "r"(bh1));
                    asm volatile("mma.sync.aligned.m16n8k16.row.col.f32.bf16.bf16.f32 "
                        "{%0,%1,%2,%3}, {%4,%5,%6,%7}, {%8,%9}, {%0,%1,%2,%3};"
                        : "+f"(c[n][0]), "+f"(c[n][1]), "+f"(c[n][2]), "+f"(c[n][3])
                        : "r"(ah0), "r"(ah1), "r"(ah2), "r"(ah3), "r"(bl0), "r"(bl1));
                    asm volatile("mma.sync.aligned.m16n8k16.row.col.f32.bf16.bf16.f32 "
                        "{%0,%1,%2,%3}, {%4,%5,%6,%7}, {%8,%9}, {%0,%1,%2,%3};"
                        : "+f"(c[n][0]), "+f"(c[n][1]), "+f"(c[n][2]), "+f"(c[n][3])
                        : "r"(al0), "r"(al1), "r"(al2), "r"(al3), "r"(bh0), "r"(bh1));
                }
            }
        }

        int r0 = base + m0 + g, r1 = r0 + 8;
        #pragma unroll
        for (int n = 0; n < 4; n++) {
            int col = n*8 + tg*2;
            float cb0 = cb2[col], cb1v = cb2[col+1];
            float s0 = bn2g[col]*BN_SCALE_C,  t0 = bn2b[col];
            float s1 = bn2g[col+1]*BN_SCALE_C, t1 = bn2b[col+1];
            float y00 = (c[n][0]+cb0)*s0 + t0; y00 = y00 > 0.f ? y00 : 0.f;
            float y01 = (c[n][1]+cb1v)*s1 + t1; y01 = y01 > 0.f ? y01 : 0.f;
            float y10 = (c[n][2]+cb0)*s0 + t0; y10 = y10 > 0.f ? y10 : 0.f;
            float y11 = (c[n][3]+cb1v)*s1 + t1; y11 = y11 > 0.f ? y11 : 0.f;
            *(float2*)(g_c2 + (size_t)r0*32 + col) = make_float2(y00, y01);
            *(float2*)(g_c2 + (size_t)r1*32 + col) = make_float2(y10, y11);
        }
        __syncthreads();
    }
}

// ---------------- decoder conv3 (32->1, k=3): warp per output row ----------
__global__ void __launch_bounds__(256) k_conv3(
    const float* __restrict__ cw3, const float* __restrict__ cb3,
    float* __restrict__ out)
{
    int gw = (blockIdx.x*blockDim.x + threadIdx.x) >> 5;
    int lane = threadIdx.x & 31;
    if (gw >= NT) return;
    int t = gw % 10;
    float cm = (t > 0) ? g_c2[(size_t)(gw-1)*32 + lane] : 0.f;
    float c0 = g_c2[(size_t)gw*32 + lane];
    float cp = (t < 9) ? g_c2[(size_t)(gw+1)*32 + lane] : 0.f;
    float acc = cw3[lane*3+0]*cm + cw3[lane*3+1]*c0 + cw3[lane*3+2]*cp;
    #pragma unroll
    for (int m = 16; m >= 1; m >>= 1)
        acc += __shfl_xor_sync(0xFFFFFFFFu, acc, m);
    if (lane == 0) out[gw] = acc + cb3[0];
}

// ---------------- launch ----------------------------------------------------
extern "C" void kernel_launch(void* const* d_in, const int* in_sizes, int n_in,
                              void* d_out, int out_size)
{
    const float* x    = (const float*)d_in[0];
    const int*   ei   = (const int*)  d_in[1];
    const float* ea   = (const float*)d_in[2];
    const float* W    = (const float*)d_in[3];
    const float* bp   = (const float*)d_in[4];
    const float* ap   = (const float*)d_in[5];
    const float* lng  = (const float*)d_in[6];
    const float* lnb  = (const float*)d_in[7];
    const float* cw1  = (const float*)d_in[8];
    const float* cb1  = (const float*)d_in[9];
    const float* bn1g = (const float*)d_in[10];
    const float* bn1b = (const float*)d_in[11];
    const float* cw2  = (const float*)d_in[12];
    const float* cb2  = (const float*)d_in[13];
    const float* bn2g = (const float*)d_in[14];
    const float* bn2b = (const float*)d_in[15];
    const float* cw3  = (const float*)d_in[16];
    const float* cb3  = (const float*)d_in[17];
    float* out = (float*)d_out;

    static int attr_set = 0;
    if (!attr_set) {
        cudaFuncSetAttribute(k_gemm5, cudaFuncAttributeMaxDynamicSharedMemorySize,
                             GEMM5_SMEM_BYTES);
        cudaFuncSetAttribute(k_conv1, cudaFuncAttributeMaxDynamicSharedMemorySize,
                             CONV_SMEM_BYTES);
        cudaFuncSetAttribute(k_conv2, cudaFuncAttributeMaxDynamicSharedMemorySize,
                             CONV_SMEM_BYTES);
        attr_set = 1;
    }

    k_count<<<(2*EE + 255)/256, 256>>>(ei);
    k_scan<<<2, 1024>>>();
    k_scatter<<<(2*EE + 255)/256, 256>>>(ei);

    int gemm_grid = NT/64;
    // both layers interleaved gemm->agg per type for L2 residency of each h
    k_gemm5<<<gemm_grid, 128, GEMM5_SMEM_BYTES>>>(x, 1, W, bp, ap, 0, 0);
    k_agg4<<<NN, 128>>>(x, 1, ei, ea, lng, lnb, 0, 0);
    k_gemm5<<<gemm_grid, 128, GEMM5_SMEM_BYTES>>>(x, 1, W, bp, ap, 1, 1);
    k_agg4<<<NN, 128>>>(x, 1, ei, ea, lng, lnb, 1, 1);
    k_gemm5<<<gemm_grid, 128, GEMM5_SMEM_BYTES>>>(x, 0, W, bp, ap, 2, 0);
    k_agg4<<<NN, 128>>>(x, 0, ei, ea, lng + 64, lnb + 64, 0, 0);
    k_gemm5<<<gemm_grid, 128, GEMM5_SMEM_BYTES>>>(x, 0, W, bp, ap, 3, 1);
    k_agg4<<<NN, 128>>>(x, 0, ei, ea, lng + 64, lnb + 64, 1, 1);

    k_conv1<<<CONV_GRID, 128, CONV_SMEM_BYTES>>>(cw1, cb1, bn1g, bn1b);
    k_conv2<<<CONV_GRID, 128, CONV_SMEM_BYTES>>>(cw2, cb2, bn2g, bn2b);
    k_conv3<<<NT/8, 256>>>(cw3, cb3, out);
}

// round 15
// speedup vs baseline: 3.6128x; 1.0657x over previous
#include <cuda_runtime.h>
#include <cuda_bf16.h>
#include <math.h>
#include <stdint.h>

#define NN 20000
#define TT 10
#define HH 64
#define EE 200000
#define NT (NN*TT)          // 200000 rows (NT % 64 == 0)
#define ROWF 640
#define BN_SCALE_C 0.99999500003749971893f

// ---------------- scratch ----------------
__device__ __align__(256) __nv_bfloat16 g_h0[NT*HH];   // projected features (bf16)
__device__ __align__(256) __nv_bfloat16 g_h1[NT*HH];
__device__ __align__(256) float g_s0[NT];
__device__ __align__(256) float g_s1[NT];
__device__ __align__(256) float g_X[NT*HH];
__device__ __align__(256) float g_M[NT*HH];       // type-0 message accumulator
__device__ __align__(256) float g_c1[NT*64];
__device__ __align__(256) float g_c2[NT*32];
__device__ __align__(256) int   g_deg[2][NN];     // zero-init; self-restoring
__device__ __align__(256) int   g_rowptr[2][NN+1];
__device__ __align__(256) int   g_eord[2][EE];

// ---------------- CSR build ----------------
__global__ void k_count(const int* __restrict__ ei) {
    int idx = blockIdx.x*blockDim.x + threadIdx.x;
    if (idx >= 2*EE) return;
    int ty = idx / EE, e = idx % EE;
    int dst = ei[ty*2*EE + EE + e];
    atomicAdd(&g_deg[ty][dst], 1);
}

__global__ void k_scan() {
    int ty = blockIdx.x;
    __shared__ int wsums[32];
    int tid = threadIdx.x;
    int lane = tid & 31, w = tid >> 5;
    int start = tid * 20;
    int vals[20];
    int local = 0;
    #pragma unroll
    for (int j = 0; j < 20; j++) {
        int i = start + j;
        vals[j] = (i < NN) ? g_deg[ty][i] : 0;
        local += vals[j];
    }
    int pre = local;
    #pragma unroll
    for (int o = 1; o < 32; o <<= 1) {
        int v = __shfl_up_sync(0xFFFFFFFFu, pre, o);
        if (lane >= o) pre += v;
    }
    if (lane == 31) wsums[w] = pre;
    __syncthreads();
    if (w == 0) {
        int v = wsums[lane];
        int p = v;
        #pragma unroll
        for (int o = 1; o < 32; o <<= 1) {
            int t2 = __shfl_up_sync(0xFFFFFFFFu, p, o);
            if (lane >= o) p += t2;
        }
        wsums[lane] = p - v;
    }
    __syncthreads();
    int offset = wsums[w] + pre - local;
    #pragma unroll
    for (int j = 0; j < 20; j++) {
        int i = start + j;
        if (i < NN) g_rowptr[ty][i] = offset;
        offset += vals[j];
    }
    if (tid == 1023) g_rowptr[ty][NN] = offset;
}

__global__ void k_scatter(const int* __restrict__ ei) {
    int idx = blockIdx.x*blockDim.x + threadIdx.x;
    if (idx >= 2*EE) return;
    int ty = idx / EE, e = idx % EE;
    int dst = ei[ty*2*EE + EE + e];
    int pos = g_rowptr[ty][dst] + (atomicSub(&g_deg[ty][dst], 1) - 1);
    g_eord[ty][pos] = e;
}

// ---------------- helpers ----------------
__device__ __forceinline__ void split4(float4 v, __nv_bfloat16* hi, __nv_bfloat16* lo) {
    __nv_bfloat16 h0 = __float2bfloat16(v.x), h1 = __float2bfloat16(v.y);
    __nv_bfloat16 h2 = __float2bfloat16(v.z), h3 = __float2bfloat16(v.w);
    *(__nv_bfloat162*)(hi)     = __nv_bfloat162(h0, h1);
    *(__nv_bfloat162*)(hi + 2) = __nv_bfloat162(h2, h3);
    *(__nv_bfloat162*)(lo)     = __nv_bfloat162(
        __float2bfloat16(v.x - __bfloat162float(h0)),
        __float2bfloat16(v.y - __bfloat162float(h1)));
    *(__nv_bfloat162*)(lo + 2) = __nv_bfloat162(
        __float2bfloat16(v.z - __bfloat162float(h2)),
        __float2bfloat16(v.w - __bfloat162float(h3)));
}

// ---------------- tensor-core GEMM (bf16x3), ONE edge type -----------------
// h stored bf16 (gather consumer); s computed from fp32 accumulators.
#define GEMM5_SMEM_BYTES 36864
__global__ void __launch_bounds__(128) k_gemm5(
    const float* __restrict__ Xin, int useX,
    const float* __restrict__ W, const float* __restrict__ bp,
    const float* __restrict__ ap, int idx4, int t)
{
    extern __shared__ __nv_bfloat16 smb[];
    __nv_bfloat16* Xh = smb;                 // [64][72]
    __nv_bfloat16* Xl = smb + 4608;
    __nv_bfloat16* Wh = smb + 9216;
    __nv_bfloat16* Wl = smb + 13824;

    const float* X = useX ? Xin : (const float*)g_X;
    int tid = threadIdx.x;
    int base = blockIdx.x * 64;

    {
        const float4* Xg = (const float4*)(X + (size_t)base*64);
        #pragma unroll
        for (int v = 0; v < 8; v++) {
            int idx = tid + v*128;
            float4 x4 = Xg[idx];
            int row = idx >> 4, c = (idx & 15)*4;
            split4(x4, Xh + row*72 + c, Xl + row*72 + c);
        }
    }
    {
        const float4* Wg = (const float4*)(W + (size_t)idx4*4096);
        #pragma unroll
        for (int v = 0; v < 8; v++) {
            int idx = tid + v*128;
            float4 w4 = Wg[idx];
            int row = idx >> 4, c = (idx & 15)*4;
            split4(w4, Wh + row*72 + c, Wl + row*72 + c);
        }
    }
    __syncthreads();

    int warp = tid >> 5, lane = tid & 31;
    int g = lane >> 2, tg = lane & 3;
    int m0 = warp*16;
    int a_row = m0 + (lane & 15);
    int a_col = (lane & 16) ? 8 : 0;
    uint32_t addrXh = (uint32_t)__cvta_generic_to_shared(Xh + a_row*72 + a_col);
    uint32_t addrXl = (uint32_t)__cvta_generic_to_shared(Xl + a_row*72 + a_col);
    int b_row = (lane & 15);

    float c[8][4];
    #pragma unroll
    for (int n = 0; n < 8; n++)
        #pragma unroll
        for (int i = 0; i < 4; i++) c[n][i] = 0.f;

    #pragma unroll
    for (int ks = 0; ks < 4; ks++) {
        uint32_t ah0, ah1, ah2, ah3, al0, al1, al2, al3;
        asm volatile("ldmatrix.sync.aligned.m8n8.x4.shared.b16 {%0,%1,%2,%3}, [%4];"
            : "=r"(ah0), "=r"(ah1), "=r"(ah2), "=r"(ah3) : "r"(addrXh + ks*32));
        asm volatile("ldmatrix.sync.aligned.m8n8.x4.shared.b16 {%0,%1,%2,%3}, [%4];"
            : "=r"(al0), "=r"(al1), "=r"(al2), "=r"(al3) : "r"(addrXl + ks*32));
        uint32_t wbh = (uint32_t)__cvta_generic_to_shared(Wh + (ks*16 + b_row)*72);
        uint32_t wbl = (uint32_t)__cvta_generic_to_shared(Wl + (ks*16 + b_row)*72);
        #pragma unroll
        for (int n = 0; n < 8; n++) {
            uint32_t bh0, bh1, bl0, bl1;
            asm volatile("ldmatrix.sync.aligned.m8n8.x2.trans.shared.b16 {%0,%1}, [%2];"
                : "=r"(bh0), "=r"(bh1) : "r"(wbh + n*16));
            asm volatile("ldmatrix.sync.aligned.m8n8.x2.trans.shared.b16 {%0,%1}, [%2];"
                : "=r"(bl0), "=r"(bl1) : "r"(wbl + n*16));
            asm volatile("mma.sync.aligned.m16n8k16.row.col.f32.bf16.bf16.f32 "
                "{%0,%1,%2,%3}, {%4,%5,%6,%7}, {%8,%9}, {%0,%1,%2,%3};"
                : "+f"(c[n][0]), "+f"(c[n][1]), "+f"(c[n][2]), "+f"(c[n][3])
                : "r"(ah0), "r"(ah1), "r"(ah2), "r"(ah3), "r"(bh0), "r"(bh1));
            asm volatile("mma.sync.aligned.m16n8k16.row.col.f32.bf16.bf16.f32 "
                "{%0,%1,%2,%3}, {%4,%5,%6,%7}, {%8,%9}, {%0,%1,%2,%3};"
                : "+f"(c[n][0]), "+f"(c[n][1]), "+f"(c[n][2]), "+f"(c[n][3])
                : "r"(ah0), "r"(ah1), "r"(ah2), "r"(ah3), "r"(bl0), "r"(bl1));
            asm volatile("mma.sync.aligned.m16n8k16.row.col.f32.bf16.bf16.f32 "
                "{%0,%1,%2,%3}, {%4,%5,%6,%7}, {%8,%9}, {%0,%1,%2,%3};"
                : "+f"(c[n][0]), "+f"(c[n][1]), "+f"(c[n][2]), "+f"(c[n][3])
                : "r"(al0), "r"(al1), "r"(al2), "r"(al3), "r"(bh0), "r"(bh1));
        }
    }

    const float* bP = bp + idx4*64;
    const float* aP = ap + idx4*64;
    __nv_bfloat16* hout = t ? (__nv_bfloat16*)g_h1 : (__nv_bfloat16*)g_h0;
    float* sout = t ? (float*)g_s1 : (float*)g_s0;
    int r0 = base + m0 + g, r1 = r0 + 8;
    float sd0 = 0.f, sd1 = 0.f;
    #pragma unroll
    for (int n = 0; n < 8; n++) {
        int col = n*8 + tg*2;
        float bb0 = bP[col], bb1 = bP[col+1];
        float h00 = c[n][0] + bb0, h01 = c[n][1] + bb1;
        float h10 = c[n][2] + bb0, h11 = c[n][3] + bb1;
        *(__nv_bfloat162*)(hout + (size_t)r0*64 + col) =
            __nv_bfloat162(__float2bfloat16(h00), __float2bfloat16(h01));
        *(__nv_bfloat162*)(hout + (size_t)r1*64 + col) =
            __nv_bfloat162(__float2bfloat16(h10), __float2bfloat16(h11));
        float a0 = aP[col], a1 = aP[col+1];
        sd0 += h00*a0 + h01*a1;
        sd1 += h10*a0 + h11*a1;
    }
    sd0 += __shfl_xor_sync(0xFFFFFFFFu, sd0, 1);
    sd0 += __shfl_xor_sync(0xFFFFFFFFu, sd0, 2);
    sd1 += __shfl_xor_sync(0xFFFFFFFFu, sd1, 1);
    sd1 += __shfl_xor_sync(0xFFFFFFFFu, sd1, 2);
    if (tg == 0) { sout[r0] = sd0; sout[r1] = sd1; }
}

// ---------------- per-type attention gather (bf16 h) -----------------------
// 80 active threads: thread tid<80 owns h positions tid*8..tid*8+7 (one 16B
// load = 8 bf16 per edge row). LN stats via 8-lane in-warp shuffle groups.
__global__ void __launch_bounds__(128) k_agg4(
    const float* __restrict__ xin, int useX,
    const int* __restrict__ ei, const float* __restrict__ ea,
    const float* __restrict__ lng, const float* __restrict__ lnb,
    int ty, int phase)
{
    int n = blockIdx.x;
    int tid = threadIdx.x;

    __shared__ float red_m[8][16], red_d[8][16];
    __shared__ float smax[10], srcp[10];
    __shared__ float wsh[16][10];
    __shared__ int   ssrc[16];

    int ts = tid & 15, es = tid >> 4;

    const float* sA   = ty ? (const float*)g_s1 : (const float*)g_s0;
    const __nv_bfloat16* hA = ty ? (const __nv_bfloat16*)g_h1
                                 : (const __nv_bfloat16*)g_h0;
    const float* eaA  = ea + ty*EE;
    const int*   srcA = ei + ty*2*EE;
    const int*   eord = g_eord[ty];
    int r0 = g_rowptr[ty][n], r1 = g_rowptr[ty][n+1];

    // online max + denominator in one pass
    float m = -1e30f, d = 0.f;
    if (ts < 10) {
        for (int j = r0 + es; j < r1; j += 8) {
            int src = srcA[eord[j]];
            float v = sA[src*TT + ts];
            float sc = v > 0.f ? v : 0.2f*v;
            if (sc > m) { d = d*__expf(m - sc) + 1.f; m = sc; }
            else        { d += __expf(sc - m); }
        }
    }
    red_m[es][ts] = m;
    red_d[es][ts] = d;
    __syncthreads();
    if (tid < 10) {
        float M = red_m[0][tid];
        #pragma unroll
        for (int i = 1; i < 8; i++) M = fmaxf(M, red_m[i][tid]);
        float D = 0.f;
        #pragma unroll
        for (int i = 0; i < 8; i++) D += red_d[i][tid]*__expf(red_m[i][tid] - M);
        smax[tid] = M;
        srcp[tid] = 1.f/(D + 1e-16f);
    }
    __syncthreads();

    // chunked weighted aggregation: 8 fp32 accumulators, one ld.128 per edge
    float acc[8] = {0.f,0.f,0.f,0.f,0.f,0.f,0.f,0.f};
    int active = (tid < 80);
    int tW = tid >> 3;               // t index 0..9 for active threads
    for (int j0 = r0; j0 < r1; j0 += 16) {
        int cnt = min(16, r1 - j0);
        for (int p = tid; p < cnt*10; p += 128) {
            int ce = p / 10, ct = p % 10;
            int e = eord[j0 + ce];
            int src = srcA[e];
            if (ct == 0) ssrc[ce] = src;
            float v = sA[src*TT + ct];
            float sc = v > 0.f ? v : 0.2f*v;
            wsh[ce][ct] = __expf(sc - smax[ct]) * srcp[ct] * eaA[e];
        }
        __syncthreads();
        if (active) {
            for (int c = 0; c < cnt; c++) {
                const float4* hr = (const float4*)(hA + (size_t)ssrc[c]*ROWF);
                float4 pk = hr[tid];            // 8 bf16
                float w = wsh[c][tW];
                __nv_bfloat162 b0 = *(__nv_bfloat162*)&pk.x;
                __nv_bfloat162 b1 = *(__nv_bfloat162*)&pk.y;
                __nv_bfloat162 b2 = *(__nv_bfloat162*)&pk.z;
                __nv_bfloat162 b3 = *(__nv_bfloat162*)&pk.w;
                float2 f0 = __bfloat1622float2(b0);
                float2 f1 = __bfloat1622float2(b1);
                float2 f2 = __bfloat1622float2(b2);
                float2 f3 = __bfloat1622float2(b3);
                acc[0] += w*f0.x; acc[1] += w*f0.y;
                acc[2] += w*f1.x; acc[3] += w*f1.y;
                acc[4] += w*f2.x; acc[5] += w*f2.y;
                acc[6] += w*f3.x; acc[7] += w*f3.y;
            }
        }
        __syncthreads();
    }

    if (!active) return;
    size_t nb = (size_t)n*ROWF + tid*8;
    if (phase == 0) {
        float4* Mr4 = (float4*)(g_M + nb);
        Mr4[0] = make_float4(acc[0], acc[1], acc[2], acc[3]);
        Mr4[1] = make_float4(acc[4], acc[5], acc[6], acc[7]);
        return;
    }

    // phase 1: residual + LayerNorm
    const float* Xsrc = (useX ? xin : (const float*)g_X) + nb;
    const float* Mr = g_M + nb;
    float val[8];
    float s = 0.f, q = 0.f;
    #pragma unroll
    for (int i = 0; i < 8; i++) {
        val[i] = Xsrc[i] + 0.5f*(Mr[i] + acc[i]);
        s += val[i];
        q += val[i]*val[i];
    }
    // 8-lane group reduce (threads tid/8 share t; groups in-warp)
    #pragma unroll
    for (int o = 4; o >= 1; o >>= 1) {
        s += __shfl_xor_sync(0xFFFFFFFFu, s, o);
        q += __shfl_xor_sync(0xFFFFFFFFu, q, o);
    }
    float mean = s * (1.f/64.f);
    float var  = q * (1.f/64.f) - mean*mean;
    float inv  = rsqrtf(var + 1e-5f);

    int h0 = (tid & 7)*8;
    float4 gw0 = *(const float4*)(lng + h0), gw1 = *(const float4*)(lng + h0 + 4);
    float4 bw0 = *(const float4*)(lnb + h0), bw1 = *(const float4*)(lnb + h0 + 4);
    float4* Xo4 = (float4*)(g_X + nb);
    float4 o0, o1;
    o0.x = (val[0]-mean)*inv*gw0.x + bw0.x;
    o0.y = (val[1]-mean)*inv*gw0.y + bw0.y;
    o0.z = (val[2]-mean)*inv*gw0.z + bw0.z;
    o0.w = (val[3]-mean)*inv*gw0.w + bw0.w;
    o1.x = (val[4]-mean)*inv*gw1.x + bw1.x;
    o1.y = (val[5]-mean)*inv*gw1.y + bw1.y;
    o1.z = (val[6]-mean)*inv*gw1.z + bw1.z;
    o1.w = (val[7]-mean)*inv*gw1.w + bw1.w;
    Xo4[0] = o0;
    Xo4[1] = o1;
}

// ---------------- tensorized decoder conv1 (64->64, k=3) --------------------
#define CONV_SMEM_BYTES 110592
#define CONV_GRID 296
__global__ void __launch_bounds__(128) k_conv1(
    const float* __restrict__ cw1, const float* __restrict__ cb1,
    const float* __restrict__ bn1g, const float* __restrict__ bn1b)
{
    extern __shared__ __nv_bfloat16 smc[];
    __nv_bfloat16* A  = smc;            // [shift][hi/lo][64*72]
    __nv_bfloat16* Wk = smc + 27648;
    int tid = threadIdx.x;

    for (int idx = tid; idx < 4096; idx += 128) {
        int i = idx >> 6, o = idx & 63;
        #pragma unroll
        for (int k = 0; k < 3; k++) {
            float w = cw1[o*192 + i*3 + k];
            __nv_bfloat16 h = __float2bfloat16(w);
            Wk[(k*2+0)*4608 + i*72 + o] = h;
            Wk[(k*2+1)*4608 + i*72 + o] = __float2bfloat16(w - __bfloat162float(h));
        }
    }
    __syncthreads();

    int warp = tid >> 5, lane = tid & 31;
    int g = lane >> 2, tg = lane & 3;
    int m0 = warp*16;
    int a_row = m0 + (lane & 15);
    int a_col = (lane & 16) ? 8 : 0;
    int b_row = (lane & 15);

    for (int tile = blockIdx.x; tile < NT/64; tile += CONV_GRID) {
        int base = tile*64;
        for (int idx = tid; idx < 1024; idx += 128) {
            int row = idx >> 4, c4 = (idx & 15)*4;
            int t = (base + row) % 10;
            #pragma unroll
            for (int s = 0; s < 3; s++) {
                int dt = s - 1;
                float4 x4 = make_float4(0.f,0.f,0.f,0.f);
                if ((unsigned)(t + dt) < 10u)
                    x4 = *(const float4*)(g_X + (size_t)(base + row + dt)*64 + c4);
                split4(x4, A + (s*2+0)*4608 + row*72 + c4,
                           A + (s*2+1)*4608 + row*72 + c4);
            }
        }
        __syncthreads();

        float c[8][4];
        #pragma unroll
        for (int n = 0; n < 8; n++)
            #pragma unroll
            for (int i = 0; i < 4; i++) c[n][i] = 0.f;

        #pragma unroll
        for (int s = 0; s < 3; s++) {
            uint32_t aH = (uint32_t)__cvta_generic_to_shared(
                A + (s*2+0)*4608 + a_row*72 + a_col);
            uint32_t aL = (uint32_t)__cvta_generic_to_shared(
                A + (s*2+1)*4608 + a_row*72 + a_col);
            #pragma unroll
            for (int ks = 0; ks < 4; ks++) {
                uint32_t ah0, ah1, ah2, ah3, al0, al1, al2, al3;
                asm volatile("ldmatrix.sync.aligned.m8n8.x4.shared.b16 {%0,%1,%2,%3}, [%4];"
                    : "=r"(ah0), "=r"(ah1), "=r"(ah2), "=r"(ah3) : "r"(aH + ks*32));
                asm volatile("ldmatrix.sync.aligned.m8n8.x4.shared.b16 {%0,%1,%2,%3}, [%4];"
                    : "=r"(al0), "=r"(al1), "=r"(al2), "=r"(al3) : "r"(aL + ks*32));
                uint32_t wbh = (uint32_t)__cvta_generic_to_shared(
                    Wk + (s*2+0)*4608 + (ks*16 + b_row)*72);
                uint32_t wbl = (uint32_t)__cvta_generic_to_shared(
                    Wk + (s*2+1)*4608 + (ks*16 + b_row)*72);
                #pragma unroll
                for (int n = 0; n < 8; n++) {
                    uint32_t bh0, bh1, bl0, bl1;
                    asm volatile("ldmatrix.sync.aligned.m8n8.x2.trans.shared.b16 {%0,%1}, [%2];"
                        : "=r"(bh0), "=r"(bh1) : "r"(wbh + n*16));
                    asm volatile("ldmatrix.sync.aligned.m8n8.x2.trans.shared.b16 {%0,%1}, [%2];"
                        : "=r"(bl0), "=r"(bl1) : "r"(wbl + n*16));
                    asm volatile("mma.sync.aligned.m16n8k16.row.col.f32.bf16.bf16.f32 "
                        "{%0,%1,%2,%3}, {%4,%5,%6,%7}, {%8,%9}, {%0,%1,%2,%3};"
                        : "+f"(c[n][0]), "+f"(c[n][1]), "+f"(c[n][2]), "+f"(c[n][3])
                        : "r"(ah0), "r"(ah1), "r"(ah2), "r"(ah3), "r"(bh0), "r"(bh1));
                    asm volatile("mma.sync.aligned.m16n8k16.row.col.f32.bf16.bf16.f32 "
                        "{%0,%1,%2,%3}, {%4,%5,%6,%7}, {%8,%9}, {%0,%1,%2,%3};"
                        : "+f"(c[n][0]), "+f"(c[n][1]), "+f"(c[n][2]), "+f"(c[n][3])
                        : "r"(ah0), "r"(ah1), "r"(ah2), "r"(ah3), "r"(bl0), "r"(bl1));
                    asm volatile("mma.sync.aligned.m16n8k16.row.col.f32.bf16.bf16.f32 "
                        "{%0,%1,%2,%3}, {%4,%5,%6,%7}, {%8,%9}, {%0,%1,%2,%3};"
                        : "+f"(c[n][0]), "+f"(c[n][1]), "+f"(c[n][2]), "+f"(c[n][3])
                        : "r"(al0), "r"(al1), "r"(al2), "r"(al3), "r"(bh0), "r"(bh1));
                }
            }
        }

        int r0 = base + m0 + g, r1 = r0 + 8;
        #pragma unroll
        for (int n = 0; n < 8; n++) {
            int col = n*8 + tg*2;
            float cb0 = cb1[col], cb1v = cb1[col+1];
            float s0 = bn1g[col]*BN_SCALE_C,  t0 = bn1b[col];
            float s1 = bn1g[col+1]*BN_SCALE_C, t1 = bn1b[col+1];
            float y00 = (c[n][0]+cb0)*s0 + t0; y00 = y00 > 0.f ? y00 : 0.f;
            float y01 = (c[n][1]+cb1v)*s1 + t1; y01 = y01 > 0.f ? y01 : 0.f;
            float y10 = (c[n][2]+cb0)*s0 + t0; y10 = y10 > 0.f ? y10 : 0.f;
            float y11 = (c[n][3]+cb1v)*s1 + t1; y11 = y11 > 0.f ? y11 : 0.f;
            *(float2*)(g_c1 + (size_t)r0*64 + col) = make_float2(y00, y01);
            *(float2*)(g_c1 + (size_t)r1*64 + col) = make_float2(y10, y11);
        }
        __syncthreads();
    }
}

// ---------------- tensorized decoder conv2 (64->32, k=3) --------------------
__global__ void __launch_bounds__(128) k_conv2(
    const float* __restrict__ cw2, const float* __restrict__ cb2,
    const float* __restrict__ bn2g, const float* __restrict__ bn2b)
{
    extern __shared__ __nv_bfloat16 smc[];
    __nv_bfloat16* A  = smc;
    __nv_bfloat16* Wk = smc + 27648;
    int tid = threadIdx.x;

    for (int idx = tid; idx < 2048; idx += 128) {
        int i = idx >> 5, o = idx & 31;
        #pragma unroll
        for (int k = 0; k < 3; k++) {
            float w = cw2[o*192 + i*3 + k];
            __nv_bfloat16 h = __float2bfloat16(w);
            Wk[(k*2+0)*4608 + i*72 + o] = h;
            Wk[(k*2+1)*4608 + i*72 + o] = __float2bfloat16(w - __bfloat162float(h));
        }
    }
    __syncthreads();

    int warp = tid >> 5, lane = tid & 31;
    int g = lane >> 2, tg = lane & 3;
    int m0 = warp*16;
    int a_row = m0 + (lane & 15);
    int a_col = (lane & 16) ? 8 : 0;
    int b_row = (lane & 15);

    for (int tile = blockIdx.x; tile < NT/64; tile += CONV_GRID) {
        int base = tile*64;
        for (int idx = tid; idx < 1024; idx += 128) {
            int row = idx >> 4, c4 = (idx & 15)*4;
            int t = (base + row) % 10;
            #pragma unroll
            for (int s = 0; s < 3; s++) {
                int dt = s - 1;
                float4 x4 = make_float4(0.f,0.f,0.f,0.f);
                if ((unsigned)(t + dt) < 10u)
                    x4 = *(const float4*)(g_c1 + (size_t)(base + row + dt)*64 + c4);
                split4(x4, A + (s*2+0)*4608 + row*72 + c4,
                           A + (s*2+1)*4608 + row*72 + c4);
            }
        }
        __syncthreads();

        float c[4][4];
        #pragma unroll
        for (int n = 0; n < 4; n++)
            #pragma unroll
            for (int i = 0; i < 4; i++) c[n][i] = 0.f;

        #pragma unroll
        for (int s = 0; s < 3; s++) {
            uint32_t aH = (uint32_t)__cvta_generic_to_shared(
                A + (s*2+0)*4608 + a_row*72 + a_col);
            uint32_t aL = (uint32_t)__cvta_generic_to_shared(
                A + (s*2+1)*4608 + a_row*72 + a_col);
            #pragma unroll
            for (int ks = 0; ks < 4; ks++) {
                uint32_t ah0, ah1, ah2, ah3, al0, al1, al2, al3;
                asm volatile("ldmatrix.sync.aligned.m8n8.x4.shared.b16 {%0,%1,%2,%3}, [%4];"
                    : "=r"(ah0), "=r"(ah1), "=r"(ah2), "=r"(ah3) : "r"(aH + ks*32));
                asm volatile("ldmatrix.sync.aligned.m8n8.x4.shared.b16 {%0,%1,%2,%3}, [%4];"
                    : "=r"(al0), "=r"(al1), "=r"(al2), "=r"(al3) : "r"(aL + ks*32));
                uint32_t wbh = (uint32_t)__cvta_generic_to_shared(
                    Wk + (s*2+0)*4608 + (ks*16 + b_row)*72);
                uint32_t wbl = (uint32_t)__cvta_generic_to_shared(
                    Wk + (s*2+1)*4608 + (ks*16 + b_row)*72);
                #pragma unroll
                for (int n = 0; n < 4; n++) {
                    uint32_t bh0, bh1, bl0, bl1;
                    asm volatile("ldmatrix.sync.aligned.m8n8.x2.trans.shared.b16 {%0,%1}, [%2];"
                        : "=r"(bh0), "=r"(bh1) : "r"(wbh + n*16));
                    asm volatile("ldmatrix.sync.aligned.m8n8.x2.trans.shared.b16 {%0,%1}, [%2];"
                        : "=r"(bl0), "=r"(bl1) : "r"(wbl + n*16));
                    asm volatile("mma.sync.aligned.m16n8k16.row.col.f32.bf16.bf16.f32 "
                        "{%0,%1,%2,%3}, {%4,%5,%6,%7}, {%8,%9}, {%0,%1,%2,%3};"
                        : "+f"(c[n][0]), "+f"(c[n][1]), "+f"(c[n][2]), "+f"(c[n][3])
                        : "r"(ah0), "r"(ah1), "r"(ah2), "r"(ah3), "r"(bh0), "r"(bh1));
                    asm volatile("mma.sync.aligned.m16n8k16.row.col.f32.bf16.bf16.f32 "
                        "{%0,%1,%2,%3}, {%4,%5,%6,%7}, {%8,%9}, {%0,%1,%2,%3};"
                        : "+f"(c[n][0]), "+f"(c[n][1]), "+f"(c[n][2]), "+f"(c[n][3])
                        : "r"(ah0), "r"(ah1), "r"(ah2), "r"(ah3), "r"(bl0), "r"(bl1));
                    asm volatile("mma.sync.aligned.m16n8k16.row.col.f32.bf16.bf16.f32 "
                        "{%0,%1,%2,%3}, {%4,%5,%6,%7}, {%8,%9}, {%0,%1,%2,%3};"
                        : "+f"(c[n][0]), "+f"(c[n][1]), "+f"(c[n][2]), "+f"(c[n][3])
                        : "r"(al0), "r"(al1), "r"(al2), "r"(al3), "r"(bh0), "r"(bh1));
                }
            }
        }

        int r0 = base + m0 + g, r1 = r0 + 8;
        #pragma unroll
        for (int n = 0; n < 4; n++) {
            int col = n*8 + tg*2;
            float cb0 = cb2[col], cb1v = cb2[col+1];
            float s0 = bn2g[col]*BN_SCALE_C,  t0 = bn2b[col];
            float s1 = bn2g[col+1]*BN_SCALE_C, t1 = bn2b[col+1];
            float y00 = (c[n][0]+cb0)*s0 + t0; y00 = y00 > 0.f ? y00 : 0.f;
            float y01 = (c[n][1]+cb1v)*s1 + t1; y01 = y01 > 0.f ? y01 : 0.f;
            float y10 = (c[n][2]+cb0)*s0 + t0; y10 = y10 > 0.f ? y10 : 0.f;
            float y11 = (c[n][3]+cb1v)*s1 + t1; y11 = y11 > 0.f ? y11 : 0.f;
            *(float2*)(g_c2 + (size_t)r0*32 + col) = make_float2(y00, y01);
            *(float2*)(g_c2 + (size_t)r1*32 + col) = make_float2(y10, y11);
        }
        __syncthreads();
    }
}

// ---------------- decoder conv3 (32->1, k=3): warp per output row ----------
__global__ void __launch_bounds__(256) k_conv3(
    const float* __restrict__ cw3, const float* __restrict__ cb3,
    float* __restrict__ out)
{
    int gw = (blockIdx.x*blockDim.x + threadIdx.x) >> 5;
    int lane = threadIdx.x & 31;
    if (gw >= NT) return;
    int t = gw % 10;
    float cm = (t > 0) ? g_c2[(size_t)(gw-1)*32 + lane] : 0.f;
    float c0 = g_c2[(size_t)gw*32 + lane];
    float cp = (t < 9) ? g_c2[(size_t)(gw+1)*32 + lane] : 0.f;
    float acc = cw3[lane*3+0]*cm + cw3[lane*3+1]*c0 + cw3[lane*3+2]*cp;
    #pragma unroll
    for (int m = 16; m >= 1; m >>= 1)
        acc += __shfl_xor_sync(0xFFFFFFFFu, acc, m);
    if (lane == 0) out[gw] = acc + cb3[0];
}

// ---------------- launch ----------------------------------------------------
extern "C" void kernel_launch(void* const* d_in, const int* in_sizes, int n_in,
                              void* d_out, int out_size)
{
    const float* x    = (const float*)d_in[0];
    const int*   ei   = (const int*)  d_in[1];
    const float* ea   = (const float*)d_in[2];
    const float* W    = (const float*)d_in[3];
    const float* bp   = (const float*)d_in[4];
    const float* ap   = (const float*)d_in[5];
    const float* lng  = (const float*)d_in[6];
    const float* lnb  = (const float*)d_in[7];
    const float* cw1  = (const float*)d_in[8];
    const float* cb1  = (const float*)d_in[9];
    const float* bn1g = (const float*)d_in[10];
    const float* bn1b = (const float*)d_in[11];
    const float* cw2  = (const float*)d_in[12];
    const float* cb2  = (const float*)d_in[13];
    const float* bn2g = (const float*)d_in[14];
    const float* bn2b = (const float*)d_in[15];
    const float* cw3  = (const float*)d_in[16];
    const float* cb3  = (const float*)d_in[17];
    float* out = (float*)d_out;

    static int attr_set = 0;
    if (!attr_set) {
        cudaFuncSetAttribute(k_gemm5, cudaFuncAttributeMaxDynamicSharedMemorySize,
                             GEMM5_SMEM_BYTES);
        cudaFuncSetAttribute(k_conv1, cudaFuncAttributeMaxDynamicSharedMemorySize,
                             CONV_SMEM_BYTES);
        cudaFuncSetAttribute(k_conv2, cudaFuncAttributeMaxDynamicSharedMemorySize,
                             CONV_SMEM_BYTES);
        attr_set = 1;
    }

    k_count<<<(2*EE + 255)/256, 256>>>(ei);
    k_scan<<<2, 1024>>>();
    k_scatter<<<(2*EE + 255)/256, 256>>>(ei);

    int gemm_grid = NT/64;
    k_gemm5<<<gemm_grid, 128, GEMM5_SMEM_BYTES>>>(x, 1, W, bp, ap, 0, 0);
    k_agg4<<<NN, 128>>>(x, 1, ei, ea, lng, lnb, 0, 0);
    k_gemm5<<<gemm_grid, 128, GEMM5_SMEM_BYTES>>>(x, 1, W, bp, ap, 1, 1);
    k_agg4<<<NN, 128>>>(x, 1, ei, ea, lng, lnb, 1, 1);
    k_gemm5<<<gemm_grid, 128, GEMM5_SMEM_BYTES>>>(x, 0, W, bp, ap, 2, 0);
    k_agg4<<<NN, 128>>>(x, 0, ei, ea, lng + 64, lnb + 64, 0, 0);
    k_gemm5<<<gemm_grid, 128, GEMM5_SMEM_BYTES>>>(x, 0, W, bp, ap, 3, 1);
    k_agg4<<<NN, 128>>>(x, 0, ei, ea, lng + 64, lnb + 64, 1, 1);

    k_conv1<<<CONV_GRID, 128, CONV_SMEM_BYTES>>>(cw1, cb1, bn1g, bn1b);
    k_conv2<<<CONV_GRID, 128, CONV_SMEM_BYTES>>>(cw2, cb2, bn2g, bn2b);
    k_conv3<<<NT/8, 256>>>(cw3, cb3, out);
}

// round 16
// speedup vs baseline: 3.6227x; 1.0028x over previous
#include <cuda_runtime.h>
#include <cuda_bf16.h>
#include <math.h>
#include <stdint.h>

#define NN 20000
#define TT 10
#define HH 64
#define EE 200000
#define NT (NN*TT)          // 200000 rows (NT % 64 == 0)
#define ROWF 640
#define BN_SCALE_C 0.99999500003749971893f

// ---------------- scratch ----------------
__device__ __align__(256) __nv_bfloat16 g_h0[NT*HH];   // projected features (bf16)
__device__ __align__(256) __nv_bfloat16 g_h1[NT*HH];
__device__ __align__(256) float g_s0[NT];
__device__ __align__(256) float g_s1[NT];
__device__ __align__(256) float g_X[NT*HH];
__device__ __align__(256) float g_c1[NT*64];
__device__ __align__(256) float g_c2[NT*32];
__device__ __align__(256) int   g_deg[2][NN];     // zero-init; self-restoring
__device__ __align__(256) int   g_rowptr[2][NN+1];
__device__ __align__(256) int   g_eord[2][EE];

// ---------------- CSR build ----------------
__global__ void k_count(const int* __restrict__ ei) {
    int idx = blockIdx.x*blockDim.x + threadIdx.x;
    if (idx >= 2*EE) return;
    int ty = idx / EE, e = idx % EE;
    int dst = ei[ty*2*EE + EE + e];
    atomicAdd(&g_deg[ty][dst], 1);
}

__global__ void k_scan() {
    int ty = blockIdx.x;
    __shared__ int wsums[32];
    int tid = threadIdx.x;
    int lane = tid & 31, w = tid >> 5;
    int start = tid * 20;
    int vals[20];
    int local = 0;
    #pragma unroll
    for (int j = 0; j < 20; j++) {
        int i = start + j;
        vals[j] = (i < NN) ? g_deg[ty][i] : 0;
        local += vals[j];
    }
    int pre = local;
    #pragma unroll
    for (int o = 1; o < 32; o <<= 1) {
        int v = __shfl_up_sync(0xFFFFFFFFu, pre, o);
        if (lane >= o) pre += v;
    }
    if (lane == 31) wsums[w] = pre;
    __syncthreads();
    if (w == 0) {
        int v = wsums[lane];
        int p = v;
        #pragma unroll
        for (int o = 1; o < 32; o <<= 1) {
            int t2 = __shfl_up_sync(0xFFFFFFFFu, p, o);
            if (lane >= o) p += t2;
        }
        wsums[lane] = p - v;
    }
    __syncthreads();
    int offset = wsums[w] + pre - local;
    #pragma unroll
    for (int j = 0; j < 20; j++) {
        int i = start + j;
        if (i < NN) g_rowptr[ty][i] = offset;
        offset += vals[j];
    }
    if (tid == 1023) g_rowptr[ty][NN] = offset;
}

__global__ void k_scatter(const int* __restrict__ ei) {
    int idx = blockIdx.x*blockDim.x + threadIdx.x;
    if (idx >= 2*EE) return;
    int ty = idx / EE, e = idx % EE;
    int dst = ei[ty*2*EE + EE + e];
    int pos = g_rowptr[ty][dst] + (atomicSub(&g_deg[ty][dst], 1) - 1);
    g_eord[ty][pos] = e;
}

// ---------------- helpers ----------------
__device__ __forceinline__ void split4(float4 v, __nv_bfloat16* hi, __nv_bfloat16* lo) {
    __nv_bfloat16 h0 = __float2bfloat16(v.x), h1 = __float2bfloat16(v.y);
    __nv_bfloat16 h2 = __float2bfloat16(v.z), h3 = __float2bfloat16(v.w);
    *(__nv_bfloat162*)(hi)     = __nv_bfloat162(h0, h1);
    *(__nv_bfloat162*)(hi + 2) = __nv_bfloat162(h2, h3);
    *(__nv_bfloat162*)(lo)     = __nv_bfloat162(
        __float2bfloat16(v.x - __bfloat162float(h0)),
        __float2bfloat16(v.y - __bfloat162float(h1)));
    *(__nv_bfloat162*)(lo + 2) = __nv_bfloat162(
        __float2bfloat16(v.z - __bfloat162float(h2)),
        __float2bfloat16(v.w - __bfloat162float(h3)));
}

// ---------------- tensor-core GEMM (bf16x3), ONE edge type -----------------
#define GEMM5_SMEM_BYTES 36864
__global__ void __launch_bounds__(128) k_gemm5(
    const float* __restrict__ Xin, int useX,
    const float* __restrict__ W, const float* __restrict__ bp,
    const float* __restrict__ ap, int idx4, int t)
{
    extern __shared__ __nv_bfloat16 smb[];
    __nv_bfloat16* Xh = smb;                 // [64][72]
    __nv_bfloat16* Xl = smb + 4608;
    __nv_bfloat16* Wh = smb + 9216;
    __nv_bfloat16* Wl = smb + 13824;

    const float* X = useX ? Xin : (const float*)g_X;
    int tid = threadIdx.x;
    int base = blockIdx.x * 64;

    {
        const float4* Xg = (const float4*)(X + (size_t)base*64);
        #pragma unroll
        for (int v = 0; v < 8; v++) {
            int idx = tid + v*128;
            float4 x4 = Xg[idx];
            int row = idx >> 4, c = (idx & 15)*4;
            split4(x4, Xh + row*72 + c, Xl + row*72 + c);
        }
    }
    {
        const float4* Wg = (const float4*)(W + (size_t)idx4*4096);
        #pragma unroll
        for (int v = 0; v < 8; v++) {
            int idx = tid + v*128;
            float4 w4 = Wg[idx];
            int row = idx >> 4, c = (idx & 15)*4;
            split4(w4, Wh + row*72 + c, Wl + row*72 + c);
        }
    }
    __syncthreads();

    int warp = tid >> 5, lane = tid & 31;
    int g = lane >> 2, tg = lane & 3;
    int m0 = warp*16;
    int a_row = m0 + (lane & 15);
    int a_col = (lane & 16) ? 8 : 0;
    uint32_t addrXh = (uint32_t)__cvta_generic_to_shared(Xh + a_row*72 + a_col);
    uint32_t addrXl = (uint32_t)__cvta_generic_to_shared(Xl + a_row*72 + a_col);
    int b_row = (lane & 15);

    float c[8][4];
    #pragma unroll
    for (int n = 0; n < 8; n++)
        #pragma unroll
        for (int i = 0; i < 4; i++) c[n][i] = 0.f;

    #pragma unroll
    for (int ks = 0; ks < 4; ks++) {
        uint32_t ah0, ah1, ah2, ah3, al0, al1, al2, al3;
        asm volatile("ldmatrix.sync.aligned.m8n8.x4.shared.b16 {%0,%1,%2,%3}, [%4];"
            : "=r"(ah0), "=r"(ah1), "=r"(ah2), "=r"(ah3) : "r"(addrXh + ks*32));
        asm volatile("ldmatrix.sync.aligned.m8n8.x4.shared.b16 {%0,%1,%2,%3}, [%4];"
            : "=r"(al0), "=r"(al1), "=r"(al2), "=r"(al3) : "r"(addrXl + ks*32));
        uint32_t wbh = (uint32_t)__cvta_generic_to_shared(Wh + (ks*16 + b_row)*72);
        uint32_t wbl = (uint32_t)__cvta_generic_to_shared(Wl + (ks*16 + b_row)*72);
        #pragma unroll
        for (int n = 0; n < 8; n++) {
            uint32_t bh0, bh1, bl0, bl1;
            asm volatile("ldmatrix.sync.aligned.m8n8.x2.trans.shared.b16 {%0,%1}, [%2];"
                : "=r"(bh0), "=r"(bh1) : "r"(wbh + n*16));
            asm volatile("ldmatrix.sync.aligned.m8n8.x2.trans.shared.b16 {%0,%1}, [%2];"
                : "=r"(bl0), "=r"(bl1) : "r"(wbl + n*16));
            asm volatile("mma.sync.aligned.m16n8k16.row.col.f32.bf16.bf16.f32 "
                "{%0,%1,%2,%3}, {%4,%5,%6,%7}, {%8,%9}, {%0,%1,%2,%3};"
                : "+f"(c[n][0]), "+f"(c[n][1]), "+f"(c[n][2]), "+f"(c[n][3])
                : "r"(ah0), "r"(ah1), "r"(ah2), "r"(ah3), "r"(bh0), "r"(bh1));
            asm volatile("mma.sync.aligned.m16n8k16.row.col.f32.bf16.bf16.f32 "
                "{%0,%1,%2,%3}, {%4,%5,%6,%7}, {%8,%9}, {%0,%1,%2,%3};"
                : "+f"(c[n][0]), "+f"(c[n][1]), "+f"(c[n][2]), "+f"(c[n][3])
                : "r"(ah0), "r"(ah1), "r"(ah2), "r"(ah3), "r"(bl0), "r"(bl1));
            asm volatile("mma.sync.aligned.m16n8k16.row.col.f32.bf16.bf16.f32 "
                "{%0,%1,%2,%3}, {%4,%5,%6,%7}, {%8,%9}, {%0,%1,%2,%3};"
                : "+f"(c[n][0]), "+f"(c[n][1]), "+f"(c[n][2]), "+f"(c[n][3])
                : "r"(al0), "r"(al1), "r"(al2), "r"(al3), "r"(bh0), "r"(bh1));
        }
    }

    const float* bP = bp + idx4*64;
    const float* aP = ap + idx4*64;
    __nv_bfloat16* hout = t ? (__nv_bfloat16*)g_h1 : (__nv_bfloat16*)g_h0;
    float* sout = t ? (float*)g_s1 : (float*)g_s0;
    int r0 = base + m0 + g, r1 = r0 + 8;
    float sd0 = 0.f, sd1 = 0.f;
    #pragma unroll
    for (int n = 0; n < 8; n++) {
        int col = n*8 + tg*2;
        float bb0 = bP[col], bb1 = bP[col+1];
        float h00 = c[n][0] + bb0, h01 = c[n][1] + bb1;
        float h10 = c[n][2] + bb0, h11 = c[n][3] + bb1;
        *(__nv_bfloat162*)(hout + (size_t)r0*64 + col) =
            __nv_bfloat162(__float2bfloat16(h00), __float2bfloat16(h01));
        *(__nv_bfloat162*)(hout + (size_t)r1*64 + col) =
            __nv_bfloat162(__float2bfloat16(h10), __float2bfloat16(h11));
        float a0 = aP[col], a1 = aP[col+1];
        sd0 += h00*a0 + h01*a1;
        sd1 += h10*a0 + h11*a1;
    }
    sd0 += __shfl_xor_sync(0xFFFFFFFFu, sd0, 1);
    sd0 += __shfl_xor_sync(0xFFFFFFFFu, sd0, 2);
    sd1 += __shfl_xor_sync(0xFFFFFFFFu, sd1, 1);
    sd1 += __shfl_xor_sync(0xFFFFFFFFu, sd1, 2);
    if (tg == 0) { sout[r0] = sd0; sout[r1] = sd1; }
}

// ---------------- fused attention (BOTH types) + residual + LayerNorm ------
// bf16 h gather (both buffers = 51.2MB, fit L2 together). 80 active threads;
// thread tid<80 owns h positions tid*8..tid*8+7. No g_M round-trip.
__global__ void __launch_bounds__(128) k_agg5(
    const float* __restrict__ xin, int useX,
    const int* __restrict__ ei, const float* __restrict__ ea,
    const float* __restrict__ lng, const float* __restrict__ lnb)
{
    int n = blockIdx.x;
    int tid = threadIdx.x;

    __shared__ float red_m[8][16], red_d[8][16];
    __shared__ float smax[10], srcp[10];
    __shared__ float wsh[16][10];
    __shared__ int   ssrc[16];

    int ts = tid & 15, es = tid >> 4;
    float acc[8] = {0.f,0.f,0.f,0.f,0.f,0.f,0.f,0.f};
    int active = (tid < 80);
    int tW = tid >> 3;               // t index 0..9 for active threads

    #pragma unroll
    for (int ty = 0; ty < 2; ty++) {
        const float* sA   = ty ? (const float*)g_s1 : (const float*)g_s0;
        const __nv_bfloat16* hA = ty ? (const __nv_bfloat16*)g_h1
                                     : (const __nv_bfloat16*)g_h0;
        const float* eaA  = ea + ty*EE;
        const int*   srcA = ei + ty*2*EE;
        const int*   eord = g_eord[ty];
        int r0 = g_rowptr[ty][n], r1 = g_rowptr[ty][n+1];
        __syncthreads();   // shared buffers safe to reuse across types

        // online max + denominator in one pass
        float m = -1e30f, d = 0.f;
        if (ts < 10) {
            for (int j = r0 + es; j < r1; j += 8) {
                int src = srcA[eord[j]];
                float v = sA[src*TT + ts];
                float sc = v > 0.f ? v : 0.2f*v;
                if (sc > m) { d = d*__expf(m - sc) + 1.f; m = sc; }
                else        { d += __expf(sc - m); }
            }
        }
        red_m[es][ts] = m;
        red_d[es][ts] = d;
        __syncthreads();
        if (tid < 10) {
            float M = red_m[0][tid];
            #pragma unroll
            for (int i = 1; i < 8; i++) M = fmaxf(M, red_m[i][tid]);
            float D = 0.f;
            #pragma unroll
            for (int i = 0; i < 8; i++) D += red_d[i][tid]*__expf(red_m[i][tid] - M);
            smax[tid] = M;
            srcp[tid] = 1.f/(D + 1e-16f);
        }
        __syncthreads();

        // chunked weighted aggregation with one-deep prefetch
        for (int j0 = r0; j0 < r1; j0 += 16) {
            int cnt = min(16, r1 - j0);
            for (int p = tid; p < cnt*10; p += 128) {
                int ce = p / 10, ct = p % 10;
                int e = eord[j0 + ce];
                int src = srcA[e];
                if (ct == 0) ssrc[ce] = src;
                float v = sA[src*TT + ct];
                float sc = v > 0.f ? v : 0.2f*v;
                wsh[ce][ct] = __expf(sc - smax[ct]) * srcp[ct] * eaA[e];
            }
            __syncthreads();
            if (active) {
                float4 pk = ((const float4*)(hA + (size_t)ssrc[0]*ROWF))[tid];
                for (int c = 0; c < cnt; c++) {
                    float4 cur = pk;
                    if (c + 1 < cnt)
                        pk = ((const float4*)(hA + (size_t)ssrc[c+1]*ROWF))[tid];
                    float w = wsh[c][tW];
                    __nv_bfloat162 b0 = *(__nv_bfloat162*)&cur.x;
                    __nv_bfloat162 b1 = *(__nv_bfloat162*)&cur.y;
                    __nv_bfloat162 b2 = *(__nv_bfloat162*)&cur.z;
                    __nv_bfloat162 b3 = *(__nv_bfloat162*)&cur.w;
                    float2 f0 = __bfloat1622float2(b0);
                    float2 f1 = __bfloat1622float2(b1);
                    float2 f2 = __bfloat1622float2(b2);
                    float2 f3 = __bfloat1622float2(b3);
                    acc[0] += w*f0.x; acc[1] += w*f0.y;
                    acc[2] += w*f1.x; acc[3] += w*f1.y;
                    acc[4] += w*f2.x; acc[5] += w*f2.y;
                    acc[6] += w*f3.x; acc[7] += w*f3.y;
                }
            }
            __syncthreads();
        }
    }

    if (!active) return;
    size_t nb = (size_t)n*ROWF + tid*8;

    // residual + LayerNorm (messages of both types summed in acc; /2 per ref)
    const float* Xsrc = (useX ? xin : (const float*)g_X) + nb;
    float val[8];
    float s = 0.f, q = 0.f;
    #pragma unroll
    for (int i = 0; i < 8; i++) {
        val[i] = Xsrc[i] + 0.5f*acc[i];
        s += val[i];
        q += val[i]*val[i];
    }
    #pragma unroll
    for (int o = 4; o >= 1; o >>= 1) {
        s += __shfl_xor_sync(0xFFFFFFFFu, s, o);
        q += __shfl_xor_sync(0xFFFFFFFFu, q, o);
    }
    float mean = s * (1.f/64.f);
    float var  = q * (1.f/64.f) - mean*mean;
    float inv  = rsqrtf(var + 1e-5f);

    int h0 = (tid & 7)*8;
    float4 gw0 = *(const float4*)(lng + h0), gw1 = *(const float4*)(lng + h0 + 4);
    float4 bw0 = *(const float4*)(lnb + h0), bw1 = *(const float4*)(lnb + h0 + 4);
    float4* Xo4 = (float4*)(g_X + nb);
    float4 o0, o1;
    o0.x = (val[0]-mean)*inv*gw0.x + bw0.x;
    o0.y = (val[1]-mean)*inv*gw0.y + bw0.y;
    o0.z = (val[2]-mean)*inv*gw0.z + bw0.z;
    o0.w = (val[3]-mean)*inv*gw0.w + bw0.w;
    o1.x = (val[4]-mean)*inv*gw1.x + bw1.x;
    o1.y = (val[5]-mean)*inv*gw1.y + bw1.y;
    o1.z = (val[6]-mean)*inv*gw1.z + bw1.z;
    o1.w = (val[7]-mean)*inv*gw1.w + bw1.w;
    Xo4[0] = o0;
    Xo4[1] = o1;
}

// ---------------- tensorized decoder conv1 (64->64, k=3) --------------------
#define CONV_SMEM_BYTES 110592
#define CONV_GRID 296
__global__ void __launch_bounds__(128) k_conv1(
    const float* __restrict__ cw1, const float* __restrict__ cb1,
    const float* __restrict__ bn1g, const float* __restrict__ bn1b)
{
    extern __shared__ __nv_bfloat16 smc[];
    __nv_bfloat16* A  = smc;            // [shift][hi/lo][64*72]
    __nv_bfloat16* Wk = smc + 27648;
    int tid = threadIdx.x;

    for (int idx = tid; idx < 4096; idx += 128) {
        int i = idx >> 6, o = idx & 63;
        #pragma unroll
        for (int k = 0; k < 3; k++) {
            float w = cw1[o*192 + i*3 + k];
            __nv_bfloat16 h = __float2bfloat16(w);
            Wk[(k*2+0)*4608 + i*72 + o] = h;
            Wk[(k*2+1)*4608 + i*72 + o] = __float2bfloat16(w - __bfloat162float(h));
        }
    }
    __syncthreads();

    int warp = tid >> 5, lane = tid & 31;
    int g = lane >> 2, tg = lane & 3;
    int m0 = warp*16;
    int a_row = m0 + (lane & 15);
    int a_col = (lane & 16) ? 8 : 0;
    int b_row = (lane & 15);

    for (int tile = blockIdx.x; tile < NT/64; tile += CONV_GRID) {
        int base = tile*64;
        for (int idx = tid; idx < 1024; idx += 128) {
            int row = idx >> 4, c4 = (idx & 15)*4;
            int t = (base + row) % 10;
            #pragma unroll
            for (int s = 0; s < 3; s++) {
                int dt = s - 1;
                float4 x4 = make_float4(0.f,0.f,0.f,0.f);
                if ((unsigned)(t + dt) < 10u)
                    x4 = *(const float4*)(g_X + (size_t)(base + row + dt)*64 + c4);
                split4(x4, A + (s*2+0)*4608 + row*72 + c4,
                           A + (s*2+1)*4608 + row*72 + c4);
            }
        }
        __syncthreads();

        float c[8][4];
        #pragma unroll
        for (int n = 0; n < 8; n++)
            #pragma unroll
            for (int i = 0; i < 4; i++) c[n][i] = 0.f;

        #pragma unroll
        for (int s = 0; s < 3; s++) {
            uint32_t aH = (uint32_t)__cvta_generic_to_shared(
                A + (s*2+0)*4608 + a_row*72 + a_col);
            uint32_t aL = (uint32_t)__cvta_generic_to_shared(
                A + (s*2+1)*4608 + a_row*72 + a_col);
            #pragma unroll
            for (int ks = 0; ks < 4; ks++) {
                uint32_t ah0, ah1, ah2, ah3, al0, al1, al2, al3;
                asm volatile("ldmatrix.sync.aligned.m8n8.x4.shared.b16 {%0,%1,%2,%3}, [%4];"
                    : "=r"(ah0), "=r"(ah1), "=r"(ah2), "=r"(ah3) : "r"(aH + ks*32));
                asm volatile("ldmatrix.sync.aligned.m8n8.x4.shared.b16 {%0,%1,%2,%3}, [%4];"
                    : "=r"(al0), "=r"(al1), "=r"(al2), "=r"(al3) : "r"(aL + ks*32));
                uint32_t wbh = (uint32_t)__cvta_generic_to_shared(
                    Wk + (s*2+0)*4608 + (ks*16 + b_row)*72);
                uint32_t wbl = (uint32_t)__cvta_generic_to_shared(
                    Wk + (s*2+1)*4608 + (ks*16 + b_row)*72);
                #pragma unroll
                for (int n = 0; n < 8; n++) {
                    uint32_t bh0, bh1, bl0, bl1;
                    asm volatile("ldmatrix.sync.aligned.m8n8.x2.trans.shared.b16 {%0,%1}, [%2];"
                        : "=r"(bh0), "=r"(bh1) : "r"(wbh + n*16));
                    asm volatile("ldmatrix.sync.aligned.m8n8.x2.trans.shared.b16 {%0,%1}, [%2];"
                        : "=r"(bl0), "=r"(bl1) : "r"(wbl + n*16));
                    asm volatile("mma.sync.aligned.m16n8k16.row.col.f32.bf16.bf16.f32 "
                        "{%0,%1,%2,%3}, {%4,%5,%6,%7}, {%8,%9}, {%0,%1,%2,%3};"
                        : "+f"(c[n][0]), "+f"(c[n][1]), "+f"(c[n][2]), "+f"(c[n][3])
                        : "r"(ah0), "r"(ah1), "r"(ah2), "r"(ah3), "r"(bh0), "r"(bh1));
                    asm volatile("mma.sync.aligned.m16n8k16.row.col.f32.bf16.bf16.f32 "
                        "{%0,%1,%2,%3}, {%4,%5,%6,%7}, {%8,%9}, {%0,%1,%2,%3};"
                        : "+f"(c[n][0]), "+f"(c[n][1]), "+f"(c[n][2]), "+f"(c[n][3])
                        : "r"(ah0), "r"(ah1), "r"(ah2), "r"(ah3), "r"(bl0), "r"(bl1));
                    asm volatile("mma.sync.aligned.m16n8k16.row.col.f32.bf16.bf16.f32 "
                        "{%0,%1,%2,%3}, {%4,%5,%6,%7}, {%8,%9}, {%0,%1,%2,%3};"
                        : "+f"(c[n][0]), "+f"(c[n][1]), "+f"(c[n][2]), "+f"(c[n][3])
                        : "r"(al0), "r"(al1), "r"(al2), "r"(al3), "r"(bh0), "r"(bh1));
                }
            }
        }

        int r0 = base + m0 + g, r1 = r0 + 8;
        #pragma unroll
        for (int n = 0; n < 8; n++) {
            int col = n*8 + tg*2;
            float cb0 = cb1[col], cb1v = cb1[col+1];
            float s0 = bn1g[col]*BN_SCALE_C,  t0 = bn1b[col];
            float s1 = bn1g[col+1]*BN_SCALE_C, t1 = bn1b[col+1];
            float y00 = (c[n][0]+cb0)*s0 + t0; y00 = y00 > 0.f ? y00 : 0.f;
            float y01 = (c[n][1]+cb1v)*s1 + t1; y01 = y01 > 0.f ? y01 : 0.f;
            float y10 = (c[n][2]+cb0)*s0 + t0; y10 = y10 > 0.f ? y10 : 0.f;
            float y11 = (c[n][3]+cb1v)*s1 + t1; y11 = y11 > 0.f ? y11 : 0.f;
            *(float2*)(g_c1 + (size_t)r0*64 + col) = make_float2(y00, y01);
            *(float2*)(g_c1 + (size_t)r1*64 + col) = make_float2(y10, y11);
        }
        __syncthreads();
    }
}

// ---------------- tensorized decoder conv2 (64->32, k=3) --------------------
__global__ void __launch_bounds__(128) k_conv2(
    const float* __restrict__ cw2, const float* __restrict__ cb2,
    const float* __restrict__ bn2g, const float* __restrict__ bn2b)
{
    extern __shared__ __nv_bfloat16 smc[];
    __nv_bfloat16* A  = smc;
    __nv_bfloat16* Wk = smc + 27648;
    int tid = threadIdx.x;

    for (int idx = tid; idx < 2048; idx += 128) {
        int i = idx >> 5, o = idx & 31;
        #pragma unroll
        for (int k = 0; k < 3; k++) {
            float w = cw2[o*192 + i*3 + k];
            __nv_bfloat16 h = __float2bfloat16(w);
            Wk[(k*2+0)*4608 + i*72 + o] = h;
            Wk[(k*2+1)*4608 + i*72 + o] = __float2bfloat16(w - __bfloat162float(h));
        }
    }
    __syncthreads();

    int warp = tid >> 5, lane = tid & 31;
    int g = lane >> 2, tg = lane & 3;
    int m0 = warp*16;
    int a_row = m0 + (lane & 15);
    int a_col = (lane & 16) ? 8 : 0;
    int b_row = (lane & 15);

    for (int tile = blockIdx.x; tile < NT/64; tile += CONV_GRID) {
        int base = tile*64;
        for (int idx = tid; idx < 1024; idx += 128) {
            int row = idx >> 4, c4 = (idx & 15)*4;
            int t = (base + row) % 10;
            #pragma unroll
            for (int s = 0; s < 3; s++) {
                int dt = s - 1;
                float4 x4 = make_float4(0.f,0.f,0.f,0.f);
                if ((unsigned)(t + dt) < 10u)
                    x4 = *(const float4*)(g_c1 + (size_t)(base + row + dt)*64 + c4);
                split4(x4, A + (s*2+0)*4608 + row*72 + c4,
                           A + (s*2+1)*4608 + row*72 + c4);
            }
        }
        __syncthreads();

        float c[4][4];
        #pragma unroll
        for (int n = 0; n < 4; n++)
            #pragma unroll
            for (int i = 0; i < 4; i++) c[n][i] = 0.f;

        #pragma unroll
        for (int s = 0; s < 3; s++) {
            uint32_t aH = (uint32_t)__cvta_generic_to_shared(
                A + (s*2+0)*4608 + a_row*72 + a_col);
            uint32_t aL = (uint32_t)__cvta_generic_to_shared(
                A + (s*2+1)*4608 + a_row*72 + a_col);
            #pragma unroll
            for (int ks = 0; ks < 4; ks++) {
                uint32_t ah0, ah1, ah2, ah3, al0, al1, al2, al3;
                asm volatile("ldmatrix.sync.aligned.m8n8.x4.shared.b16 {%0,%1,%2,%3}, [%4];"
                    : "=r"(ah0), "=r"(ah1), "=r"(ah2), "=r"(ah3) : "r"(aH + ks*32));
                asm volatile("ldmatrix.sync.aligned.m8n8.x4.shared.b16 {%0,%1,%2,%3}, [%4];"
                    : "=r"(al0), "=r"(al1), "=r"(al2), "=r"(al3) : "r"(aL + ks*32));
                uint32_t wbh = (uint32_t)__cvta_generic_to_shared(
                    Wk + (s*2+0)*4608 + (ks*16 + b_row)*72);
                uint32_t wbl = (uint32_t)__cvta_generic_to_shared(
                    Wk + (s*2+1)*4608 + (ks*16 + b_row)*72);
                #pragma unroll
                for (int n = 0; n < 4; n++) {
                    uint32_t bh0, bh1, bl0, bl1;
                    asm volatile("ldmatrix.sync.aligned.m8n8.x2.trans.shared.b16 {%0,%1}, [%2];"
                        : "=r"(bh0), "=r"(bh1) : "r"(wbh + n*16));
                    asm volatile("ldmatrix.sync.aligned.m8n8.x2.trans.shared.b16 {%0,%1}, [%2];"
                        : "=r"(bl0), "=r"(bl1) : "r"(wbl + n*16));
                    asm volatile("mma.sync.aligned.m16n8k16.row.col.f32.bf16.bf16.f32 "
                        "{%0,%1,%2,%3}, {%4,%5,%6,%7}, {%8,%9}, {%0,%1,%2,%3};"
                        : "+f"(c[n][0]), "+f"(c[n][1]), "+f"(c[n][2]), "+f"(c[n][3])
                        : "r"(ah0), "r"(ah1), "r"(ah2), "r"(ah3), "r"(bh0), "r"(bh1));
                    asm volatile("mma.sync.aligned.m16n8k16.row.col.f32.bf16.bf16.f32 "
                        "{%0,%1,%2,%3}, {%4,%5,%6,%7}, {%8,%9}, {%0,%1,%2,%3};"
                        : "+f"(c[n][0]), "+f"(c[n][1]), "+f"(c[n][2]), "+f"(c[n][3])
                        : "r"(ah0), "r"(ah1), "r"(ah2), "r"(ah3), "r"(bl0), "r"(bl1));
                    asm volatile("mma.sync.aligned.m16n8k16.row.col.f32.bf16.bf16.f32 "
                        "{%0,%1,%2,%3}, {%4,%5,%6,%7}, {%8,%9}, {%0,%1,%2,%3};"
                        : "+f"(c[n][0]), "+f"(c[n][1]), "+f"(c[n][2]), "+f"(c[n][3])
                        : "r"(al0), "r"(al1), "r"(al2), "r"(al3), "r"(bh0), "r"(bh1));
                }
            }
        }

        int r0 = base + m0 + g, r1 = r0 + 8;
        #pragma unroll
        for (int n = 0; n < 4; n++) {
            int col = n*8 + tg*2;
            float cb0 = cb2[col], cb1v = cb2[col+1];
            float s0 = bn2g[col]*BN_SCALE_C,  t0 = bn2b[col];
            float s1 = bn2g[col+1]*BN_SCALE_C, t1 = bn2b[col+1];
            float y00 = (c[n][0]+cb0)*s0 + t0; y00 = y00 > 0.f ? y00 : 0.f;
            float y01 = (c[n][1]+cb1v)*s1 + t1; y01 = y01 > 0.f ? y01 : 0.f;
            float y10 = (c[n][2]+cb0)*s0 + t0; y10 = y10 > 0.f ? y10 : 0.f;
            float y11 = (c[n][3]+cb1v)*s1 + t1; y11 = y11 > 0.f ? y11 : 0.f;
            *(float2*)(g_c2 + (size_t)r0*32 + col) = make_float2(y00, y01);
            *(float2*)(g_c2 + (size_t)r1*32 + col) = make_float2(y10, y11);
        }
        __syncthreads();
    }
}

// ---------------- decoder conv3 (32->1, k=3): warp per output row ----------
__global__ void __launch_bounds__(256) k_conv3(
    const float* __restrict__ cw3, const float* __restrict__ cb3,
    float* __restrict__ out)
{
    int gw = (blockIdx.x*blockDim.x + threadIdx.x) >> 5;
    int lane = threadIdx.x & 31;
    if (gw >= NT) return;
    int t = gw % 10;
    float cm = (t > 0) ? g_c2[(size_t)(gw-1)*32 + lane] : 0.f;
    float c0 = g_c2[(size_t)gw*32 + lane];
    float cp = (t < 9) ? g_c2[(size_t)(gw+1)*32 + lane] : 0.f;
    float acc = cw3[lane*3+0]*cm + cw3[lane*3+1]*c0 + cw3[lane*3+2]*cp;
    #pragma unroll
    for (int m = 16; m >= 1; m >>= 1)
        acc += __shfl_xor_sync(0xFFFFFFFFu, acc, m);
    if (lane == 0) out[gw] = acc + cb3[0];
}

// ---------------- launch ----------------------------------------------------
extern "C" void kernel_launch(void* const* d_in, const int* in_sizes, int n_in,
                              void* d_out, int out_size)
{
    const float* x    = (const float*)d_in[0];
    const int*   ei   = (const int*)  d_in[1];
    const float* ea   = (const float*)d_in[2];
    const float* W    = (const float*)d_in[3];
    const float* bp   = (const float*)d_in[4];
    const float* ap   = (const float*)d_in[5];
    const float* lng  = (const float*)d_in[6];
    const float* lnb  = (const float*)d_in[7];
    const float* cw1  = (const float*)d_in[8];
    const float* cb1  = (const float*)d_in[9];
    const float* bn1g = (const float*)d_in[10];
    const float* bn1b = (const float*)d_in[11];
    const float* cw2  = (const float*)d_in[12];
    const float* cb2  = (const float*)d_in[13];
    const float* bn2g = (const float*)d_in[14];
    const float* bn2b = (const float*)d_in[15];
    const float* cw3  = (const float*)d_in[16];
    const float* cb3  = (const float*)d_in[17];
    float* out = (float*)d_out;

    static int attr_set = 0;
    if (!attr_set) {
        cudaFuncSetAttribute(k_gemm5, cudaFuncAttributeMaxDynamicSharedMemorySize,
                             GEMM5_SMEM_BYTES);
        cudaFuncSetAttribute(k_conv1, cudaFuncAttributeMaxDynamicSharedMemorySize,
                             CONV_SMEM_BYTES);
        cudaFuncSetAttribute(k_conv2, cudaFuncAttributeMaxDynamicSharedMemorySize,
                             CONV_SMEM_BYTES);
        attr_set = 1;
    }

    k_count<<<(2*EE + 255)/256, 256>>>(ei);
    k_scan<<<2, 1024>>>();
    k_scatter<<<(2*EE + 255)/256, 256>>>(ei);

    int gemm_grid = NT/64;
    for (int l = 0; l < 2; l++) {
        int useX = (l == 0) ? 1 : 0;
        k_gemm5<<<gemm_grid, 128, GEMM5_SMEM_BYTES>>>(x, useX, W, bp, ap, l*2+0, 0);
        k_gemm5<<<gemm_grid, 128, GEMM5_SMEM_BYTES>>>(x, useX, W, bp, ap, l*2+1, 1);
        k_agg5<<<NN, 128>>>(x, useX, ei, ea, lng + l*64, lnb + l*64);
    }

    k_conv1<<<CONV_GRID, 128, CONV_SMEM_BYTES>>>(cw1, cb1, bn1g, bn1b);
    k_conv2<<<CONV_GRID, 128, CONV_SMEM_BYTES>>>(cw2, cb2, bn2g, bn2b);
    k_conv3<<<NT/8, 256>>>(cw3, cb3, out);
}